// round 1
// baseline (speedup 1.0000x reference)
#include <cuda_runtime.h>
#include <math.h>

#define Bn 4
#define C1 128
#define H1 128
#define W1 128
#define C2 64
#define H2 64
#define W2 64
#define L 4096      // H2*W2 patches / pixels
#define M2 2048     // C1*4*4 patch elements
#define SCALE_F 10.0f

// ---- static device scratch (allocation-free rule) ----
__device__ float g_corr[L * L];          // 64 MB  pixel gram matrix
__device__ float g_S[L * L];             // 64 MB  scores -> attention (in place)
__device__ float g_Z[M2 * L];            // 32 MB  paste GEMM result [m][p]
__device__ float g_y[Bn * C1 * H1 * W1]; // 33.5 MB pasted images
__device__ float g_pix2[L];
__device__ float g_invnorm[L];
__device__ float g_mm[L];
__device__ int   g_idx1[L];
__device__ int   g_idx0[L];
__device__ int   g_cnt[2];
__device__ float g_cm0[M2];

// ---------------------------------------------------------------------------
// per-pixel squared channel norm: pix2[a] = sum_c x2[c][a]^2
__global__ void pix2_kernel(const float* __restrict__ x2b) {
    int a = blockIdx.x * 256 + threadIdx.x;
    float s = 0.f;
#pragma unroll 16
    for (int c = 0; c < C2; c++) { float v = x2b[c * L + a]; s += v * v; }
    g_pix2[a] = s;
}

// patch norm: invnorm[l] = 1/max(sqrt(sum_{3x3 valid} pix2), 1e-4)
__global__ void invnorm_kernel() {
    int l = blockIdx.x * 256 + threadIdx.x;
    int li = l >> 6, lj = l & 63;
    float s = 0.f;
#pragma unroll
    for (int dy = -1; dy <= 1; dy++)
#pragma unroll
        for (int dx = -1; dx <= 1; dx++) {
            int i = li + dy, j = lj + dx;
            if ((unsigned)i < 64u && (unsigned)j < 64u) s += g_pix2[i * 64 + j];
        }
    g_invnorm[l] = 1.0f / fmaxf(sqrtf(s), 1e-4f);
}

// mm[l] = 1 iff the 4x4 (stride 2, pad 1) mask patch is all-zero
__global__ void mm_kernel(const float* __restrict__ maskb) {
    int l = blockIdx.x * 256 + threadIdx.x;
    int li = l >> 6, lj = l & 63;
    bool allzero = true;
#pragma unroll
    for (int ky = 0; ky < 4; ky++)
#pragma unroll
        for (int kx = 0; kx < 4; kx++) {
            int u = 2 * li - 1 + ky, v = 2 * lj - 1 + kx;
            if ((unsigned)u < (unsigned)H1 && (unsigned)v < (unsigned)W1) {
                if (maskb[u * W1 + v] != 0.f) allzero = false;
            }
        }
    g_mm[l] = allzero ? 1.f : 0.f;
}

// deterministic compaction of mm==1 / mm==0 index lists (block-local scan)
__global__ void compact_kernel() {
    __shared__ int cnt1[256], off1[256], cnt0[256], off0[256];
    int t = threadIdx.x;
    int c1 = 0, c0 = 0;
    for (int i = 0; i < 16; i++) {
        if (g_mm[t * 16 + i] > 0.5f) c1++; else c0++;
    }
    cnt1[t] = c1; cnt0[t] = c0;
    __syncthreads();
    if (t == 0) {
        int s1 = 0, s0 = 0;
        for (int i = 0; i < 256; i++) {
            off1[i] = s1; s1 += cnt1[i];
            off0[i] = s0; s0 += cnt0[i];
        }
        g_cnt[0] = s1; g_cnt[1] = s0;
    }
    __syncthreads();
    int o1 = off1[t], o0 = off0[t];
    for (int i = 0; i < 16; i++) {
        int l = t * 16 + i;
        if (g_mm[l] > 0.5f) g_idx1[o1++] = l; else g_idx0[o0++] = l;
    }
}

// ---------------------------------------------------------------------------
// Corr = X^T X, X = x2[b] viewed as [64 ch][4096 pix]. 64x64 tiles, K=64.
__global__ void __launch_bounds__(256) corr_gemm(const float* __restrict__ X) {
    __shared__ float sA[64][64];
    __shared__ float sB[64][64];
    int t = threadIdx.x;
    int m0 = blockIdx.x * 64, n0 = blockIdx.y * 64;
#pragma unroll
    for (int i = 0; i < 16; i++) {
        int e = i * 256 + t;
        int c = e >> 6, q = e & 63;
        sA[c][q] = X[c * L + m0 + q];
        sB[c][q] = X[c * L + n0 + q];
    }
    __syncthreads();
    int tx = t & 15, ty = t >> 4;
    float acc[4][4] = {};
#pragma unroll 8
    for (int c = 0; c < 64; c++) {
        float a[4], b[4];
#pragma unroll
        for (int i = 0; i < 4; i++) a[i] = sA[c][ty * 4 + i];
#pragma unroll
        for (int j = 0; j < 4; j++) b[j] = sB[c][tx * 4 + j];
#pragma unroll
        for (int i = 0; i < 4; i++)
#pragma unroll
            for (int j = 0; j < 4; j++) acc[i][j] += a[i] * b[j];
    }
#pragma unroll
    for (int i = 0; i < 4; i++) {
        float4 v = make_float4(acc[i][0], acc[i][1], acc[i][2], acc[i][3]);
        *(float4*)&g_corr[(m0 + ty * 4 + i) * L + n0 + tx * 4] = v;
    }
}

// S[l,p] = (sum of 9 diagonal-shifted Corr reads) * invnorm[l] * mm[l] * ma[p]
__global__ void scores_kernel(const float* __restrict__ mab) {
    int l = blockIdx.y;
    int p = blockIdx.x * 256 + threadIdx.x;
    int off = l * L + p;
    if (g_mm[l] == 0.f) { g_S[off] = 0.f; return; }
    int li = l >> 6, lj = l & 63, pi = p >> 6, pj = p & 63;
    float s = 0.f;
#pragma unroll
    for (int dy = -1; dy <= 1; dy++)
#pragma unroll
        for (int dx = -1; dx <= 1; dx++) {
            if ((unsigned)(li + dy) < 64u && (unsigned)(lj + dx) < 64u &&
                (unsigned)(pi + dy) < 64u && (unsigned)(pj + dx) < 64u) {
                int o = dy * 64 + dx;
                s += g_corr[(l + o) * L + (p + o)];
            }
        }
    g_S[off] = s * g_invnorm[l] * mab[p];
}

// column softmax over l (4096) per pixel p, then remask+floor in place.
// block = 8 l-partitions x 32 columns
__global__ void softmax_kernel(const float* __restrict__ mab) {
    __shared__ float smm[L];
    __shared__ float red[8][32];
    int t = threadIdx.x;
    for (int i = t; i < L; i += 256) smm[i] = g_mm[i];
    int col = t & 31, part = t >> 5;
    int p = blockIdx.x * 32 + col;
    __syncthreads();

    float mx = -1e30f;
    for (int l = part; l < L; l += 8) mx = fmaxf(mx, g_S[l * L + p]);
    red[part][col] = mx;
    __syncthreads();
    if (t < 32) {
        float m = red[0][t];
        for (int k = 1; k < 8; k++) m = fmaxf(m, red[k][t]);
        red[0][t] = m;
    }
    __syncthreads();
    mx = red[0][col];
    __syncthreads();

    float sm = 0.f;
    for (int l = part; l < L; l += 8)
        sm += expf(SCALE_F * (g_S[l * L + p] - mx));
    red[part][col] = sm;
    __syncthreads();
    if (t < 32) {
        float s = 0.f;
        for (int k = 0; k < 8; k++) s += red[k][t];
        red[0][t] = s;
    }
    __syncthreads();
    float inv_s = 1.0f / red[0][col];
    float mav = mab[p];

    for (int l = part; l < L; l += 8) {
        int o = l * L + p;
        float a;
        if (smm[l] == 0.f) {
            a = 1e-8f;
        } else {
            a = expf(SCALE_F * (g_S[o] - mx)) * inv_s * mav;
            a = fmaxf(a, 1e-8f);
        }
        g_S[o] = a;
    }
}

// cm0[m] = 1e-8 * sum over mm==0 patches of R[l,m] (constant column of paste)
__global__ void cm0_kernel(const float* __restrict__ x1b) {
    int m = blockIdx.x * 256 + threadIdx.x;   // 2048 threads
    int c = m >> 4, ky = (m >> 2) & 3, kx = m & 3;
    int n0 = g_cnt[1];
    float s = 0.f;
    for (int i = 0; i < n0; i++) {
        int l = g_idx0[i];
        int li = l >> 6, lj = l & 63;
        int u = 2 * li - 1 + ky, v = 2 * lj - 1 + kx;
        if ((unsigned)u < 128u && (unsigned)v < 128u)
            s += x1b[c * (H1 * W1) + u * W1 + v];
    }
    g_cm0[m] = 1e-8f * s;
}

// paste GEMM: Z[m,p] = sum_{k<n1} R[idx1[k], m] * A[idx1[k], p] + cm0[m]
// M=2048, N=4096, K=n1 (~2940). 128x128 tile, BK=8, 8x8 microtile.
__global__ void __launch_bounds__(256, 2) paste_gemm(const float* __restrict__ x1b) {
    __shared__ float sR[8][128];
    __shared__ float sS[8][128];
    int t = threadIdx.x;
    int m0 = blockIdx.x * 128;
    int p0 = blockIdx.y * 128;
    int n1 = g_cnt[0];
    int nK = (n1 + 7) >> 3;
    int tx = t & 15, ty = t >> 4;
    float acc[8][8] = {};
    for (int kt = 0; kt < nK; kt++) {
#pragma unroll
        for (int i = 0; i < 4; i++) {
            int e = i * 256 + t;            // 0..1023
            int kk = e >> 7, q = e & 127;
            int kg = kt * 8 + kk;
            float rv = 0.f, sv = 0.f;
            if (kg < n1) {
                int l = g_idx1[kg];
                int m = m0 + q;
                int c = m >> 4, ky = (m >> 2) & 3, kx = m & 3;
                int li = l >> 6, lj = l & 63;
                int u = 2 * li - 1 + ky, v = 2 * lj - 1 + kx;
                if ((unsigned)u < 128u && (unsigned)v < 128u)
                    rv = x1b[c * 16384 + u * 128 + v];
                sv = g_S[l * L + p0 + q];
            }
            sR[kk][q] = rv;
            sS[kk][q] = sv;
        }
        __syncthreads();
#pragma unroll
        for (int kk = 0; kk < 8; kk++) {
            float a[8], b[8];
#pragma unroll
            for (int i = 0; i < 8; i++) a[i] = sR[kk][ty * 8 + i];
#pragma unroll
            for (int j = 0; j < 8; j++) b[j] = sS[kk][tx * 8 + j];
#pragma unroll
            for (int i = 0; i < 8; i++)
#pragma unroll
                for (int j = 0; j < 8; j++) acc[i][j] += a[i] * b[j];
        }
        __syncthreads();
    }
#pragma unroll
    for (int i = 0; i < 8; i++) {
        int m = m0 + ty * 8 + i;
        float c0 = g_cm0[m];
#pragma unroll
        for (int j = 0; j < 8; j += 4) {
            float4 v = make_float4(acc[i][j] + c0, acc[i][j + 1] + c0,
                                   acc[i][j + 2] + c0, acc[i][j + 3] + c0);
            *(float4*)&g_Z[m * L + p0 + tx * 8 + j] = v;
        }
    }
}

// overlap-add: y[b,c,u,v] = 0.25 * sum over <=4 covering patches of Z
__global__ void scatter_kernel(int b) {
    int idx = blockIdx.x * 256 + threadIdx.x;  // [0, 128*128*128)
    int v = idx & 127, u = (idx >> 7) & 127, c = idx >> 14;
    float s = 0.f;
    int ky0 = (u + 1) & 1, kx0 = (v + 1) & 1;
#pragma unroll
    for (int a = 0; a < 2; a++) {
        int ky = ky0 + 2 * a;
        int i2 = u + 1 - ky;
        if (i2 < 0 || i2 > 126) continue;
        int pi = i2 >> 1;
#pragma unroll
        for (int q = 0; q < 2; q++) {
            int kx = kx0 + 2 * q;
            int j2 = v + 1 - kx;
            if (j2 < 0 || j2 > 126) continue;
            int pj = j2 >> 1;
            int m = c * 16 + ky * 4 + kx;
            s += g_Z[m * L + pi * 64 + pj];
        }
    }
    g_y[b * (C1 * H1 * W1) + idx] = 0.25f * s;
}

// final 4-group dilated 3x3 convs (rates 1,2,4,8) + bias + relu
__global__ void __launch_bounds__(256) final_conv(const float* __restrict__ w,
                                                  const float* __restrict__ bias,
                                                  float* __restrict__ out) {
    __shared__ float sy[32 * 32];
    __shared__ float sw[16 * 9];
    int t = threadIdx.x;
    int tv = t & 15, tu = t >> 4;
    int tile = blockIdx.x;
    int u0 = (tile >> 3) * 16, v0 = (tile & 7) * 16;
    int bg = blockIdx.y;
    int b = bg >> 2, g = bg & 3;
    int r = 1 << g;                       // rates 1,2,4,8
    int Wt = 16 + 2 * r;
    const float* yb = g_y + b * (C1 * H1 * W1);
    float acc[16] = {};
    for (int c = 0; c < C1; c++) {
        const float* yc = yb + c * (H1 * W1);
        for (int e = t; e < Wt * Wt; e += 256) {
            int lu = e / Wt, lv = e % Wt;
            int gu = u0 - r + lu, gv = v0 - r + lv;
            float val = 0.f;
            if ((unsigned)gu < 128u && (unsigned)gv < 128u) val = yc[gu * 128 + gv];
            sy[lu * Wt + lv] = val;
        }
        if (t < 144) sw[t] = w[((g * 16 + (t / 9)) * C1 + c) * 9 + (t % 9)];
        __syncthreads();
#pragma unroll
        for (int kh = 0; kh < 3; kh++)
#pragma unroll
            for (int kw = 0; kw < 3; kw++) {
                float val = sy[(tu + kh * r) * Wt + (tv + kw * r)];
#pragma unroll
                for (int oc = 0; oc < 16; oc++)
                    acc[oc] += sw[oc * 9 + kh * 3 + kw] * val;
            }
        __syncthreads();
    }
    int u = u0 + tu, v = v0 + tv;
#pragma unroll
    for (int oc = 0; oc < 16; oc++) {
        float o = acc[oc] + bias[g * 16 + oc];
        out[((b * 64 + g * 16 + oc) * 128 + u) * 128 + v] = fmaxf(o, 0.f);
    }
}

// ---------------------------------------------------------------------------
extern "C" void kernel_launch(void* const* d_in, const int* in_sizes, int n_in,
                              void* d_out, int out_size) {
    (void)in_sizes; (void)n_in; (void)out_size;
    const float* x1       = (const float*)d_in[0];
    const float* x2       = (const float*)d_in[1];
    const float* mask     = (const float*)d_in[2];
    const float* mask_all = (const float*)d_in[3];
    const float* conv_w   = (const float*)d_in[4];
    const float* conv_b   = (const float*)d_in[5];
    float* out = (float*)d_out;

    for (int b = 0; b < Bn; b++) {
        const float* x1b   = x1 + (size_t)b * C1 * H1 * W1;
        const float* x2b   = x2 + (size_t)b * C2 * H2 * W2;
        const float* maskb = mask + (size_t)b * H1 * W1;
        const float* mab   = mask_all + (size_t)b * L;

        pix2_kernel<<<16, 256>>>(x2b);
        invnorm_kernel<<<16, 256>>>();
        mm_kernel<<<16, 256>>>(maskb);
        compact_kernel<<<1, 256>>>();
        corr_gemm<<<dim3(64, 64), 256>>>(x2b);
        scores_kernel<<<dim3(16, L), 256>>>(mab);
        softmax_kernel<<<128, 256>>>(mab);
        cm0_kernel<<<8, 256>>>(x1b);
        paste_gemm<<<dim3(16, 32), 256>>>(x1b);
        scatter_kernel<<<8192, 256>>>(b);
    }
    final_conv<<<dim3(64, 16), 256>>>(conv_w, conv_b, out);
}

// round 2
// speedup vs baseline: 1.2225x; 1.2225x over previous
#include <cuda_runtime.h>
#include <math.h>

#define Bn 4
#define C1 128
#define H1 128
#define W1 128
#define C2 64
#define L 4096      // H2*W2 patches / pixels
#define M2 2048     // C1*4*4 patch elements
#define SCALE_F 10.0f

typedef unsigned long long ull;

// ---- static device scratch (allocation-free rule) ----
__device__ float g_corr[L * L];            // 64 MB  pixel gram matrix
__device__ float g_Ac[(size_t)L * L];      // 64 MB  compacted scores -> attention (dense k rows)
__device__ float g_Rc[(size_t)L * M2];     // 32 MB  compacted im2col of x1 patches
__device__ float g_Z[(size_t)M2 * L];      // 32 MB  paste GEMM result [m][p]
__device__ float g_y[Bn * C1 * H1 * W1];   // 33.5 MB pasted images
__device__ float g_pix2[L];
__device__ float g_invnorm[L];
__device__ float g_mm[L];
__device__ int   g_idx1[L];
__device__ int   g_idx0[L];
__device__ int   g_cnt[2];
__device__ float g_cm0[M2];

__device__ __forceinline__ ull ffma2(ull a, ull b, ull c) {
    asm("fma.rn.f32x2 %0, %1, %2, %0;" : "+l"(c) : "l"(a), "l"(b));
    return c;
}

// ---------------------------------------------------------------------------
__global__ void pix2_kernel(const float* __restrict__ x2b) {
    int a = blockIdx.x * 256 + threadIdx.x;
    float s = 0.f;
#pragma unroll 16
    for (int c = 0; c < C2; c++) { float v = x2b[c * L + a]; s += v * v; }
    g_pix2[a] = s;
}

__global__ void invnorm_kernel() {
    int l = blockIdx.x * 256 + threadIdx.x;
    int li = l >> 6, lj = l & 63;
    float s = 0.f;
#pragma unroll
    for (int dy = -1; dy <= 1; dy++)
#pragma unroll
        for (int dx = -1; dx <= 1; dx++) {
            int i = li + dy, j = lj + dx;
            if ((unsigned)i < 64u && (unsigned)j < 64u) s += g_pix2[i * 64 + j];
        }
    g_invnorm[l] = 1.0f / fmaxf(sqrtf(s), 1e-4f);
}

__global__ void mm_kernel(const float* __restrict__ maskb) {
    int l = blockIdx.x * 256 + threadIdx.x;
    int li = l >> 6, lj = l & 63;
    bool allzero = true;
#pragma unroll
    for (int ky = 0; ky < 4; ky++)
#pragma unroll
        for (int kx = 0; kx < 4; kx++) {
            int u = 2 * li - 1 + ky, v = 2 * lj - 1 + kx;
            if ((unsigned)u < (unsigned)H1 && (unsigned)v < (unsigned)W1) {
                if (maskb[u * W1 + v] != 0.f) allzero = false;
            }
        }
    g_mm[l] = allzero ? 1.f : 0.f;
}

__global__ void compact_kernel() {
    __shared__ int cnt1[256], off1[256], cnt0[256], off0[256];
    int t = threadIdx.x;
    int c1 = 0, c0 = 0;
    for (int i = 0; i < 16; i++) {
        if (g_mm[t * 16 + i] > 0.5f) c1++; else c0++;
    }
    cnt1[t] = c1; cnt0[t] = c0;
    __syncthreads();
    if (t == 0) {
        int s1 = 0, s0 = 0;
        for (int i = 0; i < 256; i++) {
            off1[i] = s1; s1 += cnt1[i];
            off0[i] = s0; s0 += cnt0[i];
        }
        g_cnt[0] = s1; g_cnt[1] = s0;
    }
    __syncthreads();
    int o1 = off1[t], o0 = off0[t];
    for (int i = 0; i < 16; i++) {
        int l = t * 16 + i;
        if (g_mm[l] > 0.5f) g_idx1[o1++] = l; else g_idx0[o0++] = l;
    }
}

// ---------------------------------------------------------------------------
// FFMA2 dense NT GEMM: Out[m][p] = sum_k Bmat[k][m] * Amat[k][p] (+ cm0[m])
// 128x128 tile, BK=8, 8x8 microtile packed as f32x2 pairs along p.
// Bmat tile is stored duplicated in smem: (v,v) pairs -> LDS.64 broadcast operand.
template<bool ADD_CM0>
__global__ void __launch_bounds__(256, 2) gemm_kernel(
        const float* __restrict__ Bmat, int bstride,
        const float* __restrict__ Amat,
        float* __restrict__ Out, int nKfixed) {
    __shared__ float sBd[2][8][256];   // duplicated m-operand
    __shared__ float sA[2][8][128];    // p-operand

    int t = threadIdx.x;
    int m0 = blockIdx.x * 128, p0 = blockIdx.y * 128;
    int nK = ADD_CM0 ? ((g_cnt[0] + 7) >> 3) : nKfixed;

    int lr = t >> 5;            // smem row 0..7
    int lc = (t & 31) * 4;      // smem col (float4)
    const float* Bp = Bmat + (size_t)lr * bstride + m0 + lc;
    const float* Ap = Amat + (size_t)lr * L + p0 + lc;

    // prologue: tile 0 -> buffer 0
    float4 rb = *(const float4*)Bp;
    float4 ra = *(const float4*)Ap;
    *(float4*)&sBd[0][lr][2 * lc]     = make_float4(rb.x, rb.x, rb.y, rb.y);
    *(float4*)&sBd[0][lr][2 * lc + 4] = make_float4(rb.z, rb.z, rb.w, rb.w);
    *(float4*)&sA[0][lr][lc] = ra;
    __syncthreads();

    int tx = t & 15, ty = t >> 4;
    ull acc2[8][4] = {};

    for (int kt = 0; kt < nK; kt++) {
        int cur = kt & 1, nxt = cur ^ 1;
        if (kt + 1 < nK) {
            rb = *(const float4*)(Bp + (size_t)(kt + 1) * 8 * bstride);
            ra = *(const float4*)(Ap + (size_t)(kt + 1) * 8 * L);
        }
#pragma unroll
        for (int kk = 0; kk < 8; kk++) {
            ull bb[4];
            ulonglong2 b01 = *(const ulonglong2*)&sA[cur][kk][tx * 8];
            ulonglong2 b23 = *(const ulonglong2*)&sA[cur][kk][tx * 8 + 4];
            bb[0] = b01.x; bb[1] = b01.y; bb[2] = b23.x; bb[3] = b23.y;
#pragma unroll
            for (int i = 0; i < 8; i++) {
                ull ad = *(const ull*)&sBd[cur][kk][(ty * 8 + i) * 2];
#pragma unroll
                for (int j = 0; j < 4; j++)
                    acc2[i][j] = ffma2(ad, bb[j], acc2[i][j]);
            }
        }
        if (kt + 1 < nK) {
            *(float4*)&sBd[nxt][lr][2 * lc]     = make_float4(rb.x, rb.x, rb.y, rb.y);
            *(float4*)&sBd[nxt][lr][2 * lc + 4] = make_float4(rb.z, rb.z, rb.w, rb.w);
            *(float4*)&sA[nxt][lr][lc] = ra;
        }
        __syncthreads();
    }

#pragma unroll
    for (int i = 0; i < 8; i++) {
        int m = m0 + ty * 8 + i;
        float c0 = ADD_CM0 ? g_cm0[m] : 0.f;
        float r[8];
#pragma unroll
        for (int j = 0; j < 4; j++) {
            union { ull u; float2 f; } cv; cv.u = acc2[i][j];
            r[2 * j]     = cv.f.x + c0;
            r[2 * j + 1] = cv.f.y + c0;
        }
        *(float4*)&Out[(size_t)m * L + p0 + tx * 8]     = make_float4(r[0], r[1], r[2], r[3]);
        *(float4*)&Out[(size_t)m * L + p0 + tx * 8 + 4] = make_float4(r[4], r[5], r[6], r[7]);
    }
}

// ---------------------------------------------------------------------------
// Rc[k][m] = im2col of x1 patch idx1[k]; zero-pad rows [n1, npad)
__global__ void build_Rc(const float* __restrict__ x1b) {
    int k = blockIdx.x;
    int n1 = g_cnt[0];
    int npad = (n1 + 7) & ~7;
    if (k >= npad) return;
    int t = threadIdx.x;
    if (k >= n1) {
#pragma unroll
        for (int j = 0; j < 8; j++) g_Rc[(size_t)k * M2 + t + j * 256] = 0.f;
        return;
    }
    int l = g_idx1[k];
    int li = l >> 6, lj = l & 63;
#pragma unroll
    for (int j = 0; j < 8; j++) {
        int m = t + j * 256;
        int c = m >> 4, ky = (m >> 2) & 3, kx = m & 3;
        int u = 2 * li - 1 + ky, v = 2 * lj - 1 + kx;
        float val = 0.f;
        if ((unsigned)u < 128u && (unsigned)v < 128u) val = x1b[c * 16384 + u * 128 + v];
        g_Rc[(size_t)k * M2 + m] = val;
    }
}

// scores for active rows only, written dense: Ac[k][p]
__global__ void scores_kernel(const float* __restrict__ mab) {
    int k = blockIdx.y;
    if (k >= g_cnt[0]) return;
    int l = g_idx1[k];
    int p = blockIdx.x * 256 + threadIdx.x;
    int li = l >> 6, lj = l & 63, pi = p >> 6, pj = p & 63;
    float s = 0.f;
#pragma unroll
    for (int dy = -1; dy <= 1; dy++)
#pragma unroll
        for (int dx = -1; dx <= 1; dx++) {
            if ((unsigned)(li + dy) < 64u && (unsigned)(lj + dx) < 64u &&
                (unsigned)(pi + dy) < 64u && (unsigned)(pj + dx) < 64u) {
                int o = dy * 64 + dx;
                s += g_corr[(l + o) * L + (p + o)];
            }
        }
    g_Ac[(size_t)k * L + p] = s * g_invnorm[l] * mab[p];
}

// column softmax over all 4096 rows, but only n1 rows are materialized;
// the n0 masked rows are all exactly 0 pre-softmax -> closed-form sum term.
__global__ void softmax_kernel(const float* __restrict__ mab) {
    __shared__ float red[8][32];
    int t = threadIdx.x;
    int col = t & 31, part = t >> 5;
    int p = blockIdx.x * 32 + col;
    int n1 = g_cnt[0], n0 = g_cnt[1];
    int npad = (n1 + 7) & ~7;

    float mx = 0.f;   // masked rows contribute value 0
    for (int k = part; k < n1; k += 8) mx = fmaxf(mx, g_Ac[(size_t)k * L + p]);
    red[part][col] = mx;
    __syncthreads();
    if (t < 32) {
        float m = red[0][t];
        for (int q = 1; q < 8; q++) m = fmaxf(m, red[q][t]);
        red[0][t] = m;
    }
    __syncthreads();
    mx = red[0][col];
    __syncthreads();

    float sm = 0.f;
    for (int k = part; k < n1; k += 8) {
        size_t o = (size_t)k * L + p;
        float e = __expf(SCALE_F * (g_Ac[o] - mx));
        g_Ac[o] = e;
        sm += e;
    }
    red[part][col] = sm;
    __syncthreads();
    if (t < 32) {
        float s2 = 0.f;
        for (int q = 0; q < 8; q++) s2 += red[q][t];
        s2 += (float)n0 * __expf(-SCALE_F * mx);   // masked rows (value 0)
        red[0][t] = s2;
    }
    __syncthreads();
    float inv_s = 1.0f / red[0][col];
    float mav = mab[p];
    for (int k = part; k < n1; k += 8) {
        size_t o = (size_t)k * L + p;
        g_Ac[o] = fmaxf(g_Ac[o] * inv_s * mav, 1e-8f);
    }
    for (int k = n1 + part; k < npad; k += 8) g_Ac[(size_t)k * L + p] = 0.f;
}

// cm0[m] = 1e-8 * sum over mm==0 patches of R[l,m]
__global__ void cm0_kernel(const float* __restrict__ x1b) {
    int m = blockIdx.x * 256 + threadIdx.x;
    int c = m >> 4, ky = (m >> 2) & 3, kx = m & 3;
    int n0 = g_cnt[1];
    float s = 0.f;
    for (int i = 0; i < n0; i++) {
        int l = g_idx0[i];
        int li = l >> 6, lj = l & 63;
        int u = 2 * li - 1 + ky, v = 2 * lj - 1 + kx;
        if ((unsigned)u < 128u && (unsigned)v < 128u)
            s += x1b[c * (H1 * W1) + u * W1 + v];
    }
    g_cm0[m] = 1e-8f * s;
}

// overlap-add: y[b,c,u,v] = 0.25 * sum over <=4 covering patches of Z
__global__ void scatter_kernel(int b) {
    int idx = blockIdx.x * 256 + threadIdx.x;
    int v = idx & 127, u = (idx >> 7) & 127, c = idx >> 14;
    float s = 0.f;
    int ky0 = (u + 1) & 1, kx0 = (v + 1) & 1;
#pragma unroll
    for (int a = 0; a < 2; a++) {
        int ky = ky0 + 2 * a;
        int i2 = u + 1 - ky;
        if (i2 < 0 || i2 > 126) continue;
        int pi = i2 >> 1;
#pragma unroll
        for (int q = 0; q < 2; q++) {
            int kx = kx0 + 2 * q;
            int j2 = v + 1 - kx;
            if (j2 < 0 || j2 > 126) continue;
            int pj = j2 >> 1;
            int m = c * 16 + ky * 4 + kx;
            s += g_Z[(size_t)m * L + pi * 64 + pj];
        }
    }
    g_y[b * (C1 * H1 * W1) + idx] = 0.25f * s;
}

// final 4-group dilated 3x3 convs (rates 1,2,4,8) + bias + relu
__global__ void __launch_bounds__(256) final_conv(const float* __restrict__ w,
                                                  const float* __restrict__ bias,
                                                  float* __restrict__ out) {
    __shared__ float sy[32 * 32];
    __shared__ float sw[16 * 9];
    int t = threadIdx.x;
    int tv = t & 15, tu = t >> 4;
    int tile = blockIdx.x;
    int u0 = (tile >> 3) * 16, v0 = (tile & 7) * 16;
    int bg = blockIdx.y;
    int b = bg >> 2, g = bg & 3;
    int r = 1 << g;
    int Wt = 16 + 2 * r;
    const float* yb = g_y + b * (C1 * H1 * W1);
    float acc[16] = {};
    for (int c = 0; c < C1; c++) {
        const float* yc = yb + c * (H1 * W1);
        for (int e = t; e < Wt * Wt; e += 256) {
            int lu = e / Wt, lv = e % Wt;
            int gu = u0 - r + lu, gv = v0 - r + lv;
            float val = 0.f;
            if ((unsigned)gu < 128u && (unsigned)gv < 128u) val = yc[gu * 128 + gv];
            sy[lu * Wt + lv] = val;
        }
        if (t < 144) sw[t] = w[((g * 16 + (t / 9)) * C1 + c) * 9 + (t % 9)];
        __syncthreads();
#pragma unroll
        for (int kh = 0; kh < 3; kh++)
#pragma unroll
            for (int kw = 0; kw < 3; kw++) {
                float val = sy[(tu + kh * r) * Wt + (tv + kw * r)];
#pragma unroll
                for (int oc = 0; oc < 16; oc++)
                    acc[oc] += sw[oc * 9 + kh * 3 + kw] * val;
            }
        __syncthreads();
    }
    int u = u0 + tu, v = v0 + tv;
#pragma unroll
    for (int oc = 0; oc < 16; oc++) {
        float o = acc[oc] + bias[g * 16 + oc];
        out[((b * 64 + g * 16 + oc) * 128 + u) * 128 + v] = fmaxf(o, 0.f);
    }
}

// ---------------------------------------------------------------------------
extern "C" void kernel_launch(void* const* d_in, const int* in_sizes, int n_in,
                              void* d_out, int out_size) {
    (void)in_sizes; (void)n_in; (void)out_size;
    const float* x1       = (const float*)d_in[0];
    const float* x2       = (const float*)d_in[1];
    const float* mask     = (const float*)d_in[2];
    const float* mask_all = (const float*)d_in[3];
    const float* conv_w   = (const float*)d_in[4];
    const float* conv_b   = (const float*)d_in[5];
    float* out = (float*)d_out;

    float* d_corr; cudaGetSymbolAddress((void**)&d_corr, g_corr);
    float* d_Ac;   cudaGetSymbolAddress((void**)&d_Ac,   g_Ac);
    float* d_Rc;   cudaGetSymbolAddress((void**)&d_Rc,   g_Rc);
    float* d_Z;    cudaGetSymbolAddress((void**)&d_Z,    g_Z);

    for (int b = 0; b < Bn; b++) {
        const float* x1b   = x1 + (size_t)b * C1 * H1 * W1;
        const float* x2b   = x2 + (size_t)b * C2 * 64 * 64;
        const float* maskb = mask + (size_t)b * H1 * W1;
        const float* mab   = mask_all + (size_t)b * L;

        pix2_kernel<<<16, 256>>>(x2b);
        invnorm_kernel<<<16, 256>>>();
        mm_kernel<<<16, 256>>>(maskb);
        compact_kernel<<<1, 256>>>();
        // Corr = X^T X   (K = 64 channels, nK = 8)
        gemm_kernel<false><<<dim3(32, 32), 256>>>(x2b, L, x2b, d_corr, 8);
        build_Rc<<<L, 256>>>(x1b);
        cm0_kernel<<<8, 256>>>(x1b);
        scores_kernel<<<dim3(16, L), 256>>>(mab);
        softmax_kernel<<<128, 256>>>(mab);
        // paste: Z = Rc^T * Ac  (K = n1 padded, read on device)
        gemm_kernel<true><<<dim3(16, 32), 256>>>(d_Rc, M2, d_Ac, d_Z, 0);
        scatter_kernel<<<8192, 256>>>(b);
    }
    final_conv<<<dim3(64, 16), 256>>>(conv_w, conv_b, out);
}

// round 4
// speedup vs baseline: 1.9292x; 1.5781x over previous
#include <cuda_runtime.h>
#include <cuda_bf16.h>
#include <math.h>
#include <stdint.h>

#define Bn 4
#define C1 128
#define H1 128
#define W1 128
#define C2 64
#define L 4096      // H2*W2 patches / pixels
#define M2 2048     // C1*4*4 patch elements
#define KS3 12288   // K stride for bf16 triple arrays (3 * max n1)
#define SCALE_F 10.0f

typedef unsigned long long ull;

// ---- static device scratch (allocation-free rule) ----
__device__ float g_corr[L * L];                 // 64 MB  pixel gram matrix
__device__ float g_Ac[(size_t)L * L];           // 64 MB  compacted scores -> attention
__device__ float g_Z[(size_t)M2 * L];           // 32 MB  paste GEMM result [m][p]
__device__ float g_y[Bn * C1 * H1 * W1];        // 33.5 MB pasted images
__device__ __nv_bfloat16 g_Rc3[(size_t)M2 * KS3]; // 48 MB  A triples [m][3k]
__device__ __nv_bfloat16 g_Ac3[(size_t)L * KS3];  // 96 MB  B triples [p][3k]
__device__ float g_pix2[L];
__device__ float g_invnorm[L];
__device__ float g_mm[L];
__device__ int   g_idx1[L];
__device__ int   g_idx0[L];
__device__ int   g_cnt[2];
__device__ float g_cm0[M2];

__device__ __forceinline__ ull ffma2(ull a, ull b, ull c) {
    asm("fma.rn.f32x2 %0, %1, %2, %0;" : "+l"(c) : "l"(a), "l"(b));
    return c;
}

__device__ __forceinline__ uint32_t smem_u32(const void* p) {
    uint32_t a;
    asm("{ .reg .u64 t; cvta.to.shared.u64 t, %1; cvt.u32.u64 %0, t; }" : "=r"(a) : "l"(p));
    return a;
}

__device__ __forceinline__ void split_bf16(float v, __nv_bfloat16& h, __nv_bfloat16& l) {
    h = __float2bfloat16(v);
    l = __float2bfloat16(v - __bfloat162float(h));
}

// ---------------------------------------------------------------------------
__global__ void pix2_kernel(const float* __restrict__ x2b) {
    int a = blockIdx.x * 256 + threadIdx.x;
    float s = 0.f;
#pragma unroll 16
    for (int c = 0; c < C2; c++) { float v = x2b[c * L + a]; s += v * v; }
    g_pix2[a] = s;
}

__global__ void invnorm_kernel() {
    int l = blockIdx.x * 256 + threadIdx.x;
    int li = l >> 6, lj = l & 63;
    float s = 0.f;
#pragma unroll
    for (int dy = -1; dy <= 1; dy++)
#pragma unroll
        for (int dx = -1; dx <= 1; dx++) {
            int i = li + dy, j = lj + dx;
            if ((unsigned)i < 64u && (unsigned)j < 64u) s += g_pix2[i * 64 + j];
        }
    g_invnorm[l] = 1.0f / fmaxf(sqrtf(s), 1e-4f);
}

__global__ void mm_kernel(const float* __restrict__ maskb) {
    int l = blockIdx.x * 256 + threadIdx.x;
    int li = l >> 6, lj = l & 63;
    bool allzero = true;
#pragma unroll
    for (int ky = 0; ky < 4; ky++)
#pragma unroll
        for (int kx = 0; kx < 4; kx++) {
            int u = 2 * li - 1 + ky, v = 2 * lj - 1 + kx;
            if ((unsigned)u < (unsigned)H1 && (unsigned)v < (unsigned)W1) {
                if (maskb[u * W1 + v] != 0.f) allzero = false;
            }
        }
    g_mm[l] = allzero ? 1.f : 0.f;
}

__global__ void compact_kernel() {
    __shared__ int cnt1[256], off1[256], cnt0[256], off0[256];
    int t = threadIdx.x;
    int c1 = 0, c0 = 0;
    for (int i = 0; i < 16; i++) {
        if (g_mm[t * 16 + i] > 0.5f) c1++; else c0++;
    }
    cnt1[t] = c1; cnt0[t] = c0;
    __syncthreads();
    if (t == 0) {
        int s1 = 0, s0 = 0;
        for (int i = 0; i < 256; i++) {
            off1[i] = s1; s1 += cnt1[i];
            off0[i] = s0; s0 += cnt0[i];
        }
        g_cnt[0] = s1; g_cnt[1] = s0;
    }
    __syncthreads();
    int o1 = off1[t], o0 = off0[t];
    for (int i = 0; i < 16; i++) {
        int l = t * 16 + i;
        if (g_mm[l] > 0.5f) g_idx1[o1++] = l; else g_idx0[o0++] = l;
    }
}

// ---------------------------------------------------------------------------
// FFMA2 dense NT GEMM (used for Corr = X^T X, K=64)
__global__ void __launch_bounds__(256, 2) corr_gemm(
        const float* __restrict__ Bmat, const float* __restrict__ Amat,
        float* __restrict__ Out) {
    __shared__ float sBd[2][8][256];
    __shared__ float sA[2][8][128];
    int t = threadIdx.x;
    int m0 = blockIdx.x * 128, p0 = blockIdx.y * 128;
    const int nK = 8;
    int lr = t >> 5, lc = (t & 31) * 4;
    const float* Bp = Bmat + (size_t)lr * L + m0 + lc;
    const float* Ap = Amat + (size_t)lr * L + p0 + lc;
    float4 rb = *(const float4*)Bp;
    float4 ra = *(const float4*)Ap;
    *(float4*)&sBd[0][lr][2 * lc]     = make_float4(rb.x, rb.x, rb.y, rb.y);
    *(float4*)&sBd[0][lr][2 * lc + 4] = make_float4(rb.z, rb.z, rb.w, rb.w);
    *(float4*)&sA[0][lr][lc] = ra;
    __syncthreads();
    int tx = t & 15, ty = t >> 4;
    ull acc2[8][4] = {};
    for (int kt = 0; kt < nK; kt++) {
        int cur = kt & 1, nxt = cur ^ 1;
        if (kt + 1 < nK) {
            rb = *(const float4*)(Bp + (size_t)(kt + 1) * 8 * L);
            ra = *(const float4*)(Ap + (size_t)(kt + 1) * 8 * L);
        }
#pragma unroll
        for (int kk = 0; kk < 8; kk++) {
            ull bb[4];
            ulonglong2 b01 = *(const ulonglong2*)&sA[cur][kk][tx * 8];
            ulonglong2 b23 = *(const ulonglong2*)&sA[cur][kk][tx * 8 + 4];
            bb[0] = b01.x; bb[1] = b01.y; bb[2] = b23.x; bb[3] = b23.y;
#pragma unroll
            for (int i = 0; i < 8; i++) {
                ull ad = *(const ull*)&sBd[cur][kk][(ty * 8 + i) * 2];
#pragma unroll
                for (int j = 0; j < 4; j++)
                    acc2[i][j] = ffma2(ad, bb[j], acc2[i][j]);
            }
        }
        if (kt + 1 < nK) {
            *(float4*)&sBd[nxt][lr][2 * lc]     = make_float4(rb.x, rb.x, rb.y, rb.y);
            *(float4*)&sBd[nxt][lr][2 * lc + 4] = make_float4(rb.z, rb.z, rb.w, rb.w);
            *(float4*)&sA[nxt][lr][lc] = ra;
        }
        __syncthreads();
    }
#pragma unroll
    for (int i = 0; i < 8; i++) {
        int m = m0 + ty * 8 + i;
        float r[8];
#pragma unroll
        for (int j = 0; j < 4; j++) {
            union { ull u; float2 f; } cv; cv.u = acc2[i][j];
            r[2 * j] = cv.f.x; r[2 * j + 1] = cv.f.y;
        }
        *(float4*)&Out[(size_t)m * L + p0 + tx * 8]     = make_float4(r[0], r[1], r[2], r[3]);
        *(float4*)&Out[(size_t)m * L + p0 + tx * 8 + 4] = make_float4(r[4], r[5], r[6], r[7]);
    }
}

// ---------------------------------------------------------------------------
// Rc3[m][3k..3k+2] = (hi, hi, lo) bf16 triple of im2col(x1)[idx1[k]][m]
__global__ void build_Rc3(const float* __restrict__ x1b) {
    int k = blockIdx.x * 256 + threadIdx.x;
    int m = blockIdx.y;
    int n1 = g_cnt[0];
    int n1p = (n1 + 31) & ~31;
    if (k >= n1p) return;
    float val = 0.f;
    if (k < n1) {
        int l = g_idx1[k];
        int li = l >> 6, lj = l & 63;
        int c = m >> 4, ky = (m >> 2) & 3, kx = m & 3;
        int u = 2 * li - 1 + ky, v = 2 * lj - 1 + kx;
        if ((unsigned)u < 128u && (unsigned)v < 128u) val = x1b[c * 16384 + u * 128 + v];
    }
    __nv_bfloat16 h, lo;
    split_bf16(val, h, lo);
    size_t o = (size_t)m * KS3 + 3 * k;
    g_Rc3[o] = h; g_Rc3[o + 1] = h; g_Rc3[o + 2] = lo;
}

// scores for active rows only, written dense: Ac[k][p]
__global__ void scores_kernel(const float* __restrict__ mab) {
    int k = blockIdx.y;
    if (k >= g_cnt[0]) return;
    int l = g_idx1[k];
    int p = blockIdx.x * 256 + threadIdx.x;
    int li = l >> 6, lj = l & 63, pi = p >> 6, pj = p & 63;
    float s = 0.f;
#pragma unroll
    for (int dy = -1; dy <= 1; dy++)
#pragma unroll
        for (int dx = -1; dx <= 1; dx++) {
            if ((unsigned)(li + dy) < 64u && (unsigned)(lj + dx) < 64u &&
                (unsigned)(pi + dy) < 64u && (unsigned)(pj + dx) < 64u) {
                int o = dy * 64 + dx;
                s += g_corr[(l + o) * L + (p + o)];
            }
        }
    g_Ac[(size_t)k * L + p] = s * g_invnorm[l] * mab[p];
}

// column softmax over all 4096 rows (masked rows = closed form)
__global__ void softmax_kernel(const float* __restrict__ mab) {
    __shared__ float red[8][32];
    int t = threadIdx.x;
    int col = t & 31, part = t >> 5;
    int p = blockIdx.x * 32 + col;
    int n1 = g_cnt[0], n0 = g_cnt[1];

    float mx = 0.f;
    for (int k = part; k < n1; k += 8) mx = fmaxf(mx, g_Ac[(size_t)k * L + p]);
    red[part][col] = mx;
    __syncthreads();
    if (t < 32) {
        float m = red[0][t];
        for (int q = 1; q < 8; q++) m = fmaxf(m, red[q][t]);
        red[0][t] = m;
    }
    __syncthreads();
    mx = red[0][col];
    __syncthreads();

    float sm = 0.f;
    for (int k = part; k < n1; k += 8) {
        size_t o = (size_t)k * L + p;
        float e = __expf(SCALE_F * (g_Ac[o] - mx));
        g_Ac[o] = e;
        sm += e;
    }
    red[part][col] = sm;
    __syncthreads();
    if (t < 32) {
        float s2 = 0.f;
        for (int q = 0; q < 8; q++) s2 += red[q][t];
        s2 += (float)n0 * __expf(-SCALE_F * mx);
        red[0][t] = s2;
    }
    __syncthreads();
    float inv_s = 1.0f / red[0][col];
    float mav = mab[p];
    for (int k = part; k < n1; k += 8) {
        size_t o = (size_t)k * L + p;
        g_Ac[o] = fmaxf(g_Ac[o] * inv_s * mav, 1e-8f);
    }
}

// transpose + triple-split: Ac[k][p] -> Ac3[p][3k..3k+2] = (hi, lo, hi)
__global__ void __launch_bounds__(256) transpose_split3() {
    __shared__ float s[32][33];
    int n1 = g_cnt[0];
    int n1p = (n1 + 31) & ~31;
    int k0 = blockIdx.x * 32, p0 = blockIdx.y * 32;
    if (k0 >= n1p) return;
    int t = threadIdx.x;
    int pp = t & 31, kk = t >> 5;
#pragma unroll
    for (int i = 0; i < 4; i++) {
        int k = k0 + kk + i * 8;
        s[kk + i * 8][pp] = (k < n1) ? g_Ac[(size_t)k * L + p0 + pp] : 0.f;
    }
    __syncthreads();
    int kx = t & 31, py = t >> 5;
#pragma unroll
    for (int i = 0; i < 4; i++) {
        int p = p0 + py + i * 8;
        float v = s[kx][py + i * 8];
        __nv_bfloat16 h, lo;
        split_bf16(v, h, lo);
        size_t o = (size_t)p * KS3 + 3 * (k0 + kx);
        g_Ac3[o] = h; g_Ac3[o + 1] = lo; g_Ac3[o + 2] = h;
    }
}

// cm0[m] = 1e-8 * sum over mm==0 patches of R[l,m]
__global__ void cm0_kernel(const float* __restrict__ x1b) {
    int m = blockIdx.x * 256 + threadIdx.x;
    int c = m >> 4, ky = (m >> 2) & 3, kx = m & 3;
    int n0 = g_cnt[1];
    float s = 0.f;
    for (int i = 0; i < n0; i++) {
        int l = g_idx0[i];
        int li = l >> 6, lj = l & 63;
        int u = 2 * li - 1 + ky, v = 2 * lj - 1 + kx;
        if ((unsigned)u < 128u && (unsigned)v < 128u)
            s += x1b[c * (H1 * W1) + u * W1 + v];
    }
    g_cm0[m] = 1e-8f * s;
}

// ---------------------------------------------------------------------------
// HMMA paste GEMM: Z[m,p] = sum_K3 Rc3[m,k]*Ac3[p,k] + cm0[m]
// CTA tile 128(m) x 256(p), BK=32, 8 warps of 64x64, 3-stage cp.async.
#define GSTAGES 3
#define ABYTES (128 * 64)          // 128 rows x 32 bf16
#define BBYTES (256 * 64)
#define STAGE_B (ABYTES + BBYTES)  // 24576
#define SMEM_GEMM (GSTAGES * STAGE_B)

__device__ __forceinline__ void cp_async16(uint32_t dst, const void* src) {
    asm volatile("cp.async.cg.shared.global [%0], [%1], 16;" :: "r"(dst), "l"(src) : "memory");
}
__device__ __forceinline__ void ldsm4(uint32_t& r0, uint32_t& r1, uint32_t& r2, uint32_t& r3,
                                      uint32_t a) {
    asm volatile("ldmatrix.sync.aligned.m8n8.x4.shared.b16 {%0,%1,%2,%3}, [%4];"
                 : "=r"(r0), "=r"(r1), "=r"(r2), "=r"(r3) : "r"(a));
}
__device__ __forceinline__ void mma16816(float* c, const uint32_t* a, uint32_t b0, uint32_t b1) {
    asm volatile(
        "mma.sync.aligned.m16n8k16.row.col.f32.bf16.bf16.f32 "
        "{%0,%1,%2,%3}, {%4,%5,%6,%7}, {%8,%9}, {%0,%1,%2,%3};"
        : "+f"(c[0]), "+f"(c[1]), "+f"(c[2]), "+f"(c[3])
        : "r"(a[0]), "r"(a[1]), "r"(a[2]), "r"(a[3]), "r"(b0), "r"(b1));
}

__global__ void __launch_bounds__(256, 1) paste_hmma() {
    extern __shared__ __align__(16) char smem[];
    uint32_t sb = smem_u32(smem);
    int t = threadIdx.x;
    int lane = t & 31;
    int wr = (t >> 5) & 1;        // warp m-row (0..1)
    int wc = t >> 6;              // warp p-col (0..3)
    int m0 = blockIdx.x * 128;
    int p0 = blockIdx.y * 256;
    int n1 = g_cnt[0];
    int n1p = (n1 + 31) & ~31;
    int nC = (3 * n1p) >> 5;      // K3 / 32

    const __nv_bfloat16* Abase = g_Rc3 + (size_t)m0 * KS3;
    const __nv_bfloat16* Bbase = g_Ac3 + (size_t)p0 * KS3;

    // cp.async one BK=32 chunk into stage s. 1536 x 16B, 6 per thread.
    auto load_chunk = [&](int kt, int s) {
        uint32_t stage = sb + s * STAGE_B;
        int k0 = kt * 32;
#pragma unroll
        for (int i = 0; i < 2; i++) {
            int e = t + i * 256;              // A: 512 chunks
            int row = e >> 2, c = e & 3;
            uint32_t dst = stage + row * 64 + ((c ^ (row & 3)) << 4);
            cp_async16(dst, Abase + (size_t)row * KS3 + k0 + c * 8);
        }
#pragma unroll
        for (int i = 0; i < 4; i++) {
            int e = t + i * 256;              // B: 1024 chunks
            int row = e >> 2, c = e & 3;
            uint32_t dst = stage + ABYTES + row * 64 + ((c ^ (row & 3)) << 4);
            cp_async16(dst, Bbase + (size_t)row * KS3 + k0 + c * 8);
        }
        asm volatile("cp.async.commit_group;" ::: "memory");
    };

#pragma unroll
    for (int s = 0; s < GSTAGES - 1; s++) {
        if (s < nC) load_chunk(s, s);
        else asm volatile("cp.async.commit_group;" ::: "memory");
    }

    float acc[4][8][4] = {};
    int r8 = lane & 7;
    int mat = lane >> 3;
    int rowSwz = r8 & 3;
    // ldmatrix row offsets (row base per fragment row set)
    int rA = wr * 64 + r8 + (mat & 1) * 8;   // + mi*16
    int rB = wc * 64 + r8 + (mat & 1) * 8;   // + nj*16
    int chi = mat >> 1;                       // k-half select

    for (int kt = 0; kt < nC; kt++) {
        asm volatile("cp.async.wait_group %0;" :: "n"(GSTAGES - 2) : "memory");
        __syncthreads();
        uint32_t stage = sb + (kt % GSTAGES) * STAGE_B;

        if (kt + GSTAGES - 1 < nC) load_chunk(kt + GSTAGES - 1, (kt + GSTAGES - 1) % GSTAGES);
        else asm volatile("cp.async.commit_group;" ::: "memory");

#pragma unroll
        for (int ks = 0; ks < 2; ks++) {
            int kc = ks * 2 + chi;            // 16B chunk index for this lane
            uint32_t a[4][4];
            uint32_t b[4][4];
#pragma unroll
            for (int mi = 0; mi < 4; mi++) {
                int row = rA + mi * 16;
                ldsm4(a[mi][0], a[mi][1], a[mi][2], a[mi][3],
                      stage + row * 64 + ((kc ^ rowSwz) << 4));
            }
#pragma unroll
            for (int nj = 0; nj < 4; nj++) {
                int row = rB + nj * 16;
                ldsm4(b[nj][0], b[nj][1], b[nj][2], b[nj][3],
                      stage + ABYTES + row * 64 + ((kc ^ rowSwz) << 4));
            }
#pragma unroll
            for (int mi = 0; mi < 4; mi++)
#pragma unroll
                for (int nj = 0; nj < 4; nj++) {
                    mma16816(acc[mi][nj * 2],     a[mi], b[nj][0], b[nj][2]);
                    mma16816(acc[mi][nj * 2 + 1], a[mi], b[nj][1], b[nj][3]);
                }
        }
        __syncthreads();
    }

    // epilogue: add cm0, store Z
    int cr = lane >> 2, cc = (lane & 3) * 2;
#pragma unroll
    for (int mi = 0; mi < 4; mi++) {
        int mbase = m0 + wr * 64 + mi * 16;
        float c0a = g_cm0[mbase + cr];
        float c0b = g_cm0[mbase + cr + 8];
#pragma unroll
        for (int ni = 0; ni < 8; ni++) {
            int p = p0 + wc * 64 + ni * 8 + cc;
            float* z0 = &g_Z[(size_t)(mbase + cr) * L + p];
            float* z1 = &g_Z[(size_t)(mbase + cr + 8) * L + p];
            *(float2*)z0 = make_float2(acc[mi][ni][0] + c0a, acc[mi][ni][1] + c0a);
            *(float2*)z1 = make_float2(acc[mi][ni][2] + c0b, acc[mi][ni][3] + c0b);
        }
    }
}

// ---------------------------------------------------------------------------
// overlap-add: y[b,c,u,v] = 0.25 * sum over <=4 covering patches of Z
__global__ void scatter_kernel(int b) {
    int idx = blockIdx.x * 256 + threadIdx.x;
    int v = idx & 127, u = (idx >> 7) & 127, c = idx >> 14;
    float s = 0.f;
    int ky0 = (u + 1) & 1, kx0 = (v + 1) & 1;
#pragma unroll
    for (int a = 0; a < 2; a++) {
        int ky = ky0 + 2 * a;
        int i2 = u + 1 - ky;
        if (i2 < 0 || i2 > 126) continue;
        int pi = i2 >> 1;
#pragma unroll
        for (int q = 0; q < 2; q++) {
            int kx = kx0 + 2 * q;
            int j2 = v + 1 - kx;
            if (j2 < 0 || j2 > 126) continue;
            int pj = j2 >> 1;
            int m = c * 16 + ky * 4 + kx;
            s += g_Z[(size_t)m * L + pi * 64 + pj];
        }
    }
    g_y[b * (C1 * H1 * W1) + idx] = 0.25f * s;
}

// final 4-group dilated 3x3 convs (rates 1,2,4,8) + bias + relu
__global__ void __launch_bounds__(256) final_conv(const float* __restrict__ w,
                                                  const float* __restrict__ bias,
                                                  float* __restrict__ out) {
    __shared__ float sy[32 * 32];
    __shared__ float sw[16 * 9];
    int t = threadIdx.x;
    int tv = t & 15, tu = t >> 4;
    int tile = blockIdx.x;
    int u0 = (tile >> 3) * 16, v0 = (tile & 7) * 16;
    int bg = blockIdx.y;
    int b = bg >> 2, g = bg & 3;
    int r = 1 << g;
    int Wt = 16 + 2 * r;
    const float* yb = g_y + b * (C1 * H1 * W1);
    float acc[16] = {};
    for (int c = 0; c < C1; c++) {
        const float* yc = yb + c * (H1 * W1);
        for (int e = t; e < Wt * Wt; e += 256) {
            int lu = e / Wt, lv = e % Wt;
            int gu = u0 - r + lu, gv = v0 - r + lv;
            float val = 0.f;
            if ((unsigned)gu < 128u && (unsigned)gv < 128u) val = yc[gu * 128 + gv];
            sy[lu * Wt + lv] = val;
        }
        if (t < 144) sw[t] = w[((g * 16 + (t / 9)) * C1 + c) * 9 + (t % 9)];
        __syncthreads();
#pragma unroll
        for (int kh = 0; kh < 3; kh++)
#pragma unroll
            for (int kw = 0; kw < 3; kw++) {
                float val = sy[(tu + kh * r) * Wt + (tv + kw * r)];
#pragma unroll
                for (int oc = 0; oc < 16; oc++)
                    acc[oc] += sw[oc * 9 + kh * 3 + kw] * val;
            }
        __syncthreads();
    }
    int u = u0 + tu, v = v0 + tv;
#pragma unroll
    for (int oc = 0; oc < 16; oc++) {
        float o = acc[oc] + bias[g * 16 + oc];
        out[((b * 64 + g * 16 + oc) * 128 + u) * 128 + v] = fmaxf(o, 0.f);
    }
}

// ---------------------------------------------------------------------------
extern "C" void kernel_launch(void* const* d_in, const int* in_sizes, int n_in,
                              void* d_out, int out_size) {
    (void)in_sizes; (void)n_in; (void)out_size;
    const float* x1       = (const float*)d_in[0];
    const float* x2       = (const float*)d_in[1];
    const float* mask     = (const float*)d_in[2];
    const float* mask_all = (const float*)d_in[3];
    const float* conv_w   = (const float*)d_in[4];
    const float* conv_b   = (const float*)d_in[5];
    float* out = (float*)d_out;

    cudaFuncSetAttribute(paste_hmma, cudaFuncAttributeMaxDynamicSharedMemorySize, SMEM_GEMM);

    float* d_corr; cudaGetSymbolAddress((void**)&d_corr, g_corr);

    for (int b = 0; b < Bn; b++) {
        const float* x1b   = x1 + (size_t)b * C1 * H1 * W1;
        const float* x2b   = x2 + (size_t)b * C2 * 64 * 64;
        const float* maskb = mask + (size_t)b * H1 * W1;
        const float* mab   = mask_all + (size_t)b * L;

        pix2_kernel<<<16, 256>>>(x2b);
        invnorm_kernel<<<16, 256>>>();
        mm_kernel<<<16, 256>>>(maskb);
        compact_kernel<<<1, 256>>>();
        corr_gemm<<<dim3(32, 32), 256>>>(x2b, x2b, d_corr);
        build_Rc3<<<dim3(16, 2048), 256>>>(x1b);
        cm0_kernel<<<8, 256>>>(x1b);
        scores_kernel<<<dim3(16, L), 256>>>(mab);
        softmax_kernel<<<128, 256>>>(mab);
        transpose_split3<<<dim3(128, 128), 256>>>();
        paste_hmma<<<dim3(16, 16), 256, SMEM_GEMM>>>();
        scatter_kernel<<<8192, 256>>>(b);
    }
    final_conv<<<dim3(64, 16), 256>>>(conv_w, conv_b, out);
}

// round 6
// speedup vs baseline: 2.5911x; 1.3430x over previous
#include <cuda_runtime.h>
#include <cuda_fp16.h>
#include <math.h>
#include <stdint.h>

#define Bn 4
#define C1 128
#define H1 128
#define W1 128
#define C2 64
#define L 4096      // H2*W2 patches / pixels
#define M2 2048     // C1*4*4 patch elements
#define KS 4096     // K stride for fp16 operand arrays
#define SCALE_F 10.0f
#define ASCALE 1024.0f

typedef unsigned long long ull;

// ---- static device scratch (allocation-free rule) ----
__device__ float g_corr[L * L];                    // 64 MB  pixel gram (reused per batch)
__device__ float g_Ac[(size_t)L * L];              // 64 MB  scores/attention (reused per batch)
__device__ __half g_Rch[Bn][(size_t)M2 * KS];      // 64 MB  A operand fp16 [b][m][k]
__device__ __half g_AcTh[Bn][(size_t)L * KS];      // 128 MB B operand fp16 [b][p][k]
__device__ float g_Z[Bn][(size_t)M2 * L];          // 128 MB paste result [b][m][p]
__device__ float g_y[Bn * C1 * H1 * W1];           // 33.5 MB pasted images
__device__ float g_pix2[L];
__device__ float g_invnorm[L];
__device__ float g_mm[L];
__device__ int   g_idx1[Bn][L];
__device__ int   g_cnt[Bn][2];
__device__ float g_cmT[Bn][M2];

__device__ __forceinline__ ull ffma2(ull a, ull b, ull c) {
    asm("fma.rn.f32x2 %0, %1, %2, %0;" : "+l"(c) : "l"(a), "l"(b));
    return c;
}

__device__ __forceinline__ ull packf2(float v) {
    ull r;
    uint32_t u = __float_as_uint(v);
    asm("mov.b64 %0, {%1, %1};" : "=l"(r) : "r"(u));
    return r;
}

__device__ __forceinline__ uint32_t smem_u32(const void* p) {
    uint32_t a;
    asm("{ .reg .u64 t; cvta.to.shared.u64 t, %1; cvt.u32.u64 %0, t; }" : "=r"(a) : "l"(p));
    return a;
}

// ---------------------------------------------------------------------------
// fused: pix2 (per-pixel squared norm of x2) + mm (mask-patch-all-zero flag)
__global__ void prep_kernel(const float* __restrict__ x2b, const float* __restrict__ maskb) {
    int a = blockIdx.x * 256 + threadIdx.x;
    float s = 0.f;
#pragma unroll 16
    for (int c = 0; c < C2; c++) { float v = x2b[c * L + a]; s += v * v; }
    g_pix2[a] = s;

    int li = a >> 6, lj = a & 63;
    bool allzero = true;
#pragma unroll
    for (int ky = 0; ky < 4; ky++)
#pragma unroll
        for (int kx = 0; kx < 4; kx++) {
            int u = 2 * li - 1 + ky, v = 2 * lj - 1 + kx;
            if ((unsigned)u < (unsigned)H1 && (unsigned)v < (unsigned)W1) {
                if (maskb[u * W1 + v] != 0.f) allzero = false;
            }
        }
    g_mm[a] = allzero ? 1.f : 0.f;
}

__global__ void invnorm_kernel() {
    int l = blockIdx.x * 256 + threadIdx.x;
    int li = l >> 6, lj = l & 63;
    float s = 0.f;
#pragma unroll
    for (int dy = -1; dy <= 1; dy++)
#pragma unroll
        for (int dx = -1; dx <= 1; dx++) {
            int i = li + dy, j = lj + dx;
            if ((unsigned)i < 64u && (unsigned)j < 64u) s += g_pix2[i * 64 + j];
        }
    g_invnorm[l] = 1.0f / fmaxf(sqrtf(s), 1e-4f);
}

__global__ void compact_kernel(int b) {
    __shared__ int cnt1[256], off1[256];
    int t = threadIdx.x;
    int c1 = 0;
    for (int i = 0; i < 16; i++)
        if (g_mm[t * 16 + i] > 0.5f) c1++;
    cnt1[t] = c1;
    __syncthreads();
    if (t == 0) {
        int s1 = 0;
        for (int i = 0; i < 256; i++) { off1[i] = s1; s1 += cnt1[i]; }
        g_cnt[b][0] = s1; g_cnt[b][1] = L - s1;
    }
    __syncthreads();
    int o1 = off1[t];
    for (int i = 0; i < 16; i++) {
        int l = t * 16 + i;
        if (g_mm[l] > 0.5f) g_idx1[b][o1++] = l;
    }
}

// ---------------------------------------------------------------------------
// FFMA2 dense NT GEMM (Corr = X^T X, K=64)
__global__ void __launch_bounds__(256, 2) corr_gemm(
        const float* __restrict__ Bmat, const float* __restrict__ Amat,
        float* __restrict__ Out) {
    __shared__ __align__(16) float sBd[2][8][256];
    __shared__ __align__(16) float sA[2][8][128];
    int t = threadIdx.x;
    int m0 = blockIdx.x * 128, p0 = blockIdx.y * 128;
    const int nK = 8;
    int lr = t >> 5, lc = (t & 31) * 4;
    const float* Bp = Bmat + (size_t)lr * L + m0 + lc;
    const float* Ap = Amat + (size_t)lr * L + p0 + lc;
    float4 rb = *(const float4*)Bp;
    float4 ra = *(const float4*)Ap;
    *(float4*)&sBd[0][lr][2 * lc]     = make_float4(rb.x, rb.x, rb.y, rb.y);
    *(float4*)&sBd[0][lr][2 * lc + 4] = make_float4(rb.z, rb.z, rb.w, rb.w);
    *(float4*)&sA[0][lr][lc] = ra;
    __syncthreads();
    int tx = t & 15, ty = t >> 4;
    ull acc2[8][4] = {};
    for (int kt = 0; kt < nK; kt++) {
        int cur = kt & 1, nxt = cur ^ 1;
        if (kt + 1 < nK) {
            rb = *(const float4*)(Bp + (size_t)(kt + 1) * 8 * L);
            ra = *(const float4*)(Ap + (size_t)(kt + 1) * 8 * L);
        }
#pragma unroll
        for (int kk = 0; kk < 8; kk++) {
            ull bb[4];
            ulonglong2 b01 = *(const ulonglong2*)&sA[cur][kk][tx * 8];
            ulonglong2 b23 = *(const ulonglong2*)&sA[cur][kk][tx * 8 + 4];
            bb[0] = b01.x; bb[1] = b01.y; bb[2] = b23.x; bb[3] = b23.y;
#pragma unroll
            for (int i = 0; i < 8; i++) {
                ull ad = *(const ull*)&sBd[cur][kk][(ty * 8 + i) * 2];
#pragma unroll
                for (int j = 0; j < 4; j++)
                    acc2[i][j] = ffma2(ad, bb[j], acc2[i][j]);
            }
        }
        if (kt + 1 < nK) {
            *(float4*)&sBd[nxt][lr][2 * lc]     = make_float4(rb.x, rb.x, rb.y, rb.y);
            *(float4*)&sBd[nxt][lr][2 * lc + 4] = make_float4(rb.z, rb.z, rb.w, rb.w);
            *(float4*)&sA[nxt][lr][lc] = ra;
        }
        __syncthreads();
    }
#pragma unroll
    for (int i = 0; i < 8; i++) {
        int m = m0 + ty * 8 + i;
        float r[8];
#pragma unroll
        for (int j = 0; j < 4; j++) {
            union { ull u; float2 f; } cv; cv.u = acc2[i][j];
            r[2 * j] = cv.f.x; r[2 * j + 1] = cv.f.y;
        }
        *(float4*)&Out[(size_t)m * L + p0 + tx * 8]     = make_float4(r[0], r[1], r[2], r[3]);
        *(float4*)&Out[(size_t)m * L + p0 + tx * 8 + 4] = make_float4(r[4], r[5], r[6], r[7]);
    }
}

// ---------------------------------------------------------------------------
// Rch[b][m][k] = fp16 of im2col(x1)[idx1[k]][m], zero-pad k in [n1, n1p)
__global__ void build_Rc(const float* __restrict__ x1b, int b) {
    int k = blockIdx.x * 256 + threadIdx.x;
    int m = blockIdx.y;
    int n1 = g_cnt[b][0];
    int n1p = (n1 + 31) & ~31;
    if (k >= n1p) return;
    float val = 0.f;
    if (k < n1) {
        int l = g_idx1[b][k];
        int li = l >> 6, lj = l & 63;
        int c = m >> 4, ky = (m >> 2) & 3, kx = m & 3;
        int u = 2 * li - 1 + ky, v = 2 * lj - 1 + kx;
        if ((unsigned)u < 128u && (unsigned)v < 128u) val = x1b[c * 16384 + u * 128 + v];
    }
    g_Rch[b][(size_t)m * KS + k] = __float2half(val);
}

// cmT[m] = 1e-8 * sum over ALL 4096 patches of R[l,m]
__global__ void cmT_kernel(const float* __restrict__ x1b, int b) {
    int m = blockIdx.x * 256 + threadIdx.x;
    int c = m >> 4, ky = (m >> 2) & 3, kx = m & 3;
    const float* xc = x1b + c * (H1 * W1);
    float s = 0.f;
#pragma unroll 4
    for (int l = 0; l < L; l++) {
        int li = l >> 6, lj = l & 63;
        int u = 2 * li - 1 + ky, v = 2 * lj - 1 + kx;
        if ((unsigned)u < 128u && (unsigned)v < 128u)
            s += xc[u * W1 + v];
    }
    g_cmT[b][m] = 1e-8f * s;
}

// scores for active rows only, written dense: Ac[k][p]
__global__ void scores_kernel(const float* __restrict__ mab, int b) {
    int k = blockIdx.y;
    if (k >= g_cnt[b][0]) return;
    int l = g_idx1[b][k];
    int p = blockIdx.x * 256 + threadIdx.x;
    int li = l >> 6, lj = l & 63, pi = p >> 6, pj = p & 63;
    float s = 0.f;
#pragma unroll
    for (int dy = -1; dy <= 1; dy++)
#pragma unroll
        for (int dx = -1; dx <= 1; dx++) {
            if ((unsigned)(li + dy) < 64u && (unsigned)(lj + dx) < 64u &&
                (unsigned)(pi + dy) < 64u && (unsigned)(pj + dx) < 64u) {
                int o = dy * 64 + dx;
                s += g_corr[(l + o) * L + (p + o)];
            }
        }
    g_Ac[(size_t)k * L + p] = s * g_invnorm[l] * mab[p];
}

// column softmax over all 4096 rows (masked rows = closed form), floor applied
__global__ void softmax_kernel(const float* __restrict__ mab, int b) {
    __shared__ float red[8][32];
    int t = threadIdx.x;
    int col = t & 31, part = t >> 5;
    int p = blockIdx.x * 32 + col;
    int n1 = g_cnt[b][0], n0 = g_cnt[b][1];

    float mx = 0.f;
    for (int k = part; k < n1; k += 8) mx = fmaxf(mx, g_Ac[(size_t)k * L + p]);
    red[part][col] = mx;
    __syncthreads();
    if (t < 32) {
        float m = red[0][t];
        for (int q = 1; q < 8; q++) m = fmaxf(m, red[q][t]);
        red[0][t] = m;
    }
    __syncthreads();
    mx = red[0][col];
    __syncthreads();

    float sm = 0.f;
    for (int k = part; k < n1; k += 8) {
        size_t o = (size_t)k * L + p;
        float e = __expf(SCALE_F * (g_Ac[o] - mx));
        g_Ac[o] = e;
        sm += e;
    }
    red[part][col] = sm;
    __syncthreads();
    if (t < 32) {
        float s2 = 0.f;
        for (int q = 0; q < 8; q++) s2 += red[q][t];
        s2 += (float)n0 * __expf(-SCALE_F * mx);
        red[0][t] = s2;
    }
    __syncthreads();
    float inv_s = 1.0f / red[0][col];
    float mav = mab[p];
    for (int k = part; k < n1; k += 8) {
        size_t o = (size_t)k * L + p;
        g_Ac[o] = fmaxf(g_Ac[o] * inv_s * mav, 1e-8f);
    }
}

// transpose + fp16 with exact floor-shift and scale:
// AcTh[b][p][k] = fp16((Ac[k][p] - 1e-8) * 1024); zero-pad k in [n1, n1p)
__global__ void __launch_bounds__(256) transpose_h(int b) {
    __shared__ float s[32][33];
    int n1 = g_cnt[b][0];
    int n1p = (n1 + 31) & ~31;
    int k0 = blockIdx.x * 32, p0 = blockIdx.y * 32;
    if (k0 >= n1p) return;
    int t = threadIdx.x;
    int pp = t & 31, kk = t >> 5;
#pragma unroll
    for (int i = 0; i < 4; i++) {
        int k = k0 + kk + i * 8;
        s[kk + i * 8][pp] = (k < n1) ? g_Ac[(size_t)k * L + p0 + pp] : 1e-8f;
    }
    __syncthreads();
    int kx = t & 31, py = t >> 5;
#pragma unroll
    for (int i = 0; i < 4; i++) {
        int p = p0 + py + i * 8;
        float v = (s[kx][py + i * 8] - 1e-8f) * ASCALE;
        g_AcTh[b][(size_t)p * KS + k0 + kx] = __float2half(v);
    }
}

// ---------------------------------------------------------------------------
// HMMA fp16 paste GEMM (batched over z): Z[b][m][p] = (1/1024)*sum_k A'[m,k]*B[p,k] + cmT[m]
// CTA tile 128(m) x 256(p), BK=32, 8 warps of 64x64, 3-stage cp.async.
#define GSTAGES 3
#define ABYTES (128 * 64)          // 128 rows x 32 fp16
#define BBYTES (256 * 64)
#define STAGE_B (ABYTES + BBYTES)  // 24576
#define SMEM_GEMM (GSTAGES * STAGE_B)

__device__ __forceinline__ void cp_async16(uint32_t dst, const void* src) {
    asm volatile("cp.async.cg.shared.global [%0], [%1], 16;" :: "r"(dst), "l"(src) : "memory");
}
__device__ __forceinline__ void ldsm4(uint32_t& r0, uint32_t& r1, uint32_t& r2, uint32_t& r3,
                                      uint32_t a) {
    asm volatile("ldmatrix.sync.aligned.m8n8.x4.shared.b16 {%0,%1,%2,%3}, [%4];"
                 : "=r"(r0), "=r"(r1), "=r"(r2), "=r"(r3) : "r"(a));
}
__device__ __forceinline__ void mma16816(float* c, const uint32_t* a, uint32_t b0, uint32_t b1) {
    asm volatile(
        "mma.sync.aligned.m16n8k16.row.col.f32.f16.f16.f32 "
        "{%0,%1,%2,%3}, {%4,%5,%6,%7}, {%8,%9}, {%0,%1,%2,%3};"
        : "+f"(c[0]), "+f"(c[1]), "+f"(c[2]), "+f"(c[3])
        : "r"(a[0]), "r"(a[1]), "r"(a[2]), "r"(a[3]), "r"(b0), "r"(b1));
}

__global__ void __launch_bounds__(256, 1) paste_hmma() {
    extern __shared__ __align__(16) char smem[];
    uint32_t sb = smem_u32(smem);
    int t = threadIdx.x;
    int lane = t & 31;
    int wr = (t >> 5) & 1;        // warp m-row (0..1)
    int wc = t >> 6;              // warp p-col (0..3)
    int m0 = blockIdx.x * 128;
    int p0 = blockIdx.y * 256;
    int z = blockIdx.z;
    int n1 = g_cnt[z][0];
    int n1p = (n1 + 31) & ~31;
    int nC = n1p >> 5;

    const __half* Abase = g_Rch[z] + (size_t)m0 * KS;
    const __half* Bbase = g_AcTh[z] + (size_t)p0 * KS;

    auto load_chunk = [&](int kt, int s) {
        uint32_t stage = sb + s * STAGE_B;
        int k0 = kt * 32;
#pragma unroll
        for (int i = 0; i < 2; i++) {
            int e = t + i * 256;              // A: 512 chunks
            int row = e >> 2, c = e & 3;
            uint32_t dst = stage + row * 64 + ((c ^ (row & 3)) << 4);
            cp_async16(dst, Abase + (size_t)row * KS + k0 + c * 8);
        }
#pragma unroll
        for (int i = 0; i < 4; i++) {
            int e = t + i * 256;              // B: 1024 chunks
            int row = e >> 2, c = e & 3;
            uint32_t dst = stage + ABYTES + row * 64 + ((c ^ (row & 3)) << 4);
            cp_async16(dst, Bbase + (size_t)row * KS + k0 + c * 8);
        }
        asm volatile("cp.async.commit_group;" ::: "memory");
    };

#pragma unroll
    for (int s = 0; s < GSTAGES - 1; s++) {
        if (s < nC) load_chunk(s, s);
        else asm volatile("cp.async.commit_group;" ::: "memory");
    }

    float acc[4][8][4] = {};
    int r8 = lane & 7;
    int mat = lane >> 3;
    int rowSwz = r8 & 3;
    int rA = wr * 64 + r8 + (mat & 1) * 8;
    int rB = wc * 64 + r8 + (mat & 1) * 8;
    int chi = mat >> 1;

    for (int kt = 0; kt < nC; kt++) {
        asm volatile("cp.async.wait_group %0;" :: "n"(GSTAGES - 2) : "memory");
        __syncthreads();
        uint32_t stage = sb + (kt % GSTAGES) * STAGE_B;

        if (kt + GSTAGES - 1 < nC) load_chunk(kt + GSTAGES - 1, (kt + GSTAGES - 1) % GSTAGES);
        else asm volatile("cp.async.commit_group;" ::: "memory");

#pragma unroll
        for (int ks = 0; ks < 2; ks++) {
            int kc = ks * 2 + chi;
            uint32_t a[4][4];
            uint32_t b[4][4];
#pragma unroll
            for (int mi = 0; mi < 4; mi++) {
                int row = rA + mi * 16;
                ldsm4(a[mi][0], a[mi][1], a[mi][2], a[mi][3],
                      stage + row * 64 + ((kc ^ rowSwz) << 4));
            }
#pragma unroll
            for (int nj = 0; nj < 4; nj++) {
                int row = rB + nj * 16;
                ldsm4(b[nj][0], b[nj][1], b[nj][2], b[nj][3],
                      stage + ABYTES + row * 64 + ((kc ^ rowSwz) << 4));
            }
#pragma unroll
            for (int mi = 0; mi < 4; mi++)
#pragma unroll
                for (int nj = 0; nj < 4; nj++) {
                    mma16816(acc[mi][nj * 2],     a[mi], b[nj][0], b[nj][2]);
                    mma16816(acc[mi][nj * 2 + 1], a[mi], b[nj][1], b[nj][3]);
                }
        }
        __syncthreads();
    }

    // epilogue: unscale, add cmT, store Z
    const float inv = 1.0f / ASCALE;
    int cr = lane >> 2, cc = (lane & 3) * 2;
#pragma unroll
    for (int mi = 0; mi < 4; mi++) {
        int mbase = m0 + wr * 64 + mi * 16;
        float c0a = g_cmT[z][mbase + cr];
        float c0b = g_cmT[z][mbase + cr + 8];
#pragma unroll
        for (int ni = 0; ni < 8; ni++) {
            int p = p0 + wc * 64 + ni * 8 + cc;
            float* z0 = &g_Z[z][(size_t)(mbase + cr) * L + p];
            float* z1 = &g_Z[z][(size_t)(mbase + cr + 8) * L + p];
            *(float2*)z0 = make_float2(acc[mi][ni][0] * inv + c0a, acc[mi][ni][1] * inv + c0a);
            *(float2*)z1 = make_float2(acc[mi][ni][2] * inv + c0b, acc[mi][ni][3] * inv + c0b);
        }
    }
}

// ---------------------------------------------------------------------------
// overlap-add: y[b,c,u,v] = 0.25 * sum over <=4 covering patches of Z
__global__ void scatter_kernel() {
    int idx = blockIdx.x * 256 + threadIdx.x;
    int b = blockIdx.y;
    int v = idx & 127, u = (idx >> 7) & 127, c = idx >> 14;
    float s = 0.f;
    int ky0 = (u + 1) & 1, kx0 = (v + 1) & 1;
#pragma unroll
    for (int a = 0; a < 2; a++) {
        int ky = ky0 + 2 * a;
        int i2 = u + 1 - ky;
        if (i2 < 0 || i2 > 126) continue;
        int pi = i2 >> 1;
#pragma unroll
        for (int q = 0; q < 2; q++) {
            int kx = kx0 + 2 * q;
            int j2 = v + 1 - kx;
            if (j2 < 0 || j2 > 126) continue;
            int pj = j2 >> 1;
            int m = c * 16 + ky * 4 + kx;
            s += g_Z[b][(size_t)m * L + pi * 64 + pj];
        }
    }
    g_y[b * (C1 * H1 * W1) + idx] = 0.25f * s;
}

// final 4-group dilated 3x3 convs (rates 1,2,4,8) + bias + relu, FFMA2 over oc-pairs
__global__ void __launch_bounds__(256) final_conv(const float* __restrict__ w,
                                                  const float* __restrict__ bias,
                                                  float* __restrict__ out) {
    __shared__ __align__(16) float sy[32 * 32];
    __shared__ __align__(16) float swp[9 * 16];   // [tap][ocpair][2]
    int t = threadIdx.x;
    int tv = t & 15, tu = t >> 4;
    int tile = blockIdx.x;
    int u0 = (tile >> 3) * 16, v0 = (tile & 7) * 16;
    int bg = blockIdx.y;
    int b = bg >> 2, g = bg & 3;
    int r = 1 << g;
    int Wt = 16 + 2 * r;
    const float* yb = g_y + b * (C1 * H1 * W1);
    ull acc2[8] = {};
    for (int c = 0; c < C1; c++) {
        const float* yc = yb + c * (H1 * W1);
        for (int e = t; e < Wt * Wt; e += 256) {
            int lu = e / Wt, lv = e % Wt;
            int gu = u0 - r + lu, gv = v0 - r + lv;
            float val = 0.f;
            if ((unsigned)gu < 128u && (unsigned)gv < 128u) val = yc[gu * 128 + gv];
            sy[lu * Wt + lv] = val;
        }
        if (t < 144) {
            int oc = t / 9, tap = t % 9;
            swp[tap * 16 + (oc >> 1) * 2 + (oc & 1)] =
                w[((g * 16 + oc) * C1 + c) * 9 + tap];
        }
        __syncthreads();
#pragma unroll
        for (int kh = 0; kh < 3; kh++)
#pragma unroll
            for (int kw = 0; kw < 3; kw++) {
                int tap = kh * 3 + kw;
                ull vv = packf2(sy[(tu + kh * r) * Wt + (tv + kw * r)]);
                const ull* wp = (const ull*)&swp[tap * 16];
#pragma unroll
                for (int pr = 0; pr < 8; pr++)
                    acc2[pr] = ffma2(vv, wp[pr], acc2[pr]);
            }
        __syncthreads();
    }
    int u = u0 + tu, v = v0 + tv;
#pragma unroll
    for (int pr = 0; pr < 8; pr++) {
        union { ull u64; float2 f; } cv; cv.u64 = acc2[pr];
        int oc0 = pr * 2;
        float o0 = fmaxf(cv.f.x + bias[g * 16 + oc0], 0.f);
        float o1 = fmaxf(cv.f.y + bias[g * 16 + oc0 + 1], 0.f);
        out[((b * 64 + g * 16 + oc0) * 128 + u) * 128 + v] = o0;
        out[((b * 64 + g * 16 + oc0 + 1) * 128 + u) * 128 + v] = o1;
    }
}

// ---------------------------------------------------------------------------
extern "C" void kernel_launch(void* const* d_in, const int* in_sizes, int n_in,
                              void* d_out, int out_size) {
    (void)in_sizes; (void)n_in; (void)out_size;
    const float* x1       = (const float*)d_in[0];
    const float* x2       = (const float*)d_in[1];
    const float* mask     = (const float*)d_in[2];
    const float* mask_all = (const float*)d_in[3];
    const float* conv_w   = (const float*)d_in[4];
    const float* conv_b   = (const float*)d_in[5];
    float* out = (float*)d_out;

    cudaFuncSetAttribute(paste_hmma, cudaFuncAttributeMaxDynamicSharedMemorySize, SMEM_GEMM);

    float* d_corr; cudaGetSymbolAddress((void**)&d_corr, g_corr);

    for (int b = 0; b < Bn; b++) {
        const float* x1b   = x1 + (size_t)b * C1 * H1 * W1;
        const float* x2b   = x2 + (size_t)b * C2 * 64 * 64;
        const float* maskb = mask + (size_t)b * H1 * W1;
        const float* mab   = mask_all + (size_t)b * L;

        prep_kernel<<<16, 256>>>(x2b, maskb);
        invnorm_kernel<<<16, 256>>>();
        compact_kernel<<<1, 256>>>(b);
        corr_gemm<<<dim3(32, 32), 256>>>(x2b, x2b, d_corr);
        build_Rc<<<dim3(16, 2048), 256>>>(x1b, b);
        cmT_kernel<<<8, 256>>>(x1b, b);
        scores_kernel<<<dim3(16, L), 256>>>(mab, b);
        softmax_kernel<<<128, 256>>>(mab, b);
        transpose_h<<<dim3(128, 128), 256>>>(b);
    }
    paste_hmma<<<dim3(16, 16, Bn), 256, SMEM_GEMM>>>();
    scatter_kernel<<<dim3(8192, Bn), 256>>>();
    final_conv<<<dim3(64, 16), 256>>>(conv_w, conv_b, out);
}

// round 8
// speedup vs baseline: 4.1643x; 1.6072x over previous
#include <cuda_runtime.h>
#include <cuda_fp16.h>
#include <math.h>
#include <stdint.h>

#define Bn 4
#define C1 128
#define H1 128
#define W1 128
#define C2 64
#define L 4096      // H2*W2 patches / pixels
#define M2 2048     // C1*4*4 patch elements
#define KS 4096     // K stride for paste fp16 operands
#define KX 192      // K stride for corr fp16 triple operands (3*64)
#define SCALE_F 10.0f
#define ASCALE 1024.0f

typedef unsigned long long ull;

// ---- static device scratch, pooled & aliased (allocation-free rule) ----
// poolA: [phase 1] corr[Bn] fp32 (4 x 64MB)
//        [phase 2] Z[Bn] fp32 (4 x 32MB @ 0) + AcTh[Bn] fp16 (4 x 32MB @ 128MB)
// poolB: [phase 1] Ac[Bn] fp32 (4 x 64MB)
//        [phase 2] Rch[Bn] fp16 (4 x 16MB @ 0)
__device__ __align__(1024) unsigned char g_poolA[268435456];
__device__ __align__(1024) unsigned char g_poolB[268435456];
__device__ __half g_X3a[Bn][(size_t)L * KX];       // 6.3 MB corr A triples (h,h,l)
__device__ __half g_X3b[Bn][(size_t)L * KX];       // 6.3 MB corr B triples (h,l,h)
__device__ float g_y[Bn * C1 * H1 * W1];           // 33.5 MB pasted images
__device__ float g_pix2[Bn][L];
__device__ float g_invnorm[Bn][L];
__device__ float g_mm[Bn][L];
__device__ float g_colsc[Bn][L];                   // per-column inv_sum * mask_all
__device__ int   g_idx1[Bn][L];
__device__ int   g_cnt[Bn][2];
__device__ float g_cmT[Bn][M2];

__device__ __forceinline__ ull ffma2(ull a, ull b, ull c) {
    asm("fma.rn.f32x2 %0, %1, %2, %0;" : "+l"(c) : "l"(a), "l"(b));
    return c;
}
__device__ __forceinline__ ull packf2(float v) {
    ull r;
    uint32_t u = __float_as_uint(v);
    asm("mov.b64 %0, {%1, %1};" : "=l"(r) : "r"(u));
    return r;
}
__device__ __forceinline__ uint32_t smem_u32(const void* p) {
    uint32_t a;
    asm("{ .reg .u64 t; cvta.to.shared.u64 t, %1; cvt.u32.u64 %0, t; }" : "=r"(a) : "l"(p));
    return a;
}

// ---------------------------------------------------------------------------
// fused: pix2 + mm, batched over blockIdx.y
__global__ void prep_kernel(const float* __restrict__ x2, const float* __restrict__ mask) {
    int b = blockIdx.y;
    int a = blockIdx.x * 256 + threadIdx.x;
    const float* x2b = x2 + (size_t)b * C2 * L;
    const float* maskb = mask + (size_t)b * H1 * W1;
    float s = 0.f;
#pragma unroll 16
    for (int c = 0; c < C2; c++) { float v = x2b[c * L + a]; s += v * v; }
    g_pix2[b][a] = s;

    int li = a >> 6, lj = a & 63;
    bool allzero = true;
#pragma unroll
    for (int ky = 0; ky < 4; ky++)
#pragma unroll
        for (int kx = 0; kx < 4; kx++) {
            int u = 2 * li - 1 + ky, v = 2 * lj - 1 + kx;
            if ((unsigned)u < (unsigned)H1 && (unsigned)v < (unsigned)W1) {
                if (maskb[u * W1 + v] != 0.f) allzero = false;
            }
        }
    g_mm[b][a] = allzero ? 1.f : 0.f;
}

__global__ void invnorm_kernel() {
    int b = blockIdx.y;
    int l = blockIdx.x * 256 + threadIdx.x;
    int li = l >> 6, lj = l & 63;
    float s = 0.f;
#pragma unroll
    for (int dy = -1; dy <= 1; dy++)
#pragma unroll
        for (int dx = -1; dx <= 1; dx++) {
            int i = li + dy, j = lj + dx;
            if ((unsigned)i < 64u && (unsigned)j < 64u) s += g_pix2[b][i * 64 + j];
        }
    g_invnorm[b][l] = 1.0f / fmaxf(sqrtf(s), 1e-4f);
}

__global__ void compact_kernel() {
    __shared__ int cnt1[256], off1[256];
    int b = blockIdx.x;
    int t = threadIdx.x;
    int c1 = 0;
    for (int i = 0; i < 16; i++)
        if (g_mm[b][t * 16 + i] > 0.5f) c1++;
    cnt1[t] = c1;
    __syncthreads();
    if (t == 0) {
        int s1 = 0;
        for (int i = 0; i < 256; i++) { off1[i] = s1; s1 += cnt1[i]; }
        g_cnt[b][0] = s1; g_cnt[b][1] = L - s1;
    }
    __syncthreads();
    int o1 = off1[t];
    for (int i = 0; i < 16; i++) {
        int l = t * 16 + i;
        if (g_mm[b][l] > 0.5f) g_idx1[b][o1++] = l;
    }
}

// ---------------------------------------------------------------------------
// corr operand build: per pixel m, per channel c:
// X3a[m][3c..] = (h,h,l), X3b[m][3c..] = (h,l,h)
__global__ void build_X3(const float* __restrict__ x2) {
    int b = blockIdx.y;
    int m = blockIdx.x * 256 + threadIdx.x;
    const float* x2b = x2 + (size_t)b * C2 * L;
    union { __half h[24]; uint4 v[3]; } ua, ub;
#pragma unroll
    for (int cc = 0; cc < 8; cc++) {
#pragma unroll
        for (int j = 0; j < 8; j++) {
            float val = x2b[(cc * 8 + j) * L + m];
            __half h = __float2half(val);
            __half lo = __float2half(val - __half2float(h));
            ua.h[j * 3] = h;  ua.h[j * 3 + 1] = h;  ua.h[j * 3 + 2] = lo;
            ub.h[j * 3] = h;  ub.h[j * 3 + 1] = lo; ub.h[j * 3 + 2] = h;
        }
        size_t off = (size_t)m * KX + cc * 24;
        uint4* pa = (uint4*)&g_X3a[b][off];
        uint4* pb = (uint4*)&g_X3b[b][off];
#pragma unroll
        for (int q = 0; q < 3; q++) { pa[q] = ua.v[q]; pb[q] = ub.v[q]; }
    }
}

// Rch[b][m][k] = fp16 of im2col(x1)[idx1[k]][m], zero-pad k in [n1, n1p)
__global__ void build_Rc(const float* __restrict__ x1, __half* __restrict__ RchAll) {
    int b = blockIdx.z;
    int k = blockIdx.x * 256 + threadIdx.x;
    int m = blockIdx.y;
    int n1 = g_cnt[b][0];
    int n1p = (n1 + 31) & ~31;
    if (k >= n1p) return;
    float val = 0.f;
    if (k < n1) {
        int l = g_idx1[b][k];
        int li = l >> 6, lj = l & 63;
        int c = m >> 4, ky = (m >> 2) & 3, kx = m & 3;
        int u = 2 * li - 1 + ky, v = 2 * lj - 1 + kx;
        if ((unsigned)u < 128u && (unsigned)v < 128u)
            val = x1[((size_t)b * C1 + c) * 16384 + u * 128 + v];
    }
    RchAll[(size_t)b * M2 * KS + (size_t)m * KS + k] = __float2half(val);
}

// cmT[m] = 1e-8 * sum over ALL 4096 patches of R[l,m]  (block tree-reduce)
__global__ void cmT_kernel(const float* __restrict__ x1) {
    __shared__ float red[256];
    int m = blockIdx.x, b = blockIdx.y;
    int t = threadIdx.x;
    int c = m >> 4, ky = (m >> 2) & 3, kx = m & 3;
    const float* xc = x1 + ((size_t)b * C1 + c) * (H1 * W1);
    float s = 0.f;
    for (int l = t; l < L; l += 256) {
        int li = l >> 6, lj = l & 63;
        int u = 2 * li - 1 + ky, v = 2 * lj - 1 + kx;
        if ((unsigned)u < 128u && (unsigned)v < 128u) s += xc[u * W1 + v];
    }
    red[t] = s;
    __syncthreads();
    for (int st = 128; st > 0; st >>= 1) {
        if (t < st) red[t] += red[t + st];
        __syncthreads();
    }
    if (t == 0) g_cmT[b][m] = 1e-8f * red[0];
}

// scores for active rows only, written dense: Ac[b][k][p]
__global__ void scores_kernel(const float* __restrict__ corrAll,
                              float* __restrict__ AcAll,
                              const float* __restrict__ mask_all) {
    int b = blockIdx.z;
    int k = blockIdx.y;
    if (k >= g_cnt[b][0]) return;
    int l = g_idx1[b][k];
    int p = blockIdx.x * 256 + threadIdx.x;
    int li = l >> 6, lj = l & 63, pi = p >> 6, pj = p & 63;
    const float* corr = corrAll + (size_t)b * L * L;
    float s = 0.f;
#pragma unroll
    for (int dy = -1; dy <= 1; dy++)
#pragma unroll
        for (int dx = -1; dx <= 1; dx++) {
            if ((unsigned)(li + dy) < 64u && (unsigned)(lj + dx) < 64u &&
                (unsigned)(pi + dy) < 64u && (unsigned)(pj + dx) < 64u) {
                int o = dy * 64 + dx;
                s += corr[(size_t)(l + o) * L + (p + o)];
            }
        }
    AcAll[(size_t)b * L * L + (size_t)k * L + p] =
        s * g_invnorm[b][l] * mask_all[(size_t)b * L + p];
}

// column softmax passes 1+2: max, then exp (stored) + sum; colsc = inv_sum*mav
__global__ void softmax_kernel(float* __restrict__ AcAll,
                               const float* __restrict__ mask_all) {
    __shared__ float red[8][32];
    int b = blockIdx.y;
    int t = threadIdx.x;
    int col = t & 31, part = t >> 5;
    int p = blockIdx.x * 32 + col;
    int n1 = g_cnt[b][0], n0 = g_cnt[b][1];
    float* Ac = AcAll + (size_t)b * L * L;

    float mx = 0.f;
    for (int k = part; k < n1; k += 8) mx = fmaxf(mx, Ac[(size_t)k * L + p]);
    red[part][col] = mx;
    __syncthreads();
    if (t < 32) {
        float m = red[0][t];
        for (int q = 1; q < 8; q++) m = fmaxf(m, red[q][t]);
        red[0][t] = m;
    }
    __syncthreads();
    mx = red[0][col];
    __syncthreads();

    float sm = 0.f;
    for (int k = part; k < n1; k += 8) {
        size_t o = (size_t)k * L + p;
        float e = __expf(SCALE_F * (Ac[o] - mx));
        Ac[o] = e;
        sm += e;
    }
    red[part][col] = sm;
    __syncthreads();
    if (t < 32) {
        float s2 = 0.f;
        for (int q = 0; q < 8; q++) s2 += red[q][t];
        s2 += (float)n0 * __expf(-SCALE_F * mx);
        red[0][t] = s2;
    }
    __syncthreads();
    if (part == 0)
        g_colsc[b][p] = (1.0f / red[0][col]) * mask_all[(size_t)b * L + p];
}

// transpose + scale + floor-shift + fp16:
// AcTh[b][p][k] = fp16((max(e*sc, 1e-8) - 1e-8) * 1024); zero-pad [n1, n1p)
__global__ void __launch_bounds__(256) transpose_h(const float* __restrict__ AcAll,
                                                   __half* __restrict__ AcThAll) {
    __shared__ float s[32][33];
    int b = blockIdx.z;
    int n1 = g_cnt[b][0];
    int n1p = (n1 + 31) & ~31;
    int k0 = blockIdx.x * 32, p0 = blockIdx.y * 32;
    if (k0 >= n1p) return;
    const float* Ac = AcAll + (size_t)b * L * L;
    int t = threadIdx.x;
    int pp = t & 31, kk = t >> 5;
#pragma unroll
    for (int i = 0; i < 4; i++) {
        int k = k0 + kk + i * 8;
        s[kk + i * 8][pp] = (k < n1) ? Ac[(size_t)k * L + p0 + pp] : 0.f;
    }
    __syncthreads();
    int kx = t & 31, py = t >> 5;
#pragma unroll
    for (int i = 0; i < 4; i++) {
        int p = p0 + py + i * 8;
        float sc = g_colsc[b][p];
        float e = s[kx][py + i * 8];
        float a = (e > 0.f) ? fmaxf(e * sc, 1e-8f) : 0.f;  // pad rows stay 0
        float v = (a > 0.f) ? (a - 1e-8f) * ASCALE : 0.f;
        AcThAll[(size_t)b * L * KS + (size_t)p * KS + k0 + kx] = __float2half(v);
    }
}

// ---------------------------------------------------------------------------
// generic HMMA fp16 NT GEMM, batched over z.
// PASTE:  Out[z][m][p] = (1/1024)*sum_k A[m,k]*B[p,k] + cmT[z][m], nC from g_cnt
// !PASTE: Out[z][m][p] = sum_k A[m,k]*B[p,k], nC fixed
#define GSTAGES 3
#define ABYTES (128 * 64)          // 128 rows x 32 fp16
#define BBYTES (256 * 64)
#define STAGE_B (ABYTES + BBYTES)  // 24576
#define SMEM_GEMM (GSTAGES * STAGE_B)

__device__ __forceinline__ void cp_async16(uint32_t dst, const void* src) {
    asm volatile("cp.async.cg.shared.global [%0], [%1], 16;" :: "r"(dst), "l"(src) : "memory");
}
__device__ __forceinline__ void ldsm4(uint32_t& r0, uint32_t& r1, uint32_t& r2, uint32_t& r3,
                                      uint32_t a) {
    asm volatile("ldmatrix.sync.aligned.m8n8.x4.shared.b16 {%0,%1,%2,%3}, [%4];"
                 : "=r"(r0), "=r"(r1), "=r"(r2), "=r"(r3) : "r"(a));
}
__device__ __forceinline__ void mma16816(float* c, const uint32_t* a, uint32_t b0, uint32_t b1) {
    asm volatile(
        "mma.sync.aligned.m16n8k16.row.col.f32.f16.f16.f32 "
        "{%0,%1,%2,%3}, {%4,%5,%6,%7}, {%8,%9}, {%0,%1,%2,%3};"
        : "+f"(c[0]), "+f"(c[1]), "+f"(c[2]), "+f"(c[3])
        : "r"(a[0]), "r"(a[1]), "r"(a[2]), "r"(a[3]), "r"(b0), "r"(b1));
}

template<int KSTRIDE, bool PASTE>
__global__ void __launch_bounds__(256, 1) hmma_gemm(
        const __half* __restrict__ Aall, const __half* __restrict__ Ball,
        float* __restrict__ Outall,
        size_t aStride, size_t bStride, size_t oStride, int nCfix) {
    extern __shared__ __align__(16) char smem[];
    uint32_t sb = smem_u32(smem);
    int t = threadIdx.x;
    int lane = t & 31;
    int wr = (t >> 5) & 1;
    int wc = t >> 6;
    int m0 = blockIdx.x * 128;
    int p0 = blockIdx.y * 256;
    int z = blockIdx.z;
    int nC = PASTE ? (((g_cnt[z][0] + 31) & ~31) >> 5) : nCfix;

    const __half* Abase = Aall + z * aStride + (size_t)m0 * KSTRIDE;
    const __half* Bbase = Ball + z * bStride + (size_t)p0 * KSTRIDE;
    float* Out = Outall + z * oStride;

    auto load_chunk = [&](int kt, int s) {
        uint32_t stage = sb + s * STAGE_B;
        int k0 = kt * 32;
#pragma unroll
        for (int i = 0; i < 2; i++) {
            int e = t + i * 256;
            int row = e >> 2, c = e & 3;
            uint32_t dst = stage + row * 64 + ((c ^ (row & 3)) << 4);
            cp_async16(dst, Abase + (size_t)row * KSTRIDE + k0 + c * 8);
        }
#pragma unroll
        for (int i = 0; i < 4; i++) {
            int e = t + i * 256;
            int row = e >> 2, c = e & 3;
            uint32_t dst = stage + ABYTES + row * 64 + ((c ^ (row & 3)) << 4);
            cp_async16(dst, Bbase + (size_t)row * KSTRIDE + k0 + c * 8);
        }
        asm volatile("cp.async.commit_group;" ::: "memory");
    };

#pragma unroll
    for (int s = 0; s < GSTAGES - 1; s++) {
        if (s < nC) load_chunk(s, s);
        else asm volatile("cp.async.commit_group;" ::: "memory");
    }

    float acc[4][8][4] = {};
    int r8 = lane & 7;
    int mat = lane >> 3;
    int rowSwz = r8 & 3;
    int rA = wr * 64 + r8 + (mat & 1) * 8;
    int rB = wc * 64 + r8 + (mat & 1) * 8;
    int chi = mat >> 1;

    for (int kt = 0; kt < nC; kt++) {
        asm volatile("cp.async.wait_group %0;" :: "n"(GSTAGES - 2) : "memory");
        __syncthreads();
        uint32_t stage = sb + (kt % GSTAGES) * STAGE_B;

        if (kt + GSTAGES - 1 < nC) load_chunk(kt + GSTAGES - 1, (kt + GSTAGES - 1) % GSTAGES);
        else asm volatile("cp.async.commit_group;" ::: "memory");

#pragma unroll
        for (int ks = 0; ks < 2; ks++) {
            int kc = ks * 2 + chi;
            uint32_t a[4][4];
            uint32_t b[4][4];
#pragma unroll
            for (int mi = 0; mi < 4; mi++) {
                int row = rA + mi * 16;
                ldsm4(a[mi][0], a[mi][1], a[mi][2], a[mi][3],
                      stage + row * 64 + ((kc ^ rowSwz) << 4));
            }
#pragma unroll
            for (int nj = 0; nj < 4; nj++) {
                int row = rB + nj * 16;
                ldsm4(b[nj][0], b[nj][1], b[nj][2], b[nj][3],
                      stage + ABYTES + row * 64 + ((kc ^ rowSwz) << 4));
            }
#pragma unroll
            for (int mi = 0; mi < 4; mi++)
#pragma unroll
                for (int nj = 0; nj < 4; nj++) {
                    mma16816(acc[mi][nj * 2],     a[mi], b[nj][0], b[nj][2]);
                    mma16816(acc[mi][nj * 2 + 1], a[mi], b[nj][1], b[nj][3]);
                }
        }
        __syncthreads();
    }

    const float inv = PASTE ? (1.0f / ASCALE) : 1.0f;
    int cr = lane >> 2, cc = (lane & 3) * 2;
#pragma unroll
    for (int mi = 0; mi < 4; mi++) {
        int mbase = m0 + wr * 64 + mi * 16;
        float c0a = PASTE ? g_cmT[z][mbase + cr] : 0.f;
        float c0b = PASTE ? g_cmT[z][mbase + cr + 8] : 0.f;
#pragma unroll
        for (int ni = 0; ni < 8; ni++) {
            int p = p0 + wc * 64 + ni * 8 + cc;
            float* z0 = &Out[(size_t)(mbase + cr) * L + p];
            float* z1 = &Out[(size_t)(mbase + cr + 8) * L + p];
            *(float2*)z0 = make_float2(acc[mi][ni][0] * inv + c0a, acc[mi][ni][1] * inv + c0a);
            *(float2*)z1 = make_float2(acc[mi][ni][2] * inv + c0b, acc[mi][ni][3] * inv + c0b);
        }
    }
}

// ---------------------------------------------------------------------------
// overlap-add: y[b,c,u,v] = 0.25 * sum over <=4 covering patches of Z
__global__ void scatter_kernel(const float* __restrict__ ZAll) {
    int idx = blockIdx.x * 256 + threadIdx.x;
    int b = blockIdx.y;
    int v = idx & 127, u = (idx >> 7) & 127, c = idx >> 14;
    const float* Z = ZAll + (size_t)b * M2 * L;
    float s = 0.f;
    int ky0 = (u + 1) & 1, kx0 = (v + 1) & 1;
#pragma unroll
    for (int a = 0; a < 2; a++) {
        int ky = ky0 + 2 * a;
        int i2 = u + 1 - ky;
        if (i2 < 0 || i2 > 126) continue;
        int pi = i2 >> 1;
#pragma unroll
        for (int q = 0; q < 2; q++) {
            int kx = kx0 + 2 * q;
            int j2 = v + 1 - kx;
            if (j2 < 0 || j2 > 126) continue;
            int pj = j2 >> 1;
            int m = c * 16 + ky * 4 + kx;
            s += Z[(size_t)m * L + pi * 64 + pj];
        }
    }
    g_y[b * (C1 * H1 * W1) + idx] = 0.25f * s;
}

// final 4-group dilated 3x3 convs (rates 1,2,4,8) + bias + relu, FFMA2 over oc-pairs
__global__ void __launch_bounds__(256) final_conv(const float* __restrict__ w,
                                                  const float* __restrict__ bias,
                                                  float* __restrict__ out) {
    __shared__ __align__(16) float sy[32 * 32];
    __shared__ __align__(16) float swp[9 * 16];
    int t = threadIdx.x;
    int tv = t & 15, tu = t >> 4;
    int tile = blockIdx.x;
    int u0 = (tile >> 3) * 16, v0 = (tile & 7) * 16;
    int bg = blockIdx.y;
    int b = bg >> 2, g = bg & 3;
    int r = 1 << g;
    int Wt = 16 + 2 * r;
    const float* yb = g_y + b * (C1 * H1 * W1);
    ull acc2[8] = {};
    for (int c = 0; c < C1; c++) {
        const float* yc = yb + c * (H1 * W1);
        for (int e = t; e < Wt * Wt; e += 256) {
            int lu = e / Wt, lv = e % Wt;
            int gu = u0 - r + lu, gv = v0 - r + lv;
            float val = 0.f;
            if ((unsigned)gu < 128u && (unsigned)gv < 128u) val = yc[gu * 128 + gv];
            sy[lu * Wt + lv] = val;
        }
        if (t < 144) {
            int oc = t / 9, tap = t % 9;
            swp[tap * 16 + (oc >> 1) * 2 + (oc & 1)] =
                w[((g * 16 + oc) * C1 + c) * 9 + tap];
        }
        __syncthreads();
#pragma unroll
        for (int kh = 0; kh < 3; kh++)
#pragma unroll
            for (int kw = 0; kw < 3; kw++) {
                int tap = kh * 3 + kw;
                ull vv = packf2(sy[(tu + kh * r) * Wt + (tv + kw * r)]);
                const ull* wp = (const ull*)&swp[tap * 16];
#pragma unroll
                for (int pr = 0; pr < 8; pr++)
                    acc2[pr] = ffma2(vv, wp[pr], acc2[pr]);
            }
        __syncthreads();
    }
    int u = u0 + tu, v = v0 + tv;
#pragma unroll
    for (int pr = 0; pr < 8; pr++) {
        union { ull u64; float2 f; } cv; cv.u64 = acc2[pr];
        int oc0 = pr * 2;
        float o0 = fmaxf(cv.f.x + bias[g * 16 + oc0], 0.f);
        float o1 = fmaxf(cv.f.y + bias[g * 16 + oc0 + 1], 0.f);
        out[((b * 64 + g * 16 + oc0) * 128 + u) * 128 + v] = o0;
        out[((b * 64 + g * 16 + oc0 + 1) * 128 + u) * 128 + v] = o1;
    }
}

// ---------------------------------------------------------------------------
extern "C" void kernel_launch(void* const* d_in, const int* in_sizes, int n_in,
                              void* d_out, int out_size) {
    (void)in_sizes; (void)n_in; (void)out_size;
    const float* x1       = (const float*)d_in[0];
    const float* x2       = (const float*)d_in[1];
    const float* mask     = (const float*)d_in[2];
    const float* mask_all = (const float*)d_in[3];
    const float* conv_w   = (const float*)d_in[4];
    const float* conv_b   = (const float*)d_in[5];
    float* out = (float*)d_out;

    cudaFuncSetAttribute(hmma_gemm<KS, true>,  cudaFuncAttributeMaxDynamicSharedMemorySize, SMEM_GEMM);
    cudaFuncSetAttribute(hmma_gemm<KX, false>, cudaFuncAttributeMaxDynamicSharedMemorySize, SMEM_GEMM);

    unsigned char* pA; cudaGetSymbolAddress((void**)&pA, g_poolA);
    unsigned char* pB; cudaGetSymbolAddress((void**)&pB, g_poolB);
    __half* d_X3a;  cudaGetSymbolAddress((void**)&d_X3a, g_X3a);
    __half* d_X3b;  cudaGetSymbolAddress((void**)&d_X3b, g_X3b);

    float*  d_corr = (float*)pA;                       // phase 1 of poolA
    float*  d_Z    = (float*)pA;                       // phase 2 of poolA, first 128MB
    __half* d_AcTh = (__half*)(pA + 134217728);        // phase 2 of poolA, second 128MB
    float*  d_Ac   = (float*)pB;                       // phase 1 of poolB
    __half* d_Rch  = (__half*)pB;                      // phase 2 of poolB, first 64MB

    prep_kernel<<<dim3(16, Bn), 256>>>(x2, mask);
    invnorm_kernel<<<dim3(16, Bn), 256>>>();
    compact_kernel<<<Bn, 256>>>();
    build_X3<<<dim3(16, Bn), 256>>>(x2);
    // corr: M=N=4096, K=192 triples  (writes poolA as corr)
    hmma_gemm<KX, false><<<dim3(32, 16, Bn), 256, SMEM_GEMM>>>(
        d_X3a, d_X3b, d_corr, (size_t)L * KX, (size_t)L * KX, (size_t)L * L, KX / 32);
    scores_kernel<<<dim3(16, L, Bn), 256>>>(d_corr, d_Ac, mask_all);   // corr -> Ac; corr dead after
    softmax_kernel<<<dim3(128, Bn), 256>>>(d_Ac, mask_all);
    transpose_h<<<dim3(128, 128, Bn), 256>>>(d_Ac, d_AcTh);            // Ac dead after
    build_Rc<<<dim3(16, M2, Bn), 256>>>(x1, d_Rch);                    // reuses poolB
    cmT_kernel<<<dim3(M2, Bn), 256>>>(x1);
    // paste: M=2048, N=4096, K=n1 (padded); writes Z into poolA first half
    hmma_gemm<KS, true><<<dim3(16, 16, Bn), 256, SMEM_GEMM>>>(
        d_Rch, d_AcTh, d_Z, (size_t)M2 * KS, (size_t)L * KS, (size_t)M2 * L, 0);
    scatter_kernel<<<dim3(8192, Bn), 256>>>(d_Z);
    final_conv<<<dim3(64, 16), 256>>>(conv_w, conv_b, out);
}

// round 9
// speedup vs baseline: 4.4231x; 1.0622x over previous
#include <cuda_runtime.h>
#include <cuda_fp16.h>
#include <math.h>
#include <stdint.h>

#define Bn 4
#define C1 128
#define H1 128
#define W1 128
#define C2 64
#define L 4096      // H2*W2 patches / pixels
#define M2 2048     // C1*4*4 patch elements
#define KS 4096     // K stride for paste fp16 operands
#define KX 192      // K stride for corr fp16 triple operands (3*64)
#define SCALE_F 10.0f
#define ASCALE 1024.0f

typedef unsigned long long ull;

// ---- static device scratch, pooled & aliased (allocation-free rule) ----
// poolA: [phase 1] corr[Bn] fp32 (4 x 64MB)
//        [phase 2] Z[Bn] fp32 (4 x 32MB @ 0) + AcTh[Bn] fp16 (4 x 32MB @ 128MB)
// poolB: [phase 1] Ac[Bn] fp32 (4 x 64MB)
//        [phase 2] Rch[Bn] fp16 (4 x 16MB @ 0)
__device__ __align__(1024) unsigned char g_poolA[268435456];
__device__ __align__(1024) unsigned char g_poolB[268435456];
__device__ __half g_X3a[Bn][(size_t)L * KX];       // 6.3 MB corr A triples (h,h,l)
__device__ __half g_X3b[Bn][(size_t)L * KX];       // 6.3 MB corr B triples (h,l,h)
__device__ float g_y[Bn * C1 * H1 * W1];           // 33.5 MB pasted images
__device__ float g_pix2[Bn][L];
__device__ float g_invnorm[Bn][L];
__device__ float g_mm[Bn][L];
__device__ int   g_idx1[Bn][L];
__device__ int   g_cnt[Bn][2];
__device__ float g_cmT[Bn][M2];

__device__ __forceinline__ ull ffma2(ull a, ull b, ull c) {
    asm("fma.rn.f32x2 %0, %1, %2, %0;" : "+l"(c) : "l"(a), "l"(b));
    return c;
}
__device__ __forceinline__ ull packf2(float v) {
    ull r;
    uint32_t u = __float_as_uint(v);
    asm("mov.b64 %0, {%1, %1};" : "=l"(r) : "r"(u));
    return r;
}
__device__ __forceinline__ uint32_t smem_u32(const void* p) {
    uint32_t a;
    asm("{ .reg .u64 t; cvta.to.shared.u64 t, %1; cvt.u32.u64 %0, t; }" : "=r"(a) : "l"(p));
    return a;
}

// ---------------------------------------------------------------------------
// fused: pix2 + mm, batched over blockIdx.y
__global__ void prep_kernel(const float* __restrict__ x2, const float* __restrict__ mask) {
    int b = blockIdx.y;
    int a = blockIdx.x * 256 + threadIdx.x;
    const float* x2b = x2 + (size_t)b * C2 * L;
    const float* maskb = mask + (size_t)b * H1 * W1;
    float s = 0.f;
#pragma unroll 16
    for (int c = 0; c < C2; c++) { float v = x2b[c * L + a]; s += v * v; }
    g_pix2[b][a] = s;

    int li = a >> 6, lj = a & 63;
    bool allzero = true;
#pragma unroll
    for (int ky = 0; ky < 4; ky++)
#pragma unroll
        for (int kx = 0; kx < 4; kx++) {
            int u = 2 * li - 1 + ky, v = 2 * lj - 1 + kx;
            if ((unsigned)u < (unsigned)H1 && (unsigned)v < (unsigned)W1) {
                if (maskb[u * W1 + v] != 0.f) allzero = false;
            }
        }
    g_mm[b][a] = allzero ? 1.f : 0.f;
}

__global__ void invnorm_kernel() {
    int b = blockIdx.y;
    int l = blockIdx.x * 256 + threadIdx.x;
    int li = l >> 6, lj = l & 63;
    float s = 0.f;
#pragma unroll
    for (int dy = -1; dy <= 1; dy++)
#pragma unroll
        for (int dx = -1; dx <= 1; dx++) {
            int i = li + dy, j = lj + dx;
            if ((unsigned)i < 64u && (unsigned)j < 64u) s += g_pix2[b][i * 64 + j];
        }
    g_invnorm[b][l] = 1.0f / fmaxf(sqrtf(s), 1e-4f);
}

__global__ void compact_kernel() {
    __shared__ int cnt1[256], off1[256];
    int b = blockIdx.x;
    int t = threadIdx.x;
    int c1 = 0;
    for (int i = 0; i < 16; i++)
        if (g_mm[b][t * 16 + i] > 0.5f) c1++;
    cnt1[t] = c1;
    __syncthreads();
    if (t == 0) {
        int s1 = 0;
        for (int i = 0; i < 256; i++) { off1[i] = s1; s1 += cnt1[i]; }
        g_cnt[b][0] = s1; g_cnt[b][1] = L - s1;
    }
    __syncthreads();
    int o1 = off1[t];
    for (int i = 0; i < 16; i++) {
        int l = t * 16 + i;
        if (g_mm[b][l] > 0.5f) g_idx1[b][o1++] = l;
    }
}

// ---------------------------------------------------------------------------
// corr operand build: per pixel m, per channel c:
// X3a[m][3c..] = (h,h,l), X3b[m][3c..] = (h,l,h)
__global__ void build_X3(const float* __restrict__ x2) {
    int b = blockIdx.y;
    int m = blockIdx.x * 256 + threadIdx.x;
    const float* x2b = x2 + (size_t)b * C2 * L;
    union { __half h[24]; uint4 v[3]; } ua, ub;
#pragma unroll
    for (int cc = 0; cc < 8; cc++) {
#pragma unroll
        for (int j = 0; j < 8; j++) {
            float val = x2b[(cc * 8 + j) * L + m];
            __half h = __float2half(val);
            __half lo = __float2half(val - __half2float(h));
            ua.h[j * 3] = h;  ua.h[j * 3 + 1] = h;  ua.h[j * 3 + 2] = lo;
            ub.h[j * 3] = h;  ub.h[j * 3 + 1] = lo; ub.h[j * 3 + 2] = h;
        }
        size_t off = (size_t)m * KX + cc * 24;
        uint4* pa = (uint4*)&g_X3a[b][off];
        uint4* pb = (uint4*)&g_X3b[b][off];
#pragma unroll
        for (int q = 0; q < 3; q++) { pa[q] = ua.v[q]; pb[q] = ub.v[q]; }
    }
}

// Rch[b][m][k] = fp16 of im2col(x1)[idx1[k]][m], zero-pad k in [n1, n1p)
__global__ void build_Rc(const float* __restrict__ x1, __half* __restrict__ RchAll) {
    int b = blockIdx.z;
    int k = blockIdx.x * 256 + threadIdx.x;
    int m = blockIdx.y;
    int n1 = g_cnt[b][0];
    int n1p = (n1 + 31) & ~31;
    if (k >= n1p) return;
    float val = 0.f;
    if (k < n1) {
        int l = g_idx1[b][k];
        int li = l >> 6, lj = l & 63;
        int c = m >> 4, ky = (m >> 2) & 3, kx = m & 3;
        int u = 2 * li - 1 + ky, v = 2 * lj - 1 + kx;
        if ((unsigned)u < 128u && (unsigned)v < 128u)
            val = x1[((size_t)b * C1 + c) * 16384 + u * 128 + v];
    }
    RchAll[(size_t)b * M2 * KS + (size_t)m * KS + k] = __float2half(val);
}

// cmT[m] = 1e-8 * sum over ALL 4096 patches of R[l,m]  (block tree-reduce)
__global__ void cmT_kernel(const float* __restrict__ x1) {
    __shared__ float red[256];
    int m = blockIdx.x, b = blockIdx.y;
    int t = threadIdx.x;
    int c = m >> 4, ky = (m >> 2) & 3, kx = m & 3;
    const float* xc = x1 + ((size_t)b * C1 + c) * (H1 * W1);
    float s = 0.f;
    for (int l = t; l < L; l += 256) {
        int li = l >> 6, lj = l & 63;
        int u = 2 * li - 1 + ky, v = 2 * lj - 1 + kx;
        if ((unsigned)u < 128u && (unsigned)v < 128u) s += xc[u * W1 + v];
    }
    red[t] = s;
    __syncthreads();
    for (int st = 128; st > 0; st >>= 1) {
        if (t < st) red[t] += red[t + st];
        __syncthreads();
    }
    if (t == 0) g_cmT[b][m] = 1e-8f * red[0];
}

// scores for active rows only, written dense: Ac[b][k][p]
__global__ void scores_kernel(const float* __restrict__ corrAll,
                              float* __restrict__ AcAll,
                              const float* __restrict__ mask_all) {
    int b = blockIdx.z;
    int k = blockIdx.y;
    if (k >= g_cnt[b][0]) return;
    int l = g_idx1[b][k];
    int p = blockIdx.x * 256 + threadIdx.x;
    int li = l >> 6, lj = l & 63, pi = p >> 6, pj = p & 63;
    const float* corr = corrAll + (size_t)b * L * L;
    float s = 0.f;
#pragma unroll
    for (int dy = -1; dy <= 1; dy++)
#pragma unroll
        for (int dx = -1; dx <= 1; dx++) {
            if ((unsigned)(li + dy) < 64u && (unsigned)(lj + dx) < 64u &&
                (unsigned)(pi + dy) < 64u && (unsigned)(pj + dx) < 64u) {
                int o = dy * 64 + dx;
                s += corr[(size_t)(l + o) * L + (p + o)];
            }
        }
    AcAll[(size_t)b * L * L + (size_t)k * L + p] =
        s * g_invnorm[b][l] * mask_all[(size_t)b * L + p];
}

// fused column softmax + transposed fp16 emit:
// pass1 max, pass2 sum (no store), pass3 recompute exp (L2-hot) and write
// AcTh[b][p][k] = fp16((max(e*sc, 1e-8) - 1e-8) * 1024), transposed via smem.
__global__ void __launch_bounds__(256) softmax_emit(const float* __restrict__ AcAll,
                                                    __half* __restrict__ AcThAll,
                                                    const float* __restrict__ mask_all) {
    __shared__ float red[8][32];
    __shared__ float se[32][33];
    int b = blockIdx.y;
    int t = threadIdx.x;
    int col = t & 31, part = t >> 5;
    int p0 = blockIdx.x * 32;
    int p = p0 + col;
    int n1 = g_cnt[b][0], n0 = g_cnt[b][1];
    int n1p = (n1 + 31) & ~31;
    const float* Ac = AcAll + (size_t)b * L * L;
    __half* AcTh = AcThAll + (size_t)b * L * KS;

    // pass 1: column max (masked rows contribute value 0)
    float mx = 0.f;
    for (int k = part; k < n1; k += 8) mx = fmaxf(mx, Ac[(size_t)k * L + p]);
    red[part][col] = mx;
    __syncthreads();
    if (t < 32) {
        float m = red[0][t];
        for (int q = 1; q < 8; q++) m = fmaxf(m, red[q][t]);
        red[0][t] = m;
    }
    __syncthreads();
    mx = red[0][col];
    __syncthreads();

    // pass 2: sum (no store)
    float sm = 0.f;
    for (int k = part; k < n1; k += 8)
        sm += __expf(SCALE_F * (Ac[(size_t)k * L + p] - mx));
    red[part][col] = sm;
    __syncthreads();
    if (t < 32) {
        float s2 = 0.f;
        for (int q = 0; q < 8; q++) s2 += red[q][t];
        s2 += (float)n0 * __expf(-SCALE_F * mx);
        red[0][t] = s2;
    }
    __syncthreads();
    float sc = (1.0f / red[0][col]) * mask_all[(size_t)b * L + p];
    __syncthreads();

    // pass 3: recompute exp, scale+floor-shift, transpose 32x32 tiles, emit fp16
    int kx = t & 31, py = t >> 5;
    for (int k0 = 0; k0 < n1p; k0 += 32) {
#pragma unroll
        for (int i = 0; i < 4; i++) {
            int k = k0 + part + 8 * i;
            float v = 0.f;
            if (k < n1) {
                float e = __expf(SCALE_F * (Ac[(size_t)k * L + p] - mx));
                float a = fmaxf(e * sc, 1e-8f);
                v = (a - 1e-8f) * ASCALE;
            }
            se[part + 8 * i][col] = v;
        }
        __syncthreads();
#pragma unroll
        for (int i = 0; i < 4; i++) {
            int pr = py + 8 * i;
            AcTh[(size_t)(p0 + pr) * KS + k0 + kx] = __float2half(se[kx][pr]);
        }
        __syncthreads();
    }
}

// ---------------------------------------------------------------------------
// generic HMMA fp16 NT GEMM, batched over z.
// PASTE:  Out[z][m][p] = (1/1024)*sum_k A[m,k]*B[p,k] + cmT[z][m], nC from g_cnt
// !PASTE: Out[z][m][p] = sum_k A[m,k]*B[p,k], nC fixed
#define GSTAGES 4
#define ABYTES (128 * 64)          // 128 rows x 32 fp16
#define BBYTES (256 * 64)
#define STAGE_B (ABYTES + BBYTES)  // 24576
#define SMEM_GEMM (GSTAGES * STAGE_B)

__device__ __forceinline__ void cp_async16(uint32_t dst, const void* src) {
    asm volatile("cp.async.cg.shared.global [%0], [%1], 16;" :: "r"(dst), "l"(src) : "memory");
}
__device__ __forceinline__ void ldsm4(uint32_t& r0, uint32_t& r1, uint32_t& r2, uint32_t& r3,
                                      uint32_t a) {
    asm volatile("ldmatrix.sync.aligned.m8n8.x4.shared.b16 {%0,%1,%2,%3}, [%4];"
                 : "=r"(r0), "=r"(r1), "=r"(r2), "=r"(r3) : "r"(a));
}
__device__ __forceinline__ void mma16816(float* c, const uint32_t* a, uint32_t b0, uint32_t b1) {
    asm volatile(
        "mma.sync.aligned.m16n8k16.row.col.f32.f16.f16.f32 "
        "{%0,%1,%2,%3}, {%4,%5,%6,%7}, {%8,%9}, {%0,%1,%2,%3};"
        : "+f"(c[0]), "+f"(c[1]), "+f"(c[2]), "+f"(c[3])
        : "r"(a[0]), "r"(a[1]), "r"(a[2]), "r"(a[3]), "r"(b0), "r"(b1));
}

template<int KSTRIDE, bool PASTE>
__global__ void __launch_bounds__(256, 1) hmma_gemm(
        const __half* __restrict__ Aall, const __half* __restrict__ Ball,
        float* __restrict__ Outall,
        size_t aStride, size_t bStride, size_t oStride, int nCfix) {
    extern __shared__ __align__(16) char smem[];
    uint32_t sb = smem_u32(smem);
    int t = threadIdx.x;
    int lane = t & 31;
    int wr = (t >> 5) & 1;
    int wc = t >> 6;
    int m0 = blockIdx.x * 128;
    int p0 = blockIdx.y * 256;
    int z = blockIdx.z;
    int nC = PASTE ? (((g_cnt[z][0] + 31) & ~31) >> 5) : nCfix;

    const __half* Abase = Aall + z * aStride + (size_t)m0 * KSTRIDE;
    const __half* Bbase = Ball + z * bStride + (size_t)p0 * KSTRIDE;
    float* Out = Outall + z * oStride;

    auto load_chunk = [&](int kt, int s) {
        uint32_t stage = sb + s * STAGE_B;
        int k0 = kt * 32;
#pragma unroll
        for (int i = 0; i < 2; i++) {
            int e = t + i * 256;
            int row = e >> 2, c = e & 3;
            uint32_t dst = stage + row * 64 + ((c ^ (row & 3)) << 4);
            cp_async16(dst, Abase + (size_t)row * KSTRIDE + k0 + c * 8);
        }
#pragma unroll
        for (int i = 0; i < 4; i++) {
            int e = t + i * 256;
            int row = e >> 2, c = e & 3;
            uint32_t dst = stage + ABYTES + row * 64 + ((c ^ (row & 3)) << 4);
            cp_async16(dst, Bbase + (size_t)row * KSTRIDE + k0 + c * 8);
        }
        asm volatile("cp.async.commit_group;" ::: "memory");
    };

#pragma unroll
    for (int s = 0; s < GSTAGES - 1; s++) {
        if (s < nC) load_chunk(s, s);
        else asm volatile("cp.async.commit_group;" ::: "memory");
    }

    float acc[4][8][4] = {};
    int r8 = lane & 7;
    int mat = lane >> 3;
    int rowSwz = r8 & 3;
    int rA = wr * 64 + r8 + (mat & 1) * 8;
    int rB = wc * 64 + r8 + (mat & 1) * 8;
    int chi = mat >> 1;

    for (int kt = 0; kt < nC; kt++) {
        asm volatile("cp.async.wait_group %0;" :: "n"(GSTAGES - 2) : "memory");
        __syncthreads();   // single barrier per iter: all warps done reading the
                           // slot about to be overwritten (read in iter kt-1)
        uint32_t stage = sb + (kt % GSTAGES) * STAGE_B;

        if (kt + GSTAGES - 1 < nC) load_chunk(kt + GSTAGES - 1, (kt + GSTAGES - 1) % GSTAGES);
        else asm volatile("cp.async.commit_group;" ::: "memory");

#pragma unroll
        for (int ks = 0; ks < 2; ks++) {
            int kc = ks * 2 + chi;
            uint32_t a[4][4];
            uint32_t b[4][4];
#pragma unroll
            for (int mi = 0; mi < 4; mi++) {
                int row = rA + mi * 16;
                ldsm4(a[mi][0], a[mi][1], a[mi][2], a[mi][3],
                      stage + row * 64 + ((kc ^ rowSwz) << 4));
            }
#pragma unroll
            for (int nj = 0; nj < 4; nj++) {
                int row = rB + nj * 16;
                ldsm4(b[nj][0], b[nj][1], b[nj][2], b[nj][3],
                      stage + ABYTES + row * 64 + ((kc ^ rowSwz) << 4));
            }
#pragma unroll
            for (int mi = 0; mi < 4; mi++)
#pragma unroll
                for (int nj = 0; nj < 4; nj++) {
                    mma16816(acc[mi][nj * 2],     a[mi], b[nj][0], b[nj][2]);
                    mma16816(acc[mi][nj * 2 + 1], a[mi], b[nj][1], b[nj][3]);
                }
        }
    }

    const float inv = PASTE ? (1.0f / ASCALE) : 1.0f;
    int cr = lane >> 2, cc = (lane & 3) * 2;
#pragma unroll
    for (int mi = 0; mi < 4; mi++) {
        int mbase = m0 + wr * 64 + mi * 16;
        float c0a = PASTE ? g_cmT[z][mbase + cr] : 0.f;
        float c0b = PASTE ? g_cmT[z][mbase + cr + 8] : 0.f;
#pragma unroll
        for (int ni = 0; ni < 8; ni++) {
            int p = p0 + wc * 64 + ni * 8 + cc;
            float* z0 = &Out[(size_t)(mbase + cr) * L + p];
            float* z1 = &Out[(size_t)(mbase + cr + 8) * L + p];
            *(float2*)z0 = make_float2(acc[mi][ni][0] * inv + c0a, acc[mi][ni][1] * inv + c0a);
            *(float2*)z1 = make_float2(acc[mi][ni][2] * inv + c0b, acc[mi][ni][3] * inv + c0b);
        }
    }
}

// ---------------------------------------------------------------------------
// overlap-add: y[b,c,u,v] = 0.25 * sum over <=4 covering patches of Z
__global__ void scatter_kernel(const float* __restrict__ ZAll) {
    int idx = blockIdx.x * 256 + threadIdx.x;
    int b = blockIdx.y;
    int v = idx & 127, u = (idx >> 7) & 127, c = idx >> 14;
    const float* Z = ZAll + (size_t)b * M2 * L;
    float s = 0.f;
    int ky0 = (u + 1) & 1, kx0 = (v + 1) & 1;
#pragma unroll
    for (int a = 0; a < 2; a++) {
        int ky = ky0 + 2 * a;
        int i2 = u + 1 - ky;
        if (i2 < 0 || i2 > 126) continue;
        int pi = i2 >> 1;
#pragma unroll
        for (int q = 0; q < 2; q++) {
            int kx = kx0 + 2 * q;
            int j2 = v + 1 - kx;
            if (j2 < 0 || j2 > 126) continue;
            int pj = j2 >> 1;
            int m = c * 16 + ky * 4 + kx;
            s += Z[(size_t)m * L + pi * 64 + pj];
        }
    }
    g_y[b * (C1 * H1 * W1) + idx] = 0.25f * s;
}

// final 4-group dilated 3x3 convs (rates 1,2,4,8) + bias + relu, FFMA2 over oc-pairs
__global__ void __launch_bounds__(256) final_conv(const float* __restrict__ w,
                                                  const float* __restrict__ bias,
                                                  float* __restrict__ out) {
    __shared__ __align__(16) float sy[32 * 32];
    __shared__ __align__(16) float swp[9 * 16];
    int t = threadIdx.x;
    int tv = t & 15, tu = t >> 4;
    int tile = blockIdx.x;
    int u0 = (tile >> 3) * 16, v0 = (tile & 7) * 16;
    int bg = blockIdx.y;
    int b = bg >> 2, g = bg & 3;
    int r = 1 << g;
    int Wt = 16 + 2 * r;
    const float* yb = g_y + b * (C1 * H1 * W1);
    ull acc2[8] = {};
    for (int c = 0; c < C1; c++) {
        const float* yc = yb + c * (H1 * W1);
        for (int e = t; e < Wt * Wt; e += 256) {
            int lu = e / Wt, lv = e % Wt;
            int gu = u0 - r + lu, gv = v0 - r + lv;
            float val = 0.f;
            if ((unsigned)gu < 128u && (unsigned)gv < 128u) val = yc[gu * 128 + gv];
            sy[lu * Wt + lv] = val;
        }
        if (t < 144) {
            int oc = t / 9, tap = t % 9;
            swp[tap * 16 + (oc >> 1) * 2 + (oc & 1)] =
                w[((g * 16 + oc) * C1 + c) * 9 + tap];
        }
        __syncthreads();
#pragma unroll
        for (int kh = 0; kh < 3; kh++)
#pragma unroll
            for (int kw = 0; kw < 3; kw++) {
                int tap = kh * 3 + kw;
                ull vv = packf2(sy[(tu + kh * r) * Wt + (tv + kw * r)]);
                const ull* wp = (const ull*)&swp[tap * 16];
#pragma unroll
                for (int pr = 0; pr < 8; pr++)
                    acc2[pr] = ffma2(vv, wp[pr], acc2[pr]);
            }
        __syncthreads();
    }
    int u = u0 + tu, v = v0 + tv;
#pragma unroll
    for (int pr = 0; pr < 8; pr++) {
        union { ull u64; float2 f; } cv; cv.u64 = acc2[pr];
        int oc0 = pr * 2;
        float o0 = fmaxf(cv.f.x + bias[g * 16 + oc0], 0.f);
        float o1 = fmaxf(cv.f.y + bias[g * 16 + oc0 + 1], 0.f);
        out[((b * 64 + g * 16 + oc0) * 128 + u) * 128 + v] = o0;
        out[((b * 64 + g * 16 + oc0 + 1) * 128 + u) * 128 + v] = o1;
    }
}

// ---------------------------------------------------------------------------
extern "C" void kernel_launch(void* const* d_in, const int* in_sizes, int n_in,
                              void* d_out, int out_size) {
    (void)in_sizes; (void)n_in; (void)out_size;
    const float* x1       = (const float*)d_in[0];
    const float* x2       = (const float*)d_in[1];
    const float* mask     = (const float*)d_in[2];
    const float* mask_all = (const float*)d_in[3];
    const float* conv_w   = (const float*)d_in[4];
    const float* conv_b   = (const float*)d_in[5];
    float* out = (float*)d_out;

    cudaFuncSetAttribute(hmma_gemm<KS, true>,  cudaFuncAttributeMaxDynamicSharedMemorySize, SMEM_GEMM);
    cudaFuncSetAttribute(hmma_gemm<KX, false>, cudaFuncAttributeMaxDynamicSharedMemorySize, SMEM_GEMM);

    unsigned char* pA; cudaGetSymbolAddress((void**)&pA, g_poolA);
    unsigned char* pB; cudaGetSymbolAddress((void**)&pB, g_poolB);
    __half* d_X3a;  cudaGetSymbolAddress((void**)&d_X3a, g_X3a);
    __half* d_X3b;  cudaGetSymbolAddress((void**)&d_X3b, g_X3b);

    float*  d_corr = (float*)pA;                       // phase 1 of poolA
    float*  d_Z    = (float*)pA;                       // phase 2 of poolA, first 128MB
    __half* d_AcTh = (__half*)(pA + 134217728);        // phase 2 of poolA, second 128MB
    float*  d_Ac   = (float*)pB;                       // phase 1 of poolB
    __half* d_Rch  = (__half*)pB;                      // phase 2 of poolB, first 64MB

    prep_kernel<<<dim3(16, Bn), 256>>>(x2, mask);
    invnorm_kernel<<<dim3(16, Bn), 256>>>();
    compact_kernel<<<Bn, 256>>>();
    build_X3<<<dim3(16, Bn), 256>>>(x2);
    // corr: M=N=4096, K=192 triples  (writes poolA as corr)
    hmma_gemm<KX, false><<<dim3(32, 16, Bn), 256, SMEM_GEMM>>>(
        d_X3a, d_X3b, d_corr, (size_t)L * KX, (size_t)L * KX, (size_t)L * L, KX / 32);
    scores_kernel<<<dim3(16, L, Bn), 256>>>(d_corr, d_Ac, mask_all);   // corr -> Ac; corr dead after
    softmax_emit<<<dim3(128, Bn), 256>>>(d_Ac, d_AcTh, mask_all);      // Ac dead after
    build_Rc<<<dim3(16, M2, Bn), 256>>>(x1, d_Rch);                    // reuses poolB
    cmT_kernel<<<dim3(M2, Bn), 256>>>(x1);
    // paste: M=2048, N=4096, K=n1 (padded); writes Z into poolA first half
    hmma_gemm<KS, true><<<dim3(16, 16, Bn), 256, SMEM_GEMM>>>(
        d_Rch, d_AcTh, d_Z, (size_t)M2 * KS, (size_t)L * KS, (size_t)M2 * L, 0);
    scatter_kernel<<<dim3(8192, Bn), 256>>>(d_Z);
    final_conv<<<dim3(64, 16), 256>>>(conv_w, conv_b, out);
}

// round 10
// speedup vs baseline: 4.5021x; 1.0179x over previous
#include <cuda_runtime.h>
#include <cuda_fp16.h>
#include <math.h>
#include <stdint.h>

#define Bn 4
#define C1 128
#define H1 128
#define W1 128
#define C2 64
#define L 4096      // H2*W2 patches / pixels
#define M2 2048     // C1*4*4 patch elements
#define KS 4096     // K stride for paste fp16 operands
#define KX 192      // K stride for corr fp16 triple operands (3*64)
#define SCALE_F 10.0f
#define ASCALE 1024.0f

typedef unsigned long long ull;

// ---- static device scratch, pooled & aliased (allocation-free rule) ----
// poolA: [phase 1] corr[Bn] fp32 (4 x 64MB)
//        [phase 2] Z[Bn] fp32 (4 x 32MB @ 0) + AcTh[Bn] fp16 (4 x 32MB @ 128MB)
// poolB: Ac[Bn] fp32 (4 x 64MB)
// g_Rch: dedicated (enables stream overlap with scores/softmax which use poolB)
__device__ __align__(1024) unsigned char g_poolA[268435456];
__device__ __align__(1024) unsigned char g_poolB[268435456];
__device__ __half g_Rch[Bn][(size_t)M2 * KS];      // 64 MB paste A fp16 [b][m][k]
__device__ __half g_X3a[Bn][(size_t)L * KX];       // 6.3 MB corr A triples (h,h,l)
__device__ __half g_X3b[Bn][(size_t)L * KX];       // 6.3 MB corr B triples (h,l,h)
__device__ float g_y[Bn * C1 * H1 * W1];           // 33.5 MB pasted images
__device__ float g_pix2[Bn][L];
__device__ float g_invnorm[Bn][L];
__device__ float g_mm[Bn][L];
__device__ int   g_idx1[Bn][L];
__device__ int   g_cnt[Bn][2];
__device__ float g_cmT[Bn][M2];

__device__ __forceinline__ ull ffma2(ull a, ull b, ull c) {
    asm("fma.rn.f32x2 %0, %1, %2, %0;" : "+l"(c) : "l"(a), "l"(b));
    return c;
}
__device__ __forceinline__ ull packf2(float v) {
    ull r;
    uint32_t u = __float_as_uint(v);
    asm("mov.b64 %0, {%1, %1};" : "=l"(r) : "r"(u));
    return r;
}
__device__ __forceinline__ uint32_t smem_u32(const void* p) {
    uint32_t a;
    asm("{ .reg .u64 t; cvta.to.shared.u64 t, %1; cvt.u32.u64 %0, t; }" : "=r"(a) : "l"(p));
    return a;
}

// ---------------------------------------------------------------------------
// fused: pix2 + mm, batched over blockIdx.y
__global__ void prep_kernel(const float* __restrict__ x2, const float* __restrict__ mask) {
    int b = blockIdx.y;
    int a = blockIdx.x * 256 + threadIdx.x;
    const float* x2b = x2 + (size_t)b * C2 * L;
    const float* maskb = mask + (size_t)b * H1 * W1;
    float s = 0.f;
#pragma unroll 16
    for (int c = 0; c < C2; c++) { float v = x2b[c * L + a]; s += v * v; }
    g_pix2[b][a] = s;

    int li = a >> 6, lj = a & 63;
    bool allzero = true;
#pragma unroll
    for (int ky = 0; ky < 4; ky++)
#pragma unroll
        for (int kx = 0; kx < 4; kx++) {
            int u = 2 * li - 1 + ky, v = 2 * lj - 1 + kx;
            if ((unsigned)u < (unsigned)H1 && (unsigned)v < (unsigned)W1) {
                if (maskb[u * W1 + v] != 0.f) allzero = false;
            }
        }
    g_mm[b][a] = allzero ? 1.f : 0.f;
}

__global__ void invnorm_kernel() {
    int b = blockIdx.y;
    int l = blockIdx.x * 256 + threadIdx.x;
    int li = l >> 6, lj = l & 63;
    float s = 0.f;
#pragma unroll
    for (int dy = -1; dy <= 1; dy++)
#pragma unroll
        for (int dx = -1; dx <= 1; dx++) {
            int i = li + dy, j = lj + dx;
            if ((unsigned)i < 64u && (unsigned)j < 64u) s += g_pix2[b][i * 64 + j];
        }
    g_invnorm[b][l] = 1.0f / fmaxf(sqrtf(s), 1e-4f);
}

__global__ void compact_kernel() {
    __shared__ int cnt1[256], off1[256];
    int b = blockIdx.x;
    int t = threadIdx.x;
    int c1 = 0;
    for (int i = 0; i < 16; i++)
        if (g_mm[b][t * 16 + i] > 0.5f) c1++;
    cnt1[t] = c1;
    __syncthreads();
    if (t == 0) {
        int s1 = 0;
        for (int i = 0; i < 256; i++) { off1[i] = s1; s1 += cnt1[i]; }
        g_cnt[b][0] = s1; g_cnt[b][1] = L - s1;
    }
    __syncthreads();
    int o1 = off1[t];
    for (int i = 0; i < 16; i++) {
        int l = t * 16 + i;
        if (g_mm[b][l] > 0.5f) g_idx1[b][o1++] = l;
    }
}

// ---------------------------------------------------------------------------
// corr operand build: per pixel m, per channel c:
// X3a[m][3c..] = (h,h,l), X3b[m][3c..] = (h,l,h)
__global__ void build_X3(const float* __restrict__ x2) {
    int b = blockIdx.y;
    int m = blockIdx.x * 256 + threadIdx.x;
    const float* x2b = x2 + (size_t)b * C2 * L;
    union { __half h[24]; uint4 v[3]; } ua, ub;
#pragma unroll
    for (int cc = 0; cc < 8; cc++) {
#pragma unroll
        for (int j = 0; j < 8; j++) {
            float val = x2b[(cc * 8 + j) * L + m];
            __half h = __float2half(val);
            __half lo = __float2half(val - __half2float(h));
            ua.h[j * 3] = h;  ua.h[j * 3 + 1] = h;  ua.h[j * 3 + 2] = lo;
            ub.h[j * 3] = h;  ub.h[j * 3 + 1] = lo; ub.h[j * 3 + 2] = h;
        }
        size_t off = (size_t)m * KX + cc * 24;
        uint4* pa = (uint4*)&g_X3a[b][off];
        uint4* pb = (uint4*)&g_X3b[b][off];
#pragma unroll
        for (int q = 0; q < 3; q++) { pa[q] = ua.v[q]; pb[q] = ub.v[q]; }
    }
}

// Rch[b][m][k] = fp16 of im2col(x1)[idx1[k]][m], zero-pad k in [n1, n1p)
__global__ void build_Rc(const float* __restrict__ x1) {
    int b = blockIdx.z;
    int k = blockIdx.x * 256 + threadIdx.x;
    int m = blockIdx.y;
    int n1 = g_cnt[b][0];
    int n1p = (n1 + 31) & ~31;
    if (k >= n1p) return;
    float val = 0.f;
    if (k < n1) {
        int l = g_idx1[b][k];
        int li = l >> 6, lj = l & 63;
        int c = m >> 4, ky = (m >> 2) & 3, kx = m & 3;
        int u = 2 * li - 1 + ky, v = 2 * lj - 1 + kx;
        if ((unsigned)u < 128u && (unsigned)v < 128u)
            val = x1[((size_t)b * C1 + c) * 16384 + u * 128 + v];
    }
    g_Rch[b][(size_t)m * KS + k] = __float2half(val);
}

// cmT[m] = 1e-8 * sum over ALL 4096 patches of R[l,m]  (block tree-reduce)
__global__ void cmT_kernel(const float* __restrict__ x1) {
    __shared__ float red[256];
    int m = blockIdx.x, b = blockIdx.y;
    int t = threadIdx.x;
    int c = m >> 4, ky = (m >> 2) & 3, kx = m & 3;
    const float* xc = x1 + ((size_t)b * C1 + c) * (H1 * W1);
    float s = 0.f;
    for (int l = t; l < L; l += 256) {
        int li = l >> 6, lj = l & 63;
        int u = 2 * li - 1 + ky, v = 2 * lj - 1 + kx;
        if ((unsigned)u < 128u && (unsigned)v < 128u) s += xc[u * W1 + v];
    }
    red[t] = s;
    __syncthreads();
    for (int st = 128; st > 0; st >>= 1) {
        if (t < st) red[t] += red[t + st];
        __syncthreads();
    }
    if (t == 0) g_cmT[b][m] = 1e-8f * red[0];
}

// scores for active rows only, written dense: Ac[b][k][p]
__global__ void scores_kernel(const float* __restrict__ corrAll,
                              float* __restrict__ AcAll,
                              const float* __restrict__ mask_all) {
    int b = blockIdx.z;
    int k = blockIdx.y;
    if (k >= g_cnt[b][0]) return;
    int l = g_idx1[b][k];
    int p = blockIdx.x * 256 + threadIdx.x;
    int li = l >> 6, lj = l & 63, pi = p >> 6, pj = p & 63;
    const float* corr = corrAll + (size_t)b * L * L;
    float s = 0.f;
#pragma unroll
    for (int dy = -1; dy <= 1; dy++)
#pragma unroll
        for (int dx = -1; dx <= 1; dx++) {
            if ((unsigned)(li + dy) < 64u && (unsigned)(lj + dx) < 64u &&
                (unsigned)(pi + dy) < 64u && (unsigned)(pj + dx) < 64u) {
                int o = dy * 64 + dx;
                s += corr[(size_t)(l + o) * L + (p + o)];
            }
        }
    AcAll[(size_t)b * L * L + (size_t)k * L + p] =
        s * g_invnorm[b][l] * mask_all[(size_t)b * L + p];
}

// fused column softmax + transposed fp16 emit. Online max+sum (1 pass), then
// emit pass recomputes exp (L2-hot) and writes
// AcTh[b][p][k] = fp16((max(e*sc, 1e-8) - 1e-8) * 1024), transposed via smem.
__global__ void __launch_bounds__(256) softmax_emit(const float* __restrict__ AcAll,
                                                    __half* __restrict__ AcThAll,
                                                    const float* __restrict__ mask_all) {
    __shared__ float redM[8][32];
    __shared__ float redS[8][32];
    __shared__ float se[32][33];
    int b = blockIdx.y;
    int t = threadIdx.x;
    int col = t & 31, part = t >> 5;
    int p0 = blockIdx.x * 32;
    int p = p0 + col;
    int n1 = g_cnt[b][0], n0 = g_cnt[b][1];
    int n1p = (n1 + 31) & ~31;
    const float* Ac = AcAll + (size_t)b * L * L;
    __half* AcTh = AcThAll + (size_t)b * L * KS;

    // online pass: running max + rescaled sum (masked rows contribute value 0 to max)
    float mx = 0.f, sm = 0.f;
    for (int k = part; k < n1; k += 8) {
        float v = Ac[(size_t)k * L + p];
        if (v > mx) { sm *= __expf(SCALE_F * (mx - v)); mx = v; }
        sm += __expf(SCALE_F * (v - mx));
    }
    redM[part][col] = mx;
    redS[part][col] = sm;
    __syncthreads();
    if (t < 32) {
        float gm = redM[0][t], gs = redS[0][t];
        for (int q = 1; q < 8; q++) {
            float m2 = redM[q][t], s2 = redS[q][t];
            if (m2 > gm) { gs *= __expf(SCALE_F * (gm - m2)); gm = m2; }
            gs += s2 * __expf(SCALE_F * (m2 - gm));
        }
        gs += (float)n0 * __expf(-SCALE_F * gm);   // masked rows (value 0)
        redM[0][t] = gm;
        redS[0][t] = gs;
    }
    __syncthreads();
    mx = redM[0][col];
    float sc = (1.0f / redS[0][col]) * mask_all[(size_t)b * L + p];
    __syncthreads();

    // emit pass: recompute exp, scale+floor-shift, transpose 32x32 tiles, fp16
    int kx = t & 31, py = t >> 5;
    for (int k0 = 0; k0 < n1p; k0 += 32) {
#pragma unroll
        for (int i = 0; i < 4; i++) {
            int k = k0 + part + 8 * i;
            float v = 0.f;
            if (k < n1) {
                float e = __expf(SCALE_F * (Ac[(size_t)k * L + p] - mx));
                float a = fmaxf(e * sc, 1e-8f);
                v = (a - 1e-8f) * ASCALE;
            }
            se[part + 8 * i][col] = v;
        }
        __syncthreads();
#pragma unroll
        for (int i = 0; i < 4; i++) {
            int pr = py + 8 * i;
            AcTh[(size_t)(p0 + pr) * KS + k0 + kx] = __float2half(se[kx][pr]);
        }
        __syncthreads();
    }
}

// ---------------------------------------------------------------------------
// generic HMMA fp16 NT GEMM, batched over z.
// PASTE:  Out[z][m][p] = (1/1024)*sum_k A[m,k]*B[p,k] + cmT[z][m], nC from g_cnt
// !PASTE: Out[z][m][p] = sum_k A[m,k]*B[p,k], nC fixed
#define GSTAGES 4
#define ABYTES (128 * 64)          // 128 rows x 32 fp16
#define BBYTES (256 * 64)
#define STAGE_B (ABYTES + BBYTES)  // 24576
#define SMEM_GEMM (GSTAGES * STAGE_B)

__device__ __forceinline__ void cp_async16(uint32_t dst, const void* src) {
    asm volatile("cp.async.cg.shared.global [%0], [%1], 16;" :: "r"(dst), "l"(src) : "memory");
}
__device__ __forceinline__ void ldsm4(uint32_t& r0, uint32_t& r1, uint32_t& r2, uint32_t& r3,
                                      uint32_t a) {
    asm volatile("ldmatrix.sync.aligned.m8n8.x4.shared.b16 {%0,%1,%2,%3}, [%4];"
                 : "=r"(r0), "=r"(r1), "=r"(r2), "=r"(r3) : "r"(a));
}
__device__ __forceinline__ void mma16816(float* c, const uint32_t* a, uint32_t b0, uint32_t b1) {
    asm volatile(
        "mma.sync.aligned.m16n8k16.row.col.f32.f16.f16.f32 "
        "{%0,%1,%2,%3}, {%4,%5,%6,%7}, {%8,%9}, {%0,%1,%2,%3};"
        : "+f"(c[0]), "+f"(c[1]), "+f"(c[2]), "+f"(c[3])
        : "r"(a[0]), "r"(a[1]), "r"(a[2]), "r"(a[3]), "r"(b0), "r"(b1));
}

template<int KSTRIDE, bool PASTE>
__global__ void __launch_bounds__(256, 1) hmma_gemm(
        const __half* __restrict__ Aall, const __half* __restrict__ Ball,
        float* __restrict__ Outall,
        size_t aStride, size_t bStride, size_t oStride, int nCfix) {
    extern __shared__ __align__(16) char smem[];
    uint32_t sb = smem_u32(smem);
    int t = threadIdx.x;
    int lane = t & 31;
    int wr = (t >> 5) & 1;
    int wc = t >> 6;
    int m0 = blockIdx.x * 128;
    int p0 = blockIdx.y * 256;
    int z = blockIdx.z;
    int nC = PASTE ? (((g_cnt[z][0] + 31) & ~31) >> 5) : nCfix;

    const __half* Abase = Aall + z * aStride + (size_t)m0 * KSTRIDE;
    const __half* Bbase = Ball + z * bStride + (size_t)p0 * KSTRIDE;
    float* Out = Outall + z * oStride;

    auto load_chunk = [&](int kt, int s) {
        uint32_t stage = sb + s * STAGE_B;
        int k0 = kt * 32;
#pragma unroll
        for (int i = 0; i < 2; i++) {
            int e = t + i * 256;
            int row = e >> 2, c = e & 3;
            uint32_t dst = stage + row * 64 + ((c ^ (row & 3)) << 4);
            cp_async16(dst, Abase + (size_t)row * KSTRIDE + k0 + c * 8);
        }
#pragma unroll
        for (int i = 0; i < 4; i++) {
            int e = t + i * 256;
            int row = e >> 2, c = e & 3;
            uint32_t dst = stage + ABYTES + row * 64 + ((c ^ (row & 3)) << 4);
            cp_async16(dst, Bbase + (size_t)row * KSTRIDE + k0 + c * 8);
        }
        asm volatile("cp.async.commit_group;" ::: "memory");
    };

#pragma unroll
    for (int s = 0; s < GSTAGES - 1; s++) {
        if (s < nC) load_chunk(s, s);
        else asm volatile("cp.async.commit_group;" ::: "memory");
    }

    float acc[4][8][4] = {};
    int r8 = lane & 7;
    int mat = lane >> 3;
    int rowSwz = r8 & 3;
    int rA = wr * 64 + r8 + (mat & 1) * 8;
    int rB = wc * 64 + r8 + (mat & 1) * 8;
    int chi = mat >> 1;

    for (int kt = 0; kt < nC; kt++) {
        asm volatile("cp.async.wait_group %0;" :: "n"(GSTAGES - 2) : "memory");
        __syncthreads();   // single barrier per iter
        uint32_t stage = sb + (kt % GSTAGES) * STAGE_B;

        if (kt + GSTAGES - 1 < nC) load_chunk(kt + GSTAGES - 1, (kt + GSTAGES - 1) % GSTAGES);
        else asm volatile("cp.async.commit_group;" ::: "memory");

#pragma unroll
        for (int ks = 0; ks < 2; ks++) {
            int kc = ks * 2 + chi;
            uint32_t a[4][4];
            uint32_t b[4][4];
#pragma unroll
            for (int mi = 0; mi < 4; mi++) {
                int row = rA + mi * 16;
                ldsm4(a[mi][0], a[mi][1], a[mi][2], a[mi][3],
                      stage + row * 64 + ((kc ^ rowSwz) << 4));
            }
#pragma unroll
            for (int nj = 0; nj < 4; nj++) {
                int row = rB + nj * 16;
                ldsm4(b[nj][0], b[nj][1], b[nj][2], b[nj][3],
                      stage + ABYTES + row * 64 + ((kc ^ rowSwz) << 4));
            }
#pragma unroll
            for (int mi = 0; mi < 4; mi++)
#pragma unroll
                for (int nj = 0; nj < 4; nj++) {
                    mma16816(acc[mi][nj * 2],     a[mi], b[nj][0], b[nj][2]);
                    mma16816(acc[mi][nj * 2 + 1], a[mi], b[nj][1], b[nj][3]);
                }
        }
    }

    const float inv = PASTE ? (1.0f / ASCALE) : 1.0f;
    int cr = lane >> 2, cc = (lane & 3) * 2;
#pragma unroll
    for (int mi = 0; mi < 4; mi++) {
        int mbase = m0 + wr * 64 + mi * 16;
        float c0a = PASTE ? g_cmT[z][mbase + cr] : 0.f;
        float c0b = PASTE ? g_cmT[z][mbase + cr + 8] : 0.f;
#pragma unroll
        for (int ni = 0; ni < 8; ni++) {
            int p = p0 + wc * 64 + ni * 8 + cc;
            float* z0 = &Out[(size_t)(mbase + cr) * L + p];
            float* z1 = &Out[(size_t)(mbase + cr + 8) * L + p];
            *(float2*)z0 = make_float2(acc[mi][ni][0] * inv + c0a, acc[mi][ni][1] * inv + c0a);
            *(float2*)z1 = make_float2(acc[mi][ni][2] * inv + c0b, acc[mi][ni][3] * inv + c0b);
        }
    }
}

// ---------------------------------------------------------------------------
// overlap-add: y[b,c,u,v] = 0.25 * sum over <=4 covering patches of Z
__global__ void scatter_kernel(const float* __restrict__ ZAll) {
    int idx = blockIdx.x * 256 + threadIdx.x;
    int b = blockIdx.y;
    int v = idx & 127, u = (idx >> 7) & 127, c = idx >> 14;
    const float* Z = ZAll + (size_t)b * M2 * L;
    float s = 0.f;
    int ky0 = (u + 1) & 1, kx0 = (v + 1) & 1;
#pragma unroll
    for (int a = 0; a < 2; a++) {
        int ky = ky0 + 2 * a;
        int i2 = u + 1 - ky;
        if (i2 < 0 || i2 > 126) continue;
        int pi = i2 >> 1;
#pragma unroll
        for (int q = 0; q < 2; q++) {
            int kx = kx0 + 2 * q;
            int j2 = v + 1 - kx;
            if (j2 < 0 || j2 > 126) continue;
            int pj = j2 >> 1;
            int m = c * 16 + ky * 4 + kx;
            s += Z[(size_t)m * L + pi * 64 + pj];
        }
    }
    g_y[b * (C1 * H1 * W1) + idx] = 0.25f * s;
}

// final 4-group dilated 3x3 convs (rates 1,2,4,8) + bias + relu, FFMA2 over oc-pairs
__global__ void __launch_bounds__(256) final_conv(const float* __restrict__ w,
                                                  const float* __restrict__ bias,
                                                  float* __restrict__ out) {
    __shared__ __align__(16) float sy[32 * 32];
    __shared__ __align__(16) float swp[9 * 16];
    int t = threadIdx.x;
    int tv = t & 15, tu = t >> 4;
    int tile = blockIdx.x;
    int u0 = (tile >> 3) * 16, v0 = (tile & 7) * 16;
    int bg = blockIdx.y;
    int b = bg >> 2, g = bg & 3;
    int r = 1 << g;
    int Wt = 16 + 2 * r;
    const float* yb = g_y + b * (C1 * H1 * W1);
    ull acc2[8] = {};
    for (int c = 0; c < C1; c++) {
        const float* yc = yb + c * (H1 * W1);
        for (int e = t; e < Wt * Wt; e += 256) {
            int lu = e / Wt, lv = e % Wt;
            int gu = u0 - r + lu, gv = v0 - r + lv;
            float val = 0.f;
            if ((unsigned)gu < 128u && (unsigned)gv < 128u) val = yc[gu * 128 + gv];
            sy[lu * Wt + lv] = val;
        }
        if (t < 144) {
            int oc = t / 9, tap = t % 9;
            swp[tap * 16 + (oc >> 1) * 2 + (oc & 1)] =
                w[((g * 16 + oc) * C1 + c) * 9 + tap];
        }
        __syncthreads();
#pragma unroll
        for (int kh = 0; kh < 3; kh++)
#pragma unroll
            for (int kw = 0; kw < 3; kw++) {
                int tap = kh * 3 + kw;
                ull vv = packf2(sy[(tu + kh * r) * Wt + (tv + kw * r)]);
                const ull* wp = (const ull*)&swp[tap * 16];
#pragma unroll
                for (int pr = 0; pr < 8; pr++)
                    acc2[pr] = ffma2(vv, wp[pr], acc2[pr]);
            }
        __syncthreads();
    }
    int u = u0 + tu, v = v0 + tv;
#pragma unroll
    for (int pr = 0; pr < 8; pr++) {
        union { ull u64; float2 f; } cv; cv.u64 = acc2[pr];
        int oc0 = pr * 2;
        float o0 = fmaxf(cv.f.x + bias[g * 16 + oc0], 0.f);
        float o1 = fmaxf(cv.f.y + bias[g * 16 + oc0 + 1], 0.f);
        out[((b * 64 + g * 16 + oc0) * 128 + u) * 128 + v] = o0;
        out[((b * 64 + g * 16 + oc0 + 1) * 128 + u) * 128 + v] = o1;
    }
}

// ---------------------------------------------------------------------------
extern "C" void kernel_launch(void* const* d_in, const int* in_sizes, int n_in,
                              void* d_out, int out_size) {
    (void)in_sizes; (void)n_in; (void)out_size;
    const float* x1       = (const float*)d_in[0];
    const float* x2       = (const float*)d_in[1];
    const float* mask     = (const float*)d_in[2];
    const float* mask_all = (const float*)d_in[3];
    const float* conv_w   = (const float*)d_in[4];
    const float* conv_b   = (const float*)d_in[5];
    float* out = (float*)d_out;

    cudaFuncSetAttribute(hmma_gemm<KS, true>,  cudaFuncAttributeMaxDynamicSharedMemorySize, SMEM_GEMM);
    cudaFuncSetAttribute(hmma_gemm<KX, false>, cudaFuncAttributeMaxDynamicSharedMemorySize, SMEM_GEMM);

    unsigned char* pA; cudaGetSymbolAddress((void**)&pA, g_poolA);
    unsigned char* pB; cudaGetSymbolAddress((void**)&pB, g_poolB);
    __half* d_X3a;  cudaGetSymbolAddress((void**)&d_X3a, g_X3a);
    __half* d_X3b;  cudaGetSymbolAddress((void**)&d_X3b, g_X3b);
    __half* d_Rch;  cudaGetSymbolAddress((void**)&d_Rch, g_Rch);

    float*  d_corr = (float*)pA;                       // phase 1 of poolA
    float*  d_Z    = (float*)pA;                       // phase 2 of poolA, first 128MB
    __half* d_AcTh = (__half*)(pA + 134217728);        // phase 2 of poolA, second 128MB
    float*  d_Ac   = (float*)pB;                       // poolB

    // fork-join stream (created per call; not destroyed — destruction during
    // an active capture is the risky op, a handful of leaked host objects is not)
    cudaStream_t s2;
    cudaStreamCreateWithFlags(&s2, cudaStreamNonBlocking);
    cudaEvent_t evA, evB;
    cudaEventCreateWithFlags(&evA, cudaEventDisableTiming);
    cudaEventCreateWithFlags(&evB, cudaEventDisableTiming);

    prep_kernel<<<dim3(16, Bn), 256>>>(x2, mask);                      // #1
    build_X3<<<dim3(16, Bn), 256>>>(x2);                               // #2
    invnorm_kernel<<<dim3(16, Bn), 256>>>();                           // #3
    // corr: M=N=4096, K=192 triples (4th launch -> ncu samples this)
    hmma_gemm<KX, false><<<dim3(32, 16, Bn), 256, SMEM_GEMM>>>(        // #4
        d_X3a, d_X3b, d_corr, (size_t)L * KX, (size_t)L * KX, (size_t)L * L, KX / 32);
    compact_kernel<<<Bn, 256>>>();                                     // #5

    // fork: build_Rc + cmT overlap scores/softmax on s2 (disjoint buffers)
    cudaEventRecord(evA, 0);
    cudaStreamWaitEvent(s2, evA, 0);
    build_Rc<<<dim3(16, M2, Bn), 256, 0, s2>>>(x1);
    cmT_kernel<<<dim3(M2, Bn), 256, 0, s2>>>(x1);
    cudaEventRecord(evB, s2);

    scores_kernel<<<dim3(16, L, Bn), 256>>>(d_corr, d_Ac, mask_all);   // corr dead after
    softmax_emit<<<dim3(128, Bn), 256>>>(d_Ac, d_AcTh, mask_all);      // Ac dead after

    // join, then paste: M=2048, N=4096, K=n1 (padded)
    cudaStreamWaitEvent(0, evB, 0);
    hmma_gemm<KS, true><<<dim3(16, 16, Bn), 256, SMEM_GEMM>>>(
        d_Rch, d_AcTh, d_Z, (size_t)M2 * KS, (size_t)L * KS, (size_t)M2 * L, 0);
    scatter_kernel<<<dim3(8192, Bn), 256>>>(d_Z);
    final_conv<<<dim3(64, 16), 256>>>(conv_w, conv_b, out);
}

// round 11
// speedup vs baseline: 4.6042x; 1.0227x over previous
#include <cuda_runtime.h>
#include <cuda_fp16.h>
#include <math.h>
#include <stdint.h>

#define Bn 4
#define C1 128
#define H1 128
#define W1 128
#define C2 64
#define L 4096      // H2*W2 patches / pixels
#define M2 2048     // C1*4*4 patch elements
#define KS 4096     // K stride for paste fp16 operands
#define KX 192      // K stride for corr fp16 triple operands (3*64)
#define SCALE_F 10.0f
#define ASCALE 1024.0f

typedef unsigned long long ull;

// ---- static device scratch, pooled & aliased (allocation-free rule) ----
// poolA: [phase 1] corr[Bn] fp32 (4 x 64MB)
//        [phase 2] Z[Bn] fp32 (4 x 32MB @ 0) + AcTh[Bn] fp16 (4 x 32MB @ 128MB)
// poolB: Ac[Bn] fp32 (4 x 64MB)
// g_Rch: dedicated (enables stream overlap with scores/softmax which use poolB)
__device__ __align__(1024) unsigned char g_poolA[268435456];
__device__ __align__(1024) unsigned char g_poolB[268435456];
__device__ __half g_Rch[Bn][(size_t)M2 * KS];      // 64 MB paste A fp16 [b][m][k]
__device__ __half g_X3a[Bn][(size_t)L * KX];       // 6.3 MB corr A triples (h,h,l)
__device__ __half g_X3b[Bn][(size_t)L * KX];       // 6.3 MB corr B triples (h,l,h)
__device__ float g_y[Bn * C1 * H1 * W1];           // 33.5 MB pasted images
__device__ float g_pix2[Bn][L];
__device__ float g_invnorm[Bn][L];
__device__ float g_mm[Bn][L];
__device__ int   g_idx1[Bn][L];
__device__ int   g_cnt[Bn][2];
__device__ float g_cmT[Bn][M2];

__device__ __forceinline__ ull ffma2(ull a, ull b, ull c) {
    asm("fma.rn.f32x2 %0, %1, %2, %0;" : "+l"(c) : "l"(a), "l"(b));
    return c;
}
__device__ __forceinline__ ull packf2(float v) {
    ull r;
    uint32_t u = __float_as_uint(v);
    asm("mov.b64 %0, {%1, %1};" : "=l"(r) : "r"(u));
    return r;
}
__device__ __forceinline__ uint32_t smem_u32(const void* p) {
    uint32_t a;
    asm("{ .reg .u64 t; cvta.to.shared.u64 t, %1; cvt.u32.u64 %0, t; }" : "=r"(a) : "l"(p));
    return a;
}

// ---------------------------------------------------------------------------
// fused: pix2 + mm, batched over blockIdx.y
__global__ void prep_kernel(const float* __restrict__ x2, const float* __restrict__ mask) {
    int b = blockIdx.y;
    int a = blockIdx.x * 256 + threadIdx.x;
    const float* x2b = x2 + (size_t)b * C2 * L;
    const float* maskb = mask + (size_t)b * H1 * W1;
    float s = 0.f;
#pragma unroll 16
    for (int c = 0; c < C2; c++) { float v = x2b[c * L + a]; s += v * v; }
    g_pix2[b][a] = s;

    int li = a >> 6, lj = a & 63;
    bool allzero = true;
#pragma unroll
    for (int ky = 0; ky < 4; ky++)
#pragma unroll
        for (int kx = 0; kx < 4; kx++) {
            int u = 2 * li - 1 + ky, v = 2 * lj - 1 + kx;
            if ((unsigned)u < (unsigned)H1 && (unsigned)v < (unsigned)W1) {
                if (maskb[u * W1 + v] != 0.f) allzero = false;
            }
        }
    g_mm[b][a] = allzero ? 1.f : 0.f;
}

__global__ void invnorm_kernel() {
    int b = blockIdx.y;
    int l = blockIdx.x * 256 + threadIdx.x;
    int li = l >> 6, lj = l & 63;
    float s = 0.f;
#pragma unroll
    for (int dy = -1; dy <= 1; dy++)
#pragma unroll
        for (int dx = -1; dx <= 1; dx++) {
            int i = li + dy, j = lj + dx;
            if ((unsigned)i < 64u && (unsigned)j < 64u) s += g_pix2[b][i * 64 + j];
        }
    g_invnorm[b][l] = 1.0f / fmaxf(sqrtf(s), 1e-4f);
}

__global__ void compact_kernel() {
    __shared__ int cnt1[256], off1[256];
    int b = blockIdx.x;
    int t = threadIdx.x;
    int c1 = 0;
    for (int i = 0; i < 16; i++)
        if (g_mm[b][t * 16 + i] > 0.5f) c1++;
    cnt1[t] = c1;
    __syncthreads();
    if (t == 0) {
        int s1 = 0;
        for (int i = 0; i < 256; i++) { off1[i] = s1; s1 += cnt1[i]; }
        g_cnt[b][0] = s1; g_cnt[b][1] = L - s1;
    }
    __syncthreads();
    int o1 = off1[t];
    for (int i = 0; i < 16; i++) {
        int l = t * 16 + i;
        if (g_mm[b][l] > 0.5f) g_idx1[b][o1++] = l;
    }
}

// ---------------------------------------------------------------------------
// corr operand build: per pixel m, per channel c:
// X3a[m][3c..] = (h,h,l), X3b[m][3c..] = (h,l,h)
__global__ void build_X3(const float* __restrict__ x2) {
    int b = blockIdx.y;
    int m = blockIdx.x * 256 + threadIdx.x;
    const float* x2b = x2 + (size_t)b * C2 * L;
    union { __half h[24]; uint4 v[3]; } ua, ub;
#pragma unroll
    for (int cc = 0; cc < 8; cc++) {
#pragma unroll
        for (int j = 0; j < 8; j++) {
            float val = x2b[(cc * 8 + j) * L + m];
            __half h = __float2half(val);
            __half lo = __float2half(val - __half2float(h));
            ua.h[j * 3] = h;  ua.h[j * 3 + 1] = h;  ua.h[j * 3 + 2] = lo;
            ub.h[j * 3] = h;  ub.h[j * 3 + 1] = lo; ub.h[j * 3 + 2] = h;
        }
        size_t off = (size_t)m * KX + cc * 24;
        uint4* pa = (uint4*)&g_X3a[b][off];
        uint4* pb = (uint4*)&g_X3b[b][off];
#pragma unroll
        for (int q = 0; q < 3; q++) { pa[q] = ua.v[q]; pb[q] = ub.v[q]; }
    }
}

// Rch[b][m][k] = fp16 of im2col(x1)[idx1[k]][m], zero-pad k in [n1, n1p)
__global__ void build_Rc(const float* __restrict__ x1) {
    int b = blockIdx.z;
    int k = blockIdx.x * 256 + threadIdx.x;
    int m = blockIdx.y;
    int n1 = g_cnt[b][0];
    int n1p = (n1 + 31) & ~31;
    if (k >= n1p) return;
    float val = 0.f;
    if (k < n1) {
        int l = g_idx1[b][k];
        int li = l >> 6, lj = l & 63;
        int c = m >> 4, ky = (m >> 2) & 3, kx = m & 3;
        int u = 2 * li - 1 + ky, v = 2 * lj - 1 + kx;
        if ((unsigned)u < 128u && (unsigned)v < 128u)
            val = x1[((size_t)b * C1 + c) * 16384 + u * 128 + v];
    }
    g_Rch[b][(size_t)m * KS + k] = __float2half(val);
}

// cmT[m] = 1e-8 * sum over ALL 4096 patches of R[l,m]  (block tree-reduce)
__global__ void cmT_kernel(const float* __restrict__ x1) {
    __shared__ float red[256];
    int m = blockIdx.x, b = blockIdx.y;
    int t = threadIdx.x;
    int c = m >> 4, ky = (m >> 2) & 3, kx = m & 3;
    const float* xc = x1 + ((size_t)b * C1 + c) * (H1 * W1);
    float s = 0.f;
    for (int l = t; l < L; l += 256) {
        int li = l >> 6, lj = l & 63;
        int u = 2 * li - 1 + ky, v = 2 * lj - 1 + kx;
        if ((unsigned)u < 128u && (unsigned)v < 128u) s += xc[u * W1 + v];
    }
    red[t] = s;
    __syncthreads();
    for (int st = 128; st > 0; st >>= 1) {
        if (t < st) red[t] += red[t + st];
        __syncthreads();
    }
    if (t == 0) g_cmT[b][m] = 1e-8f * red[0];
}

// scores for active rows only, written dense: Ac[b][k][p]
__global__ void scores_kernel(const float* __restrict__ corrAll,
                              float* __restrict__ AcAll,
                              const float* __restrict__ mask_all) {
    int b = blockIdx.z;
    int k = blockIdx.y;
    if (k >= g_cnt[b][0]) return;
    int l = g_idx1[b][k];
    int p = blockIdx.x * 256 + threadIdx.x;
    int li = l >> 6, lj = l & 63, pi = p >> 6, pj = p & 63;
    const float* corr = corrAll + (size_t)b * L * L;
    float s = 0.f;
#pragma unroll
    for (int dy = -1; dy <= 1; dy++)
#pragma unroll
        for (int dx = -1; dx <= 1; dx++) {
            if ((unsigned)(li + dy) < 64u && (unsigned)(lj + dx) < 64u &&
                (unsigned)(pi + dy) < 64u && (unsigned)(pj + dx) < 64u) {
                int o = dy * 64 + dx;
                s += corr[(size_t)(l + o) * L + (p + o)];
            }
        }
    AcAll[(size_t)b * L * L + (size_t)k * L + p] =
        s * g_invnorm[b][l] * mask_all[(size_t)b * L + p];
}

// fused column softmax + transposed fp16 emit. Online max+sum (1 pass), then
// emit pass recomputes exp (L2-hot) and writes
// AcTh[b][p][k] = fp16((max(e*sc, 1e-8) - 1e-8) * 1024), transposed via smem.
__global__ void __launch_bounds__(256) softmax_emit(const float* __restrict__ AcAll,
                                                    __half* __restrict__ AcThAll,
                                                    const float* __restrict__ mask_all) {
    __shared__ float redM[8][32];
    __shared__ float redS[8][32];
    __shared__ float se[32][33];
    int b = blockIdx.y;
    int t = threadIdx.x;
    int col = t & 31, part = t >> 5;
    int p0 = blockIdx.x * 32;
    int p = p0 + col;
    int n1 = g_cnt[b][0], n0 = g_cnt[b][1];
    int n1p = (n1 + 31) & ~31;
    const float* Ac = AcAll + (size_t)b * L * L;
    __half* AcTh = AcThAll + (size_t)b * L * KS;

    // online pass: running max + rescaled sum (masked rows contribute value 0 to max)
    float mx = 0.f, sm = 0.f;
    for (int k = part; k < n1; k += 8) {
        float v = Ac[(size_t)k * L + p];
        if (v > mx) { sm *= __expf(SCALE_F * (mx - v)); mx = v; }
        sm += __expf(SCALE_F * (v - mx));
    }
    redM[part][col] = mx;
    redS[part][col] = sm;
    __syncthreads();
    if (t < 32) {
        float gm = redM[0][t], gs = redS[0][t];
        for (int q = 1; q < 8; q++) {
            float m2 = redM[q][t], s2 = redS[q][t];
            if (m2 > gm) { gs *= __expf(SCALE_F * (gm - m2)); gm = m2; }
            gs += s2 * __expf(SCALE_F * (m2 - gm));
        }
        gs += (float)n0 * __expf(-SCALE_F * gm);   // masked rows (value 0)
        redM[0][t] = gm;
        redS[0][t] = gs;
    }
    __syncthreads();
    mx = redM[0][col];
    float sc = (1.0f / redS[0][col]) * mask_all[(size_t)b * L + p];
    __syncthreads();

    // emit pass: recompute exp, scale+floor-shift, transpose 32x32 tiles, fp16
    int kx = t & 31, py = t >> 5;
    for (int k0 = 0; k0 < n1p; k0 += 32) {
#pragma unroll
        for (int i = 0; i < 4; i++) {
            int k = k0 + part + 8 * i;
            float v = 0.f;
            if (k < n1) {
                float e = __expf(SCALE_F * (Ac[(size_t)k * L + p] - mx));
                float a = fmaxf(e * sc, 1e-8f);
                v = (a - 1e-8f) * ASCALE;
            }
            se[part + 8 * i][col] = v;
        }
        __syncthreads();
#pragma unroll
        for (int i = 0; i < 4; i++) {
            int pr = py + 8 * i;
            AcTh[(size_t)(p0 + pr) * KS + k0 + kx] = __float2half(se[kx][pr]);
        }
        __syncthreads();
    }
}

// ---------------------------------------------------------------------------
// generic HMMA fp16 NT GEMM, batched over z. CTA tile 128(m) x 128(p), BK=32,
// 8 warps of 32x64, 4-stage cp.async, 2 CTAs/SM (occupancy doubled vs r10).
// PASTE:  Out[z][m][p] = (1/1024)*sum_k A[m,k]*B[p,k] + cmT[z][m], nC from g_cnt
// !PASTE: Out[z][m][p] = sum_k A[m,k]*B[p,k], nC fixed
#define GSTAGES 4
#define ABYTES (128 * 64)          // 128 rows x 32 fp16
#define BBYTES (128 * 64)
#define STAGE_B (ABYTES + BBYTES)  // 16384
#define SMEM_GEMM (GSTAGES * STAGE_B)

__device__ __forceinline__ void cp_async16(uint32_t dst, const void* src) {
    asm volatile("cp.async.cg.shared.global [%0], [%1], 16;" :: "r"(dst), "l"(src) : "memory");
}
__device__ __forceinline__ void ldsm4(uint32_t& r0, uint32_t& r1, uint32_t& r2, uint32_t& r3,
                                      uint32_t a) {
    asm volatile("ldmatrix.sync.aligned.m8n8.x4.shared.b16 {%0,%1,%2,%3}, [%4];"
                 : "=r"(r0), "=r"(r1), "=r"(r2), "=r"(r3) : "r"(a));
}
__device__ __forceinline__ void mma16816(float* c, const uint32_t* a, uint32_t b0, uint32_t b1) {
    asm volatile(
        "mma.sync.aligned.m16n8k16.row.col.f32.f16.f16.f32 "
        "{%0,%1,%2,%3}, {%4,%5,%6,%7}, {%8,%9}, {%0,%1,%2,%3};"
        : "+f"(c[0]), "+f"(c[1]), "+f"(c[2]), "+f"(c[3])
        : "r"(a[0]), "r"(a[1]), "r"(a[2]), "r"(a[3]), "r"(b0), "r"(b1));
}

template<int KSTRIDE, bool PASTE>
__global__ void __launch_bounds__(256, 2) hmma_gemm(
        const __half* __restrict__ Aall, const __half* __restrict__ Ball,
        float* __restrict__ Outall,
        size_t aStride, size_t bStride, size_t oStride, int nCfix) {
    extern __shared__ __align__(16) char smem[];
    uint32_t sb = smem_u32(smem);
    int t = threadIdx.x;
    int lane = t & 31;
    int wr = (t >> 5) & 3;        // warp m-row (0..3): 32 rows each
    int wc = t >> 7;              // warp p-col (0..1): 64 cols each
    int m0 = blockIdx.x * 128;
    int p0 = blockIdx.y * 128;
    int z = blockIdx.z;
    int nC = PASTE ? (((g_cnt[z][0] + 31) & ~31) >> 5) : nCfix;

    const __half* Abase = Aall + z * aStride + (size_t)m0 * KSTRIDE;
    const __half* Bbase = Ball + z * bStride + (size_t)p0 * KSTRIDE;
    float* Out = Outall + z * oStride;

    auto load_chunk = [&](int kt, int s) {
        uint32_t stage = sb + s * STAGE_B;
        int k0 = kt * 32;
#pragma unroll
        for (int i = 0; i < 2; i++) {
            int e = t + i * 256;              // A: 512 chunks (128 rows x 4)
            int row = e >> 2, c = e & 3;
            uint32_t dst = stage + row * 64 + ((c ^ (row & 3)) << 4);
            cp_async16(dst, Abase + (size_t)row * KSTRIDE + k0 + c * 8);
        }
#pragma unroll
        for (int i = 0; i < 2; i++) {
            int e = t + i * 256;              // B: 512 chunks
            int row = e >> 2, c = e & 3;
            uint32_t dst = stage + ABYTES + row * 64 + ((c ^ (row & 3)) << 4);
            cp_async16(dst, Bbase + (size_t)row * KSTRIDE + k0 + c * 8);
        }
        asm volatile("cp.async.commit_group;" ::: "memory");
    };

#pragma unroll
    for (int s = 0; s < GSTAGES - 1; s++) {
        if (s < nC) load_chunk(s, s);
        else asm volatile("cp.async.commit_group;" ::: "memory");
    }

    float acc[2][8][4] = {};
    int r8 = lane & 7;
    int mat = lane >> 3;
    int rowSwz = r8 & 3;
    int rA = wr * 32 + r8 + (mat & 1) * 8;    // + mi*16
    int rB = wc * 64 + r8 + (mat & 1) * 8;    // + nj*16
    int chi = mat >> 1;

    for (int kt = 0; kt < nC; kt++) {
        asm volatile("cp.async.wait_group %0;" :: "n"(GSTAGES - 2) : "memory");
        __syncthreads();   // single barrier per iter
        uint32_t stage = sb + (kt % GSTAGES) * STAGE_B;

        if (kt + GSTAGES - 1 < nC) load_chunk(kt + GSTAGES - 1, (kt + GSTAGES - 1) % GSTAGES);
        else asm volatile("cp.async.commit_group;" ::: "memory");

#pragma unroll
        for (int ks = 0; ks < 2; ks++) {
            int kc = ks * 2 + chi;
            uint32_t a[2][4];
            uint32_t b[4][4];
#pragma unroll
            for (int mi = 0; mi < 2; mi++) {
                int row = rA + mi * 16;
                ldsm4(a[mi][0], a[mi][1], a[mi][2], a[mi][3],
                      stage + row * 64 + ((kc ^ rowSwz) << 4));
            }
#pragma unroll
            for (int nj = 0; nj < 4; nj++) {
                int row = rB + nj * 16;
                ldsm4(b[nj][0], b[nj][1], b[nj][2], b[nj][3],
                      stage + ABYTES + row * 64 + ((kc ^ rowSwz) << 4));
            }
#pragma unroll
            for (int mi = 0; mi < 2; mi++)
#pragma unroll
                for (int nj = 0; nj < 4; nj++) {
                    mma16816(acc[mi][nj * 2],     a[mi], b[nj][0], b[nj][2]);
                    mma16816(acc[mi][nj * 2 + 1], a[mi], b[nj][1], b[nj][3]);
                }
        }
    }

    const float inv = PASTE ? (1.0f / ASCALE) : 1.0f;
    int cr = lane >> 2, cc = (lane & 3) * 2;
#pragma unroll
    for (int mi = 0; mi < 2; mi++) {
        int mbase = m0 + wr * 32 + mi * 16;
        float c0a = PASTE ? g_cmT[z][mbase + cr] : 0.f;
        float c0b = PASTE ? g_cmT[z][mbase + cr + 8] : 0.f;
#pragma unroll
        for (int ni = 0; ni < 8; ni++) {
            int p = p0 + wc * 64 + ni * 8 + cc;
            float* z0 = &Out[(size_t)(mbase + cr) * L + p];
            float* z1 = &Out[(size_t)(mbase + cr + 8) * L + p];
            *(float2*)z0 = make_float2(acc[mi][ni][0] * inv + c0a, acc[mi][ni][1] * inv + c0a);
            *(float2*)z1 = make_float2(acc[mi][ni][2] * inv + c0b, acc[mi][ni][3] * inv + c0b);
        }
    }
}

// ---------------------------------------------------------------------------
// overlap-add: y[b,c,u,v] = 0.25 * sum over <=4 covering patches of Z
__global__ void scatter_kernel(const float* __restrict__ ZAll) {
    int idx = blockIdx.x * 256 + threadIdx.x;
    int b = blockIdx.y;
    int v = idx & 127, u = (idx >> 7) & 127, c = idx >> 14;
    const float* Z = ZAll + (size_t)b * M2 * L;
    float s = 0.f;
    int ky0 = (u + 1) & 1, kx0 = (v + 1) & 1;
#pragma unroll
    for (int a = 0; a < 2; a++) {
        int ky = ky0 + 2 * a;
        int i2 = u + 1 - ky;
        if (i2 < 0 || i2 > 126) continue;
        int pi = i2 >> 1;
#pragma unroll
        for (int q = 0; q < 2; q++) {
            int kx = kx0 + 2 * q;
            int j2 = v + 1 - kx;
            if (j2 < 0 || j2 > 126) continue;
            int pj = j2 >> 1;
            int m = c * 16 + ky * 4 + kx;
            s += Z[(size_t)m * L + pi * 64 + pj];
        }
    }
    g_y[b * (C1 * H1 * W1) + idx] = 0.25f * s;
}

// final 4-group dilated 3x3 convs (rates 1,2,4,8) + bias + relu, FFMA2 over oc-pairs
__global__ void __launch_bounds__(256) final_conv(const float* __restrict__ w,
                                                  const float* __restrict__ bias,
                                                  float* __restrict__ out) {
    __shared__ __align__(16) float sy[32 * 32];
    __shared__ __align__(16) float swp[9 * 16];
    int t = threadIdx.x;
    int tv = t & 15, tu = t >> 4;
    int tile = blockIdx.x;
    int u0 = (tile >> 3) * 16, v0 = (tile & 7) * 16;
    int bg = blockIdx.y;
    int b = bg >> 2, g = bg & 3;
    int r = 1 << g;
    int Wt = 16 + 2 * r;
    const float* yb = g_y + b * (C1 * H1 * W1);
    ull acc2[8] = {};
    for (int c = 0; c < C1; c++) {
        const float* yc = yb + c * (H1 * W1);
        for (int e = t; e < Wt * Wt; e += 256) {
            int lu = e / Wt, lv = e % Wt;
            int gu = u0 - r + lu, gv = v0 - r + lv;
            float val = 0.f;
            if ((unsigned)gu < 128u && (unsigned)gv < 128u) val = yc[gu * 128 + gv];
            sy[lu * Wt + lv] = val;
        }
        if (t < 144) {
            int oc = t / 9, tap = t % 9;
            swp[tap * 16 + (oc >> 1) * 2 + (oc & 1)] =
                w[((g * 16 + oc) * C1 + c) * 9 + tap];
        }
        __syncthreads();
#pragma unroll
        for (int kh = 0; kh < 3; kh++)
#pragma unroll
            for (int kw = 0; kw < 3; kw++) {
                int tap = kh * 3 + kw;
                ull vv = packf2(sy[(tu + kh * r) * Wt + (tv + kw * r)]);
                const ull* wp = (const ull*)&swp[tap * 16];
#pragma unroll
                for (int pr = 0; pr < 8; pr++)
                    acc2[pr] = ffma2(vv, wp[pr], acc2[pr]);
            }
        __syncthreads();
    }
    int u = u0 + tu, v = v0 + tv;
#pragma unroll
    for (int pr = 0; pr < 8; pr++) {
        union { ull u64; float2 f; } cv; cv.u64 = acc2[pr];
        int oc0 = pr * 2;
        float o0 = fmaxf(cv.f.x + bias[g * 16 + oc0], 0.f);
        float o1 = fmaxf(cv.f.y + bias[g * 16 + oc0 + 1], 0.f);
        out[((b * 64 + g * 16 + oc0) * 128 + u) * 128 + v] = o0;
        out[((b * 64 + g * 16 + oc0 + 1) * 128 + u) * 128 + v] = o1;
    }
}

// ---------------------------------------------------------------------------
extern "C" void kernel_launch(void* const* d_in, const int* in_sizes, int n_in,
                              void* d_out, int out_size) {
    (void)in_sizes; (void)n_in; (void)out_size;
    const float* x1       = (const float*)d_in[0];
    const float* x2       = (const float*)d_in[1];
    const float* mask     = (const float*)d_in[2];
    const float* mask_all = (const float*)d_in[3];
    const float* conv_w   = (const float*)d_in[4];
    const float* conv_b   = (const float*)d_in[5];
    float* out = (float*)d_out;

    cudaFuncSetAttribute(hmma_gemm<KS, true>,  cudaFuncAttributeMaxDynamicSharedMemorySize, SMEM_GEMM);
    cudaFuncSetAttribute(hmma_gemm<KX, false>, cudaFuncAttributeMaxDynamicSharedMemorySize, SMEM_GEMM);

    unsigned char* pA; cudaGetSymbolAddress((void**)&pA, g_poolA);
    unsigned char* pB; cudaGetSymbolAddress((void**)&pB, g_poolB);
    __half* d_X3a;  cudaGetSymbolAddress((void**)&d_X3a, g_X3a);
    __half* d_X3b;  cudaGetSymbolAddress((void**)&d_X3b, g_X3b);
    __half* d_Rch;  cudaGetSymbolAddress((void**)&d_Rch, g_Rch);

    float*  d_corr = (float*)pA;                       // phase 1 of poolA
    float*  d_Z    = (float*)pA;                       // phase 2 of poolA, first 128MB
    __half* d_AcTh = (__half*)(pA + 134217728);        // phase 2 of poolA, second 128MB
    float*  d_Ac   = (float*)pB;                       // poolB

    // fork-join stream (created per call; not destroyed)
    cudaStream_t s2;
    cudaStreamCreateWithFlags(&s2, cudaStreamNonBlocking);
    cudaEvent_t evA, evB;
    cudaEventCreateWithFlags(&evA, cudaEventDisableTiming);
    cudaEventCreateWithFlags(&evB, cudaEventDisableTiming);

    prep_kernel<<<dim3(16, Bn), 256>>>(x2, mask);                      // #1
    build_X3<<<dim3(16, Bn), 256>>>(x2);                               // #2
    invnorm_kernel<<<dim3(16, Bn), 256>>>();                           // #3
    // corr: M=N=4096, K=192 triples (4th launch -> ncu samples this)
    hmma_gemm<KX, false><<<dim3(32, 32, Bn), 256, SMEM_GEMM>>>(        // #4
        d_X3a, d_X3b, d_corr, (size_t)L * KX, (size_t)L * KX, (size_t)L * L, KX / 32);
    compact_kernel<<<Bn, 256>>>();                                     // #5

    // fork: build_Rc + cmT overlap scores/softmax on s2 (disjoint buffers)
    cudaEventRecord(evA, 0);
    cudaStreamWaitEvent(s2, evA, 0);
    build_Rc<<<dim3(16, M2, Bn), 256, 0, s2>>>(x1);
    cmT_kernel<<<dim3(M2, Bn), 256, 0, s2>>>(x1);
    cudaEventRecord(evB, s2);

    scores_kernel<<<dim3(16, L, Bn), 256>>>(d_corr, d_Ac, mask_all);   // corr dead after
    softmax_emit<<<dim3(128, Bn), 256>>>(d_Ac, d_AcTh, mask_all);      // Ac dead after

    // join, then paste: M=2048, N=4096, K=n1 (padded)
    cudaStreamWaitEvent(0, evB, 0);
    hmma_gemm<KS, true><<<dim3(16, 32, Bn), 256, SMEM_GEMM>>>(
        d_Rch, d_AcTh, d_Z, (size_t)M2 * KS, (size_t)L * KS, (size_t)M2 * L, 0);
    scatter_kernel<<<dim3(8192, Bn), 256>>>(d_Z);
    final_conv<<<dim3(64, 16), 256>>>(conv_w, conv_b, out);
}

// round 12
// speedup vs baseline: 4.9224x; 1.0691x over previous
#include <cuda_runtime.h>
#include <cuda_fp16.h>
#include <math.h>
#include <stdint.h>

#define Bn 4
#define C1 128
#define H1 128
#define W1 128
#define C2 64
#define L 4096      // H2*W2 patches / pixels
#define M2 2048     // C1*4*4 patch elements
#define KS 4096     // K stride for paste fp16 operands
#define KX 192      // K stride for corr fp16 triple operands (3*64)
#define SCALE_F 10.0f
#define ASCALE 1024.0f

typedef unsigned long long ull;

// ---- static device scratch, pooled & aliased (allocation-free rule) ----
// poolA: [phase 1] corr[Bn] fp32 (4 x 64MB)
//        [phase 2] Z[Bn] fp32 (4 x 32MB @ 0) + AcTh[Bn] fp16 (4 x 32MB @ 128MB)
// poolB: Ac[Bn] fp32 (4 x 64MB)
// g_Rch: dedicated (enables stream overlap with scores/softmax which use poolB)
__device__ __align__(1024) unsigned char g_poolA[268435456];
__device__ __align__(1024) unsigned char g_poolB[268435456];
__device__ __half g_Rch[Bn][(size_t)M2 * KS];      // 64 MB paste A fp16 [b][m][k]
__device__ __half g_X3a[Bn][(size_t)L * KX];       // 6.3 MB corr A triples (h,h,l)
__device__ __half g_X3b[Bn][(size_t)L * KX];       // 6.3 MB corr B triples (h,l,h)
__device__ float g_y[Bn * C1 * H1 * W1];           // 33.5 MB pasted images
__device__ float g_pix2[Bn][L];
__device__ float g_invnorm[Bn][L];
__device__ float g_mm[Bn][L];
__device__ int   g_idx1[Bn][L];
__device__ int   g_cnt[Bn][2];
__device__ float g_cmT[Bn][M2];

__device__ __forceinline__ ull ffma2(ull a, ull b, ull c) {
    asm("fma.rn.f32x2 %0, %1, %2, %0;" : "+l"(c) : "l"(a), "l"(b));
    return c;
}
__device__ __forceinline__ ull packf2(float v) {
    ull r;
    uint32_t u = __float_as_uint(v);
    asm("mov.b64 %0, {%1, %1};" : "=l"(r) : "r"(u));
    return r;
}
__device__ __forceinline__ uint32_t smem_u32(const void* p) {
    uint32_t a;
    asm("{ .reg .u64 t; cvta.to.shared.u64 t, %1; cvt.u32.u64 %0, t; }" : "=r"(a) : "l"(p));
    return a;
}

// ---------------------------------------------------------------------------
// fused: pix2 + mm, batched over blockIdx.y
__global__ void prep_kernel(const float* __restrict__ x2, const float* __restrict__ mask) {
    int b = blockIdx.y;
    int a = blockIdx.x * 256 + threadIdx.x;
    const float* x2b = x2 + (size_t)b * C2 * L;
    const float* maskb = mask + (size_t)b * H1 * W1;
    float s = 0.f;
#pragma unroll 16
    for (int c = 0; c < C2; c++) { float v = x2b[c * L + a]; s += v * v; }
    g_pix2[b][a] = s;

    int li = a >> 6, lj = a & 63;
    bool allzero = true;
#pragma unroll
    for (int ky = 0; ky < 4; ky++)
#pragma unroll
        for (int kx = 0; kx < 4; kx++) {
            int u = 2 * li - 1 + ky, v = 2 * lj - 1 + kx;
            if ((unsigned)u < (unsigned)H1 && (unsigned)v < (unsigned)W1) {
                if (maskb[u * W1 + v] != 0.f) allzero = false;
            }
        }
    g_mm[b][a] = allzero ? 1.f : 0.f;
}

__global__ void invnorm_kernel() {
    int b = blockIdx.y;
    int l = blockIdx.x * 256 + threadIdx.x;
    int li = l >> 6, lj = l & 63;
    float s = 0.f;
#pragma unroll
    for (int dy = -1; dy <= 1; dy++)
#pragma unroll
        for (int dx = -1; dx <= 1; dx++) {
            int i = li + dy, j = lj + dx;
            if ((unsigned)i < 64u && (unsigned)j < 64u) s += g_pix2[b][i * 64 + j];
        }
    g_invnorm[b][l] = 1.0f / fmaxf(sqrtf(s), 1e-4f);
}

__global__ void compact_kernel() {
    __shared__ int cnt1[256], off1[256];
    int b = blockIdx.x;
    int t = threadIdx.x;
    int c1 = 0;
    for (int i = 0; i < 16; i++)
        if (g_mm[b][t * 16 + i] > 0.5f) c1++;
    cnt1[t] = c1;
    __syncthreads();
    if (t == 0) {
        int s1 = 0;
        for (int i = 0; i < 256; i++) { off1[i] = s1; s1 += cnt1[i]; }
        g_cnt[b][0] = s1; g_cnt[b][1] = L - s1;
    }
    __syncthreads();
    int o1 = off1[t];
    for (int i = 0; i < 16; i++) {
        int l = t * 16 + i;
        if (g_mm[b][l] > 0.5f) g_idx1[b][o1++] = l;
    }
}

// ---------------------------------------------------------------------------
// corr operand build: per pixel m, per channel c:
// X3a[m][3c..] = (h,h,l), X3b[m][3c..] = (h,l,h)
__global__ void build_X3(const float* __restrict__ x2) {
    int b = blockIdx.y;
    int m = blockIdx.x * 256 + threadIdx.x;
    const float* x2b = x2 + (size_t)b * C2 * L;
    union { __half h[24]; uint4 v[3]; } ua, ub;
#pragma unroll
    for (int cc = 0; cc < 8; cc++) {
#pragma unroll
        for (int j = 0; j < 8; j++) {
            float val = x2b[(cc * 8 + j) * L + m];
            __half h = __float2half(val);
            __half lo = __float2half(val - __half2float(h));
            ua.h[j * 3] = h;  ua.h[j * 3 + 1] = h;  ua.h[j * 3 + 2] = lo;
            ub.h[j * 3] = h;  ub.h[j * 3 + 1] = lo; ub.h[j * 3 + 2] = h;
        }
        size_t off = (size_t)m * KX + cc * 24;
        uint4* pa = (uint4*)&g_X3a[b][off];
        uint4* pb = (uint4*)&g_X3b[b][off];
#pragma unroll
        for (int q = 0; q < 3; q++) { pa[q] = ua.v[q]; pb[q] = ub.v[q]; }
    }
}

// Rch[b][m][k] = fp16 of im2col(x1)[idx1[k]][m], zero-pad k in [n1, n1p)
__global__ void build_Rc(const float* __restrict__ x1) {
    int b = blockIdx.z;
    int k = blockIdx.x * 256 + threadIdx.x;
    int m = blockIdx.y;
    int n1 = g_cnt[b][0];
    int n1p = (n1 + 31) & ~31;
    if (k >= n1p) return;
    float val = 0.f;
    if (k < n1) {
        int l = g_idx1[b][k];
        int li = l >> 6, lj = l & 63;
        int c = m >> 4, ky = (m >> 2) & 3, kx = m & 3;
        int u = 2 * li - 1 + ky, v = 2 * lj - 1 + kx;
        if ((unsigned)u < 128u && (unsigned)v < 128u)
            val = x1[((size_t)b * C1 + c) * 16384 + u * 128 + v];
    }
    g_Rch[b][(size_t)m * KS + k] = __float2half(val);
}

// cmT[m] = 1e-8 * sum over ALL 4096 patches of R[l,m]  (block tree-reduce)
__global__ void cmT_kernel(const float* __restrict__ x1) {
    __shared__ float red[256];
    int m = blockIdx.x, b = blockIdx.y;
    int t = threadIdx.x;
    int c = m >> 4, ky = (m >> 2) & 3, kx = m & 3;
    const float* xc = x1 + ((size_t)b * C1 + c) * (H1 * W1);
    float s = 0.f;
    for (int l = t; l < L; l += 256) {
        int li = l >> 6, lj = l & 63;
        int u = 2 * li - 1 + ky, v = 2 * lj - 1 + kx;
        if ((unsigned)u < 128u && (unsigned)v < 128u) s += xc[u * W1 + v];
    }
    red[t] = s;
    __syncthreads();
    for (int st = 128; st > 0; st >>= 1) {
        if (t < st) red[t] += red[t + st];
        __syncthreads();
    }
    if (t == 0) g_cmT[b][m] = 1e-8f * red[0];
}

// scores for active rows, 4 k per block (adjacent l -> corr rows L1/L2-hot)
__global__ void scores_kernel(const float* __restrict__ corrAll,
                              float* __restrict__ AcAll,
                              const float* __restrict__ mask_all) {
    int b = blockIdx.z;
    int kg = blockIdx.y;               // k-group of 4
    int n1 = g_cnt[b][0];
    int p = blockIdx.x * 256 + threadIdx.x;
    int pi = p >> 6, pj = p & 63;
    const float* corr = corrAll + (size_t)b * L * L;
    float mav = mask_all[(size_t)b * L + p];
#pragma unroll
    for (int kk = 0; kk < 4; kk++) {
        int k = kg * 4 + kk;
        if (k >= n1) break;
        int l = g_idx1[b][k];
        int li = l >> 6, lj = l & 63;
        float s = 0.f;
#pragma unroll
        for (int dy = -1; dy <= 1; dy++)
#pragma unroll
            for (int dx = -1; dx <= 1; dx++) {
                if ((unsigned)(li + dy) < 64u && (unsigned)(lj + dx) < 64u &&
                    (unsigned)(pi + dy) < 64u && (unsigned)(pj + dx) < 64u) {
                    int o = dy * 64 + dx;
                    s += corr[(size_t)(l + o) * L + (p + o)];
                }
            }
        AcAll[(size_t)b * L * L + (size_t)k * L + p] = s * g_invnorm[b][l] * mav;
    }
}

// fused column softmax + transposed fp16 emit. Online max+sum (1 pass), then
// emit pass recomputes exp (L2-hot) and writes
// AcTh[b][p][k] = fp16((max(e*sc, 1e-8) - 1e-8) * 1024), transposed via smem.
__global__ void __launch_bounds__(256) softmax_emit(const float* __restrict__ AcAll,
                                                    __half* __restrict__ AcThAll,
                                                    const float* __restrict__ mask_all) {
    __shared__ float redM[8][32];
    __shared__ float redS[8][32];
    __shared__ float se[32][33];
    int b = blockIdx.y;
    int t = threadIdx.x;
    int col = t & 31, part = t >> 5;
    int p0 = blockIdx.x * 32;
    int p = p0 + col;
    int n1 = g_cnt[b][0], n0 = g_cnt[b][1];
    int n1p = (n1 + 31) & ~31;
    const float* Ac = AcAll + (size_t)b * L * L;
    __half* AcTh = AcThAll + (size_t)b * L * KS;

    // online pass: running max + rescaled sum (masked rows contribute value 0 to max)
    float mx = 0.f, sm = 0.f;
    for (int k = part; k < n1; k += 8) {
        float v = Ac[(size_t)k * L + p];
        if (v > mx) { sm *= __expf(SCALE_F * (mx - v)); mx = v; }
        sm += __expf(SCALE_F * (v - mx));
    }
    redM[part][col] = mx;
    redS[part][col] = sm;
    __syncthreads();
    if (t < 32) {
        float gm = redM[0][t], gs = redS[0][t];
        for (int q = 1; q < 8; q++) {
            float m2 = redM[q][t], s2 = redS[q][t];
            if (m2 > gm) { gs *= __expf(SCALE_F * (gm - m2)); gm = m2; }
            gs += s2 * __expf(SCALE_F * (m2 - gm));
        }
        gs += (float)n0 * __expf(-SCALE_F * gm);   // masked rows (value 0)
        redM[0][t] = gm;
        redS[0][t] = gs;
    }
    __syncthreads();
    mx = redM[0][col];
    float sc = (1.0f / redS[0][col]) * mask_all[(size_t)b * L + p];
    __syncthreads();

    // emit pass: recompute exp, scale+floor-shift, transpose 32x32 tiles, fp16
    int kx = t & 31, py = t >> 5;
    for (int k0 = 0; k0 < n1p; k0 += 32) {
#pragma unroll
        for (int i = 0; i < 4; i++) {
            int k = k0 + part + 8 * i;
            float v = 0.f;
            if (k < n1) {
                float e = __expf(SCALE_F * (Ac[(size_t)k * L + p] - mx));
                float a = fmaxf(e * sc, 1e-8f);
                v = (a - 1e-8f) * ASCALE;
            }
            se[part + 8 * i][col] = v;
        }
        __syncthreads();
#pragma unroll
        for (int i = 0; i < 4; i++) {
            int pr = py + 8 * i;
            AcTh[(size_t)(p0 + pr) * KS + k0 + kx] = __float2half(se[kx][pr]);
        }
        __syncthreads();
    }
}

// ---------------------------------------------------------------------------
// generic HMMA fp16 NT GEMM, batched over z. CTA tile 128(m) x 128(p), BK=32,
// 8 warps of 32x64, 6-stage cp.async, 2 CTAs/SM.
// PASTE:  Out[z][m][p] = (1/1024)*sum_k A[m,k]*B[p,k] + cmT[z][m], nC from g_cnt
// !PASTE: Out[z][m][p] = sum_k A[m,k]*B[p,k], nC fixed
#define GSTAGES 6
#define ABYTES (128 * 64)          // 128 rows x 32 fp16
#define BBYTES (128 * 64)
#define STAGE_B (ABYTES + BBYTES)  // 16384
#define SMEM_GEMM (GSTAGES * STAGE_B)

__device__ __forceinline__ void cp_async16(uint32_t dst, const void* src) {
    asm volatile("cp.async.cg.shared.global [%0], [%1], 16;" :: "r"(dst), "l"(src) : "memory");
}
__device__ __forceinline__ void ldsm4(uint32_t& r0, uint32_t& r1, uint32_t& r2, uint32_t& r3,
                                      uint32_t a) {
    asm volatile("ldmatrix.sync.aligned.m8n8.x4.shared.b16 {%0,%1,%2,%3}, [%4];"
                 : "=r"(r0), "=r"(r1), "=r"(r2), "=r"(r3) : "r"(a));
}
__device__ __forceinline__ void mma16816(float* c, const uint32_t* a, uint32_t b0, uint32_t b1) {
    asm volatile(
        "mma.sync.aligned.m16n8k16.row.col.f32.f16.f16.f32 "
        "{%0,%1,%2,%3}, {%4,%5,%6,%7}, {%8,%9}, {%0,%1,%2,%3};"
        : "+f"(c[0]), "+f"(c[1]), "+f"(c[2]), "+f"(c[3])
        : "r"(a[0]), "r"(a[1]), "r"(a[2]), "r"(a[3]), "r"(b0), "r"(b1));
}

template<int KSTRIDE, bool PASTE>
__global__ void __launch_bounds__(256, 2) hmma_gemm(
        const __half* __restrict__ Aall, const __half* __restrict__ Ball,
        float* __restrict__ Outall,
        size_t aStride, size_t bStride, size_t oStride, int nCfix) {
    extern __shared__ __align__(16) char smem[];
    uint32_t sb = smem_u32(smem);
    int t = threadIdx.x;
    int lane = t & 31;
    int wr = (t >> 5) & 3;        // warp m-row (0..3): 32 rows each
    int wc = t >> 7;              // warp p-col (0..1): 64 cols each
    int m0 = blockIdx.x * 128;
    int p0 = blockIdx.y * 128;
    int z = blockIdx.z;
    int nC = PASTE ? (((g_cnt[z][0] + 31) & ~31) >> 5) : nCfix;

    const __half* Abase = Aall + z * aStride + (size_t)m0 * KSTRIDE;
    const __half* Bbase = Ball + z * bStride + (size_t)p0 * KSTRIDE;
    float* Out = Outall + z * oStride;

    auto load_chunk = [&](int kt, int s) {
        uint32_t stage = sb + s * STAGE_B;
        int k0 = kt * 32;
#pragma unroll
        for (int i = 0; i < 2; i++) {
            int e = t + i * 256;              // A: 512 chunks (128 rows x 4)
            int row = e >> 2, c = e & 3;
            uint32_t dst = stage + row * 64 + ((c ^ (row & 3)) << 4);
            cp_async16(dst, Abase + (size_t)row * KSTRIDE + k0 + c * 8);
        }
#pragma unroll
        for (int i = 0; i < 2; i++) {
            int e = t + i * 256;              // B: 512 chunks
            int row = e >> 2, c = e & 3;
            uint32_t dst = stage + ABYTES + row * 64 + ((c ^ (row & 3)) << 4);
            cp_async16(dst, Bbase + (size_t)row * KSTRIDE + k0 + c * 8);
        }
        asm volatile("cp.async.commit_group;" ::: "memory");
    };

#pragma unroll
    for (int s = 0; s < GSTAGES - 1; s++) {
        if (s < nC) load_chunk(s, s);
        else asm volatile("cp.async.commit_group;" ::: "memory");
    }

    float acc[2][8][4] = {};
    int r8 = lane & 7;
    int mat = lane >> 3;
    int rowSwz = r8 & 3;
    int rA = wr * 32 + r8 + (mat & 1) * 8;    // + mi*16
    int rB = wc * 64 + r8 + (mat & 1) * 8;    // + nj*16
    int chi = mat >> 1;

    for (int kt = 0; kt < nC; kt++) {
        asm volatile("cp.async.wait_group %0;" :: "n"(GSTAGES - 2) : "memory");
        __syncthreads();   // single barrier per iter
        uint32_t stage = sb + (kt % GSTAGES) * STAGE_B;

        if (kt + GSTAGES - 1 < nC) load_chunk(kt + GSTAGES - 1, (kt + GSTAGES - 1) % GSTAGES);
        else asm volatile("cp.async.commit_group;" ::: "memory");

#pragma unroll
        for (int ks = 0; ks < 2; ks++) {
            int kc = ks * 2 + chi;
            uint32_t a[2][4];
            uint32_t b[4][4];
#pragma unroll
            for (int mi = 0; mi < 2; mi++) {
                int row = rA + mi * 16;
                ldsm4(a[mi][0], a[mi][1], a[mi][2], a[mi][3],
                      stage + row * 64 + ((kc ^ rowSwz) << 4));
            }
#pragma unroll
            for (int nj = 0; nj < 4; nj++) {
                int row = rB + nj * 16;
                ldsm4(b[nj][0], b[nj][1], b[nj][2], b[nj][3],
                      stage + ABYTES + row * 64 + ((kc ^ rowSwz) << 4));
            }
#pragma unroll
            for (int mi = 0; mi < 2; mi++)
#pragma unroll
                for (int nj = 0; nj < 4; nj++) {
                    mma16816(acc[mi][nj * 2],     a[mi], b[nj][0], b[nj][2]);
                    mma16816(acc[mi][nj * 2 + 1], a[mi], b[nj][1], b[nj][3]);
                }
        }
    }

    const float inv = PASTE ? (1.0f / ASCALE) : 1.0f;
    int cr = lane >> 2, cc = (lane & 3) * 2;
#pragma unroll
    for (int mi = 0; mi < 2; mi++) {
        int mbase = m0 + wr * 32 + mi * 16;
        float c0a = PASTE ? g_cmT[z][mbase + cr] : 0.f;
        float c0b = PASTE ? g_cmT[z][mbase + cr + 8] : 0.f;
#pragma unroll
        for (int ni = 0; ni < 8; ni++) {
            int p = p0 + wc * 64 + ni * 8 + cc;
            float* z0 = &Out[(size_t)(mbase + cr) * L + p];
            float* z1 = &Out[(size_t)(mbase + cr + 8) * L + p];
            *(float2*)z0 = make_float2(acc[mi][ni][0] * inv + c0a, acc[mi][ni][1] * inv + c0a);
            *(float2*)z1 = make_float2(acc[mi][ni][2] * inv + c0b, acc[mi][ni][3] * inv + c0b);
        }
    }
}

// ---------------------------------------------------------------------------
// overlap-add: y[b,c,u,v] = 0.25 * sum over <=4 covering patches of Z
__global__ void scatter_kernel(const float* __restrict__ ZAll) {
    int idx = blockIdx.x * 256 + threadIdx.x;
    int b = blockIdx.y;
    int v = idx & 127, u = (idx >> 7) & 127, c = idx >> 14;
    const float* Z = ZAll + (size_t)b * M2 * L;
    float s = 0.f;
    int ky0 = (u + 1) & 1, kx0 = (v + 1) & 1;
#pragma unroll
    for (int a = 0; a < 2; a++) {
        int ky = ky0 + 2 * a;
        int i2 = u + 1 - ky;
        if (i2 < 0 || i2 > 126) continue;
        int pi = i2 >> 1;
#pragma unroll
        for (int q = 0; q < 2; q++) {
            int kx = kx0 + 2 * q;
            int j2 = v + 1 - kx;
            if (j2 < 0 || j2 > 126) continue;
            int pj = j2 >> 1;
            int m = c * 16 + ky * 4 + kx;
            s += Z[(size_t)m * L + pi * 64 + pj];
        }
    }
    g_y[b * (C1 * H1 * W1) + idx] = 0.25f * s;
}

// final 4-group dilated 3x3 convs (rates 1,2,4,8) + bias + relu, FFMA2 over oc-pairs
__global__ void __launch_bounds__(256) final_conv(const float* __restrict__ w,
                                                  const float* __restrict__ bias,
                                                  float* __restrict__ out) {
    __shared__ __align__(16) float sy[32 * 32];
    __shared__ __align__(16) float swp[9 * 16];
    int t = threadIdx.x;
    int tv = t & 15, tu = t >> 4;
    int tile = blockIdx.x;
    int u0 = (tile >> 3) * 16, v0 = (tile & 7) * 16;
    int bg = blockIdx.y;
    int b = bg >> 2, g = bg & 3;
    int r = 1 << g;
    int Wt = 16 + 2 * r;
    const float* yb = g_y + b * (C1 * H1 * W1);
    ull acc2[8] = {};
    for (int c = 0; c < C1; c++) {
        const float* yc = yb + c * (H1 * W1);
        for (int e = t; e < Wt * Wt; e += 256) {
            int lu = e / Wt, lv = e % Wt;
            int gu = u0 - r + lu, gv = v0 - r + lv;
            float val = 0.f;
            if ((unsigned)gu < 128u && (unsigned)gv < 128u) val = yc[gu * 128 + gv];
            sy[lu * Wt + lv] = val;
        }
        if (t < 144) {
            int oc = t / 9, tap = t % 9;
            swp[tap * 16 + (oc >> 1) * 2 + (oc & 1)] =
                w[((g * 16 + oc) * C1 + c) * 9 + tap];
        }
        __syncthreads();
#pragma unroll
        for (int kh = 0; kh < 3; kh++)
#pragma unroll
            for (int kw = 0; kw < 3; kw++) {
                int tap = kh * 3 + kw;
                ull vv = packf2(sy[(tu + kh * r) * Wt + (tv + kw * r)]);
                const ull* wp = (const ull*)&swp[tap * 16];
#pragma unroll
                for (int pr = 0; pr < 8; pr++)
                    acc2[pr] = ffma2(vv, wp[pr], acc2[pr]);
            }
        __syncthreads();
    }
    int u = u0 + tu, v = v0 + tv;
#pragma unroll
    for (int pr = 0; pr < 8; pr++) {
        union { ull u64; float2 f; } cv; cv.u64 = acc2[pr];
        int oc0 = pr * 2;
        float o0 = fmaxf(cv.f.x + bias[g * 16 + oc0], 0.f);
        float o1 = fmaxf(cv.f.y + bias[g * 16 + oc0 + 1], 0.f);
        out[((b * 64 + g * 16 + oc0) * 128 + u) * 128 + v] = o0;
        out[((b * 64 + g * 16 + oc0 + 1) * 128 + u) * 128 + v] = o1;
    }
}

// ---------------------------------------------------------------------------
extern "C" void kernel_launch(void* const* d_in, const int* in_sizes, int n_in,
                              void* d_out, int out_size) {
    (void)in_sizes; (void)n_in; (void)out_size;
    const float* x1       = (const float*)d_in[0];
    const float* x2       = (const float*)d_in[1];
    const float* mask     = (const float*)d_in[2];
    const float* mask_all = (const float*)d_in[3];
    const float* conv_w   = (const float*)d_in[4];
    const float* conv_b   = (const float*)d_in[5];
    float* out = (float*)d_out;

    cudaFuncSetAttribute(hmma_gemm<KS, true>,  cudaFuncAttributeMaxDynamicSharedMemorySize, SMEM_GEMM);
    cudaFuncSetAttribute(hmma_gemm<KX, false>, cudaFuncAttributeMaxDynamicSharedMemorySize, SMEM_GEMM);

    unsigned char* pA; cudaGetSymbolAddress((void**)&pA, g_poolA);
    unsigned char* pB; cudaGetSymbolAddress((void**)&pB, g_poolB);
    __half* d_X3a;  cudaGetSymbolAddress((void**)&d_X3a, g_X3a);
    __half* d_X3b;  cudaGetSymbolAddress((void**)&d_X3b, g_X3b);
    __half* d_Rch;  cudaGetSymbolAddress((void**)&d_Rch, g_Rch);

    float*  d_corr = (float*)pA;                       // phase 1 of poolA
    float*  d_Z    = (float*)pA;                       // phase 2 of poolA, first 128MB
    __half* d_AcTh = (__half*)(pA + 134217728);        // phase 2 of poolA, second 128MB
    float*  d_Ac   = (float*)pB;                       // poolB

    // fork-join stream (created per call; not destroyed)
    cudaStream_t s2;
    cudaStreamCreateWithFlags(&s2, cudaStreamNonBlocking);
    cudaEvent_t evA, evB;
    cudaEventCreateWithFlags(&evA, cudaEventDisableTiming);
    cudaEventCreateWithFlags(&evB, cudaEventDisableTiming);

    prep_kernel<<<dim3(16, Bn), 256>>>(x2, mask);                      // #1
    build_X3<<<dim3(16, Bn), 256>>>(x2);                               // #2
    invnorm_kernel<<<dim3(16, Bn), 256>>>();                           // #3
    // corr: M=N=4096, K=192 triples (4th launch -> ncu samples this)
    hmma_gemm<KX, false><<<dim3(32, 32, Bn), 256, SMEM_GEMM>>>(        // #4
        d_X3a, d_X3b, d_corr, (size_t)L * KX, (size_t)L * KX, (size_t)L * L, KX / 32);
    compact_kernel<<<Bn, 256>>>();                                     // #5

    // fork: build_Rc + cmT overlap scores/softmax on s2 (disjoint buffers)
    cudaEventRecord(evA, 0);
    cudaStreamWaitEvent(s2, evA, 0);
    build_Rc<<<dim3(16, M2, Bn), 256, 0, s2>>>(x1);
    cmT_kernel<<<dim3(M2, Bn), 256, 0, s2>>>(x1);
    cudaEventRecord(evB, s2);

    scores_kernel<<<dim3(16, 1024, Bn), 256>>>(d_corr, d_Ac, mask_all); // corr dead after
    softmax_emit<<<dim3(128, Bn), 256>>>(d_Ac, d_AcTh, mask_all);       // Ac dead after

    // join, then paste: M=2048, N=4096, K=n1 (padded)
    cudaStreamWaitEvent(0, evB, 0);
    hmma_gemm<KS, true><<<dim3(16, 32, Bn), 256, SMEM_GEMM>>>(
        d_Rch, d_AcTh, d_Z, (size_t)M2 * KS, (size_t)L * KS, (size_t)M2 * L, 0);
    scatter_kernel<<<dim3(8192, Bn), 256>>>(d_Z);
    final_conv<<<dim3(64, 16), 256>>>(conv_w, conv_b, out);
}

// round 13
// speedup vs baseline: 5.0412x; 1.0241x over previous
#include <cuda_runtime.h>
#include <cuda_fp16.h>
#include <math.h>
#include <stdint.h>

#define Bn 4
#define C1 128
#define H1 128
#define W1 128
#define C2 64
#define L 4096      // H2*W2 patches / pixels
#define M2 2048     // C1*4*4 patch elements
#define KS 4096     // K stride for paste fp16 operands
#define KX 192      // K stride for corr fp16 triple operands (3*64)
#define SCALE_F 10.0f
#define ASCALE 1024.0f

typedef unsigned long long ull;

// ---- static device scratch, pooled & aliased (allocation-free rule) ----
// poolA: [phase 1] corr[Bn] fp32 (4 x 64MB)
//        [phase 2] Z[Bn] fp32 (4 x 32MB @ 0) + AcTh[Bn] fp16 (4 x 32MB @ 128MB)
// poolB: Ac[Bn] fp32 (4 x 64MB)
// g_Rch: dedicated (enables stream overlap with scores/softmax which use poolB)
__device__ __align__(1024) unsigned char g_poolA[268435456];
__device__ __align__(1024) unsigned char g_poolB[268435456];
__device__ __half g_Rch[Bn][(size_t)M2 * KS];      // 64 MB paste A fp16 [b][m][k]
__device__ __half g_X3a[Bn][(size_t)L * KX];       // 6.3 MB corr A triples (h,h,l)
__device__ __half g_X3b[Bn][(size_t)L * KX];       // 6.3 MB corr B triples (h,l,h)
__device__ float g_y[Bn * C1 * H1 * W1];           // 33.5 MB pasted images
__device__ float g_pix2[Bn][L];
__device__ float g_invnorm[Bn][L];
__device__ float g_mm[Bn][L];
__device__ int   g_idx1[Bn][L];
__device__ int   g_cnt[Bn][2];
__device__ float g_cmT[Bn][M2];

__device__ __forceinline__ ull ffma2(ull a, ull b, ull c) {
    asm("fma.rn.f32x2 %0, %1, %2, %0;" : "+l"(c) : "l"(a), "l"(b));
    return c;
}
__device__ __forceinline__ ull packf2(float v) {
    ull r;
    uint32_t u = __float_as_uint(v);
    asm("mov.b64 %0, {%1, %1};" : "=l"(r) : "r"(u));
    return r;
}
__device__ __forceinline__ uint32_t smem_u32(const void* p) {
    uint32_t a;
    asm("{ .reg .u64 t; cvta.to.shared.u64 t, %1; cvt.u32.u64 %0, t; }" : "=r"(a) : "l"(p));
    return a;
}

// ---------------------------------------------------------------------------
// fused: pix2 + mm, batched over blockIdx.y
__global__ void prep_kernel(const float* __restrict__ x2, const float* __restrict__ mask) {
    int b = blockIdx.y;
    int a = blockIdx.x * 256 + threadIdx.x;
    const float* x2b = x2 + (size_t)b * C2 * L;
    const float* maskb = mask + (size_t)b * H1 * W1;
    float s = 0.f;
#pragma unroll 16
    for (int c = 0; c < C2; c++) { float v = x2b[c * L + a]; s += v * v; }
    g_pix2[b][a] = s;

    int li = a >> 6, lj = a & 63;
    bool allzero = true;
#pragma unroll
    for (int ky = 0; ky < 4; ky++)
#pragma unroll
        for (int kx = 0; kx < 4; kx++) {
            int u = 2 * li - 1 + ky, v = 2 * lj - 1 + kx;
            if ((unsigned)u < (unsigned)H1 && (unsigned)v < (unsigned)W1) {
                if (maskb[u * W1 + v] != 0.f) allzero = false;
            }
        }
    g_mm[b][a] = allzero ? 1.f : 0.f;
}

__global__ void invnorm_kernel() {
    int b = blockIdx.y;
    int l = blockIdx.x * 256 + threadIdx.x;
    int li = l >> 6, lj = l & 63;
    float s = 0.f;
#pragma unroll
    for (int dy = -1; dy <= 1; dy++)
#pragma unroll
        for (int dx = -1; dx <= 1; dx++) {
            int i = li + dy, j = lj + dx;
            if ((unsigned)i < 64u && (unsigned)j < 64u) s += g_pix2[b][i * 64 + j];
        }
    g_invnorm[b][l] = 1.0f / fmaxf(sqrtf(s), 1e-4f);
}

__global__ void compact_kernel() {
    __shared__ int cnt1[256], off1[256];
    int b = blockIdx.x;
    int t = threadIdx.x;
    int c1 = 0;
    for (int i = 0; i < 16; i++)
        if (g_mm[b][t * 16 + i] > 0.5f) c1++;
    cnt1[t] = c1;
    __syncthreads();
    if (t == 0) {
        int s1 = 0;
        for (int i = 0; i < 256; i++) { off1[i] = s1; s1 += cnt1[i]; }
        g_cnt[b][0] = s1; g_cnt[b][1] = L - s1;
    }
    __syncthreads();
    int o1 = off1[t];
    for (int i = 0; i < 16; i++) {
        int l = t * 16 + i;
        if (g_mm[b][l] > 0.5f) g_idx1[b][o1++] = l;
    }
}

// ---------------------------------------------------------------------------
// corr operand build: per pixel m, per channel c:
// X3a[m][3c..] = (h,h,l), X3b[m][3c..] = (h,l,h)
__global__ void build_X3(const float* __restrict__ x2) {
    int b = blockIdx.y;
    int m = blockIdx.x * 256 + threadIdx.x;
    const float* x2b = x2 + (size_t)b * C2 * L;
    union { __half h[24]; uint4 v[3]; } ua, ub;
#pragma unroll
    for (int cc = 0; cc < 8; cc++) {
#pragma unroll
        for (int j = 0; j < 8; j++) {
            float val = x2b[(cc * 8 + j) * L + m];
            __half h = __float2half(val);
            __half lo = __float2half(val - __half2float(h));
            ua.h[j * 3] = h;  ua.h[j * 3 + 1] = h;  ua.h[j * 3 + 2] = lo;
            ub.h[j * 3] = h;  ub.h[j * 3 + 1] = lo; ub.h[j * 3 + 2] = h;
        }
        size_t off = (size_t)m * KX + cc * 24;
        uint4* pa = (uint4*)&g_X3a[b][off];
        uint4* pb = (uint4*)&g_X3b[b][off];
#pragma unroll
        for (int q = 0; q < 3; q++) { pa[q] = ua.v[q]; pb[q] = ub.v[q]; }
    }
}

// Rch[b][m][k] = fp16 of im2col(x1)[idx1[k]][m], zero-pad k in [n1, n1p)
__global__ void build_Rc(const float* __restrict__ x1) {
    int b = blockIdx.z;
    int k = blockIdx.x * 256 + threadIdx.x;
    int m = blockIdx.y;
    int n1 = g_cnt[b][0];
    int n1p = (n1 + 31) & ~31;
    if (k >= n1p) return;
    float val = 0.f;
    if (k < n1) {
        int l = g_idx1[b][k];
        int li = l >> 6, lj = l & 63;
        int c = m >> 4, ky = (m >> 2) & 3, kx = m & 3;
        int u = 2 * li - 1 + ky, v = 2 * lj - 1 + kx;
        if ((unsigned)u < 128u && (unsigned)v < 128u)
            val = x1[((size_t)b * C1 + c) * 16384 + u * 128 + v];
    }
    g_Rch[b][(size_t)m * KS + k] = __float2half(val);
}

// cmT[m] = 1e-8 * sum over ALL 4096 patches of R[l,m]  (block tree-reduce)
__global__ void cmT_kernel(const float* __restrict__ x1) {
    __shared__ float red[256];
    int m = blockIdx.x, b = blockIdx.y;
    int t = threadIdx.x;
    int c = m >> 4, ky = (m >> 2) & 3, kx = m & 3;
    const float* xc = x1 + ((size_t)b * C1 + c) * (H1 * W1);
    float s = 0.f;
    for (int l = t; l < L; l += 256) {
        int li = l >> 6, lj = l & 63;
        int u = 2 * li - 1 + ky, v = 2 * lj - 1 + kx;
        if ((unsigned)u < 128u && (unsigned)v < 128u) s += xc[u * W1 + v];
    }
    red[t] = s;
    __syncthreads();
    for (int st = 128; st > 0; st >>= 1) {
        if (t < st) red[t] += red[t + st];
        __syncthreads();
    }
    if (t == 0) g_cmT[b][m] = 1e-8f * red[0];
}

// scores for active rows, 4 k per block (adjacent l -> corr rows L1/L2-hot)
__global__ void scores_kernel(const float* __restrict__ corrAll,
                              float* __restrict__ AcAll,
                              const float* __restrict__ mask_all) {
    int b = blockIdx.z;
    int kg = blockIdx.y;               // k-group of 4
    int n1 = g_cnt[b][0];
    int p = blockIdx.x * 256 + threadIdx.x;
    int pi = p >> 6, pj = p & 63;
    const float* corr = corrAll + (size_t)b * L * L;
    float mav = mask_all[(size_t)b * L + p];
#pragma unroll
    for (int kk = 0; kk < 4; kk++) {
        int k = kg * 4 + kk;
        if (k >= n1) break;
        int l = g_idx1[b][k];
        int li = l >> 6, lj = l & 63;
        float s = 0.f;
#pragma unroll
        for (int dy = -1; dy <= 1; dy++)
#pragma unroll
            for (int dx = -1; dx <= 1; dx++) {
                if ((unsigned)(li + dy) < 64u && (unsigned)(lj + dx) < 64u &&
                    (unsigned)(pi + dy) < 64u && (unsigned)(pj + dx) < 64u) {
                    int o = dy * 64 + dx;
                    s += corr[(size_t)(l + o) * L + (p + o)];
                }
            }
        AcAll[(size_t)b * L * L + (size_t)k * L + p] = s * g_invnorm[b][l] * mav;
    }
}

// fused column softmax + transposed fp16 emit. Online max+sum (1 pass), then
// emit pass recomputes exp (L2-hot) and writes
// AcTh[b][p][k] = fp16((max(e*sc, 1e-8) - 1e-8) * 1024), transposed via smem.
__global__ void __launch_bounds__(256) softmax_emit(const float* __restrict__ AcAll,
                                                    __half* __restrict__ AcThAll,
                                                    const float* __restrict__ mask_all) {
    __shared__ float redM[8][32];
    __shared__ float redS[8][32];
    __shared__ float se[32][33];
    int b = blockIdx.y;
    int t = threadIdx.x;
    int col = t & 31, part = t >> 5;
    int p0 = blockIdx.x * 32;
    int p = p0 + col;
    int n1 = g_cnt[b][0], n0 = g_cnt[b][1];
    int n1p = (n1 + 31) & ~31;
    const float* Ac = AcAll + (size_t)b * L * L;
    __half* AcTh = AcThAll + (size_t)b * L * KS;

    // online pass: running max + rescaled sum (masked rows contribute value 0 to max)
    float mx = 0.f, sm = 0.f;
    for (int k = part; k < n1; k += 8) {
        float v = Ac[(size_t)k * L + p];
        if (v > mx) { sm *= __expf(SCALE_F * (mx - v)); mx = v; }
        sm += __expf(SCALE_F * (v - mx));
    }
    redM[part][col] = mx;
    redS[part][col] = sm;
    __syncthreads();
    if (t < 32) {
        float gm = redM[0][t], gs = redS[0][t];
        for (int q = 1; q < 8; q++) {
            float m2 = redM[q][t], s2 = redS[q][t];
            if (m2 > gm) { gs *= __expf(SCALE_F * (gm - m2)); gm = m2; }
            gs += s2 * __expf(SCALE_F * (m2 - gm));
        }
        gs += (float)n0 * __expf(-SCALE_F * gm);   // masked rows (value 0)
        redM[0][t] = gm;
        redS[0][t] = gs;
    }
    __syncthreads();
    mx = redM[0][col];
    float sc = (1.0f / redS[0][col]) * mask_all[(size_t)b * L + p];
    __syncthreads();

    // emit pass: recompute exp, scale+floor-shift, transpose 32x32 tiles, fp16
    int kx = t & 31, py = t >> 5;
    for (int k0 = 0; k0 < n1p; k0 += 32) {
#pragma unroll
        for (int i = 0; i < 4; i++) {
            int k = k0 + part + 8 * i;
            float v = 0.f;
            if (k < n1) {
                float e = __expf(SCALE_F * (Ac[(size_t)k * L + p] - mx));
                float a = fmaxf(e * sc, 1e-8f);
                v = (a - 1e-8f) * ASCALE;
            }
            se[part + 8 * i][col] = v;
        }
        __syncthreads();
#pragma unroll
        for (int i = 0; i < 4; i++) {
            int pr = py + 8 * i;
            AcTh[(size_t)(p0 + pr) * KS + k0 + kx] = __float2half(se[kx][pr]);
        }
        __syncthreads();
    }
}

// ---------------------------------------------------------------------------
// generic HMMA fp16 NT GEMM, batched over z. CTA = 128 threads / 4 warps in a
// 2x2 grid of 64x64 warp tiles -> CTA tile 128(m) x 128(p), BK=32, 4-stage
// cp.async, 3 CTAs/SM (12 warps). 64x64 warp tile: ldsm bytes/mma 1.5x lower
// than 32x64 (the L1-crossbar was the measured bottleneck).
#define GSTAGES 4
#define ABYTES (128 * 64)          // 128 rows x 32 fp16
#define BBYTES (128 * 64)
#define STAGE_B (ABYTES + BBYTES)  // 16384
#define SMEM_GEMM (GSTAGES * STAGE_B)

__device__ __forceinline__ void cp_async16(uint32_t dst, const void* src) {
    asm volatile("cp.async.cg.shared.global [%0], [%1], 16;" :: "r"(dst), "l"(src) : "memory");
}
__device__ __forceinline__ void ldsm4(uint32_t& r0, uint32_t& r1, uint32_t& r2, uint32_t& r3,
                                      uint32_t a) {
    asm volatile("ldmatrix.sync.aligned.m8n8.x4.shared.b16 {%0,%1,%2,%3}, [%4];"
                 : "=r"(r0), "=r"(r1), "=r"(r2), "=r"(r3) : "r"(a));
}
__device__ __forceinline__ void mma16816(float* c, const uint32_t* a, uint32_t b0, uint32_t b1) {
    asm volatile(
        "mma.sync.aligned.m16n8k16.row.col.f32.f16.f16.f32 "
        "{%0,%1,%2,%3}, {%4,%5,%6,%7}, {%8,%9}, {%0,%1,%2,%3};"
        : "+f"(c[0]), "+f"(c[1]), "+f"(c[2]), "+f"(c[3])
        : "r"(a[0]), "r"(a[1]), "r"(a[2]), "r"(a[3]), "r"(b0), "r"(b1));
}

template<int KSTRIDE, bool PASTE>
__global__ void __launch_bounds__(128, 3) hmma_gemm(
        const __half* __restrict__ Aall, const __half* __restrict__ Ball,
        float* __restrict__ Outall,
        size_t aStride, size_t bStride, size_t oStride, int nCfix) {
    extern __shared__ __align__(16) char smem[];
    uint32_t sb = smem_u32(smem);
    int t = threadIdx.x;
    int lane = t & 31;
    int wid = t >> 5;
    int wr = wid & 1;             // warp m-row (0..1): 64 rows each
    int wc = wid >> 1;            // warp p-col (0..1): 64 cols each
    int m0 = blockIdx.x * 128;
    int p0 = blockIdx.y * 128;
    int z = blockIdx.z;
    int nC = PASTE ? (((g_cnt[z][0] + 31) & ~31) >> 5) : nCfix;

    const __half* Abase = Aall + z * aStride + (size_t)m0 * KSTRIDE;
    const __half* Bbase = Ball + z * bStride + (size_t)p0 * KSTRIDE;
    float* Out = Outall + z * oStride;

    auto load_chunk = [&](int kt, int s) {
        uint32_t stage = sb + s * STAGE_B;
        int k0 = kt * 32;
#pragma unroll
        for (int i = 0; i < 4; i++) {
            int e = t + i * 128;              // A: 512 chunks (128 rows x 4)
            int row = e >> 2, c = e & 3;
            uint32_t dst = stage + row * 64 + ((c ^ (row & 3)) << 4);
            cp_async16(dst, Abase + (size_t)row * KSTRIDE + k0 + c * 8);
        }
#pragma unroll
        for (int i = 0; i < 4; i++) {
            int e = t + i * 128;              // B: 512 chunks
            int row = e >> 2, c = e & 3;
            uint32_t dst = stage + ABYTES + row * 64 + ((c ^ (row & 3)) << 4);
            cp_async16(dst, Bbase + (size_t)row * KSTRIDE + k0 + c * 8);
        }
        asm volatile("cp.async.commit_group;" ::: "memory");
    };

#pragma unroll
    for (int s = 0; s < GSTAGES - 1; s++) {
        if (s < nC) load_chunk(s, s);
        else asm volatile("cp.async.commit_group;" ::: "memory");
    }

    float acc[4][8][4] = {};
    int r8 = lane & 7;
    int mat = lane >> 3;
    int rowSwz = r8 & 3;
    int rA = wr * 64 + r8 + (mat & 1) * 8;    // + mi*16
    int rB = wc * 64 + r8 + (mat & 1) * 8;    // + nj*16
    int chi = mat >> 1;

    for (int kt = 0; kt < nC; kt++) {
        asm volatile("cp.async.wait_group %0;" :: "n"(GSTAGES - 2) : "memory");
        __syncthreads();   // single barrier per iter
        uint32_t stage = sb + (kt % GSTAGES) * STAGE_B;

        if (kt + GSTAGES - 1 < nC) load_chunk(kt + GSTAGES - 1, (kt + GSTAGES - 1) % GSTAGES);
        else asm volatile("cp.async.commit_group;" ::: "memory");

#pragma unroll
        for (int ks = 0; ks < 2; ks++) {
            int kc = ks * 2 + chi;
            uint32_t a[4][4];
            uint32_t b[4][4];
#pragma unroll
            for (int mi = 0; mi < 4; mi++) {
                int row = rA + mi * 16;
                ldsm4(a[mi][0], a[mi][1], a[mi][2], a[mi][3],
                      stage + row * 64 + ((kc ^ rowSwz) << 4));
            }
#pragma unroll
            for (int nj = 0; nj < 4; nj++) {
                int row = rB + nj * 16;
                ldsm4(b[nj][0], b[nj][1], b[nj][2], b[nj][3],
                      stage + ABYTES + row * 64 + ((kc ^ rowSwz) << 4));
            }
#pragma unroll
            for (int mi = 0; mi < 4; mi++)
#pragma unroll
                for (int nj = 0; nj < 4; nj++) {
                    mma16816(acc[mi][nj * 2],     a[mi], b[nj][0], b[nj][2]);
                    mma16816(acc[mi][nj * 2 + 1], a[mi], b[nj][1], b[nj][3]);
                }
        }
    }

    const float inv = PASTE ? (1.0f / ASCALE) : 1.0f;
    int cr = lane >> 2, cc = (lane & 3) * 2;
#pragma unroll
    for (int mi = 0; mi < 4; mi++) {
        int mbase = m0 + wr * 64 + mi * 16;
        float c0a = PASTE ? g_cmT[z][mbase + cr] : 0.f;
        float c0b = PASTE ? g_cmT[z][mbase + cr + 8] : 0.f;
#pragma unroll
        for (int ni = 0; ni < 8; ni++) {
            int p = p0 + wc * 64 + ni * 8 + cc;
            float* z0 = &Out[(size_t)(mbase + cr) * L + p];
            float* z1 = &Out[(size_t)(mbase + cr + 8) * L + p];
            *(float2*)z0 = make_float2(acc[mi][ni][0] * inv + c0a, acc[mi][ni][1] * inv + c0a);
            *(float2*)z1 = make_float2(acc[mi][ni][2] * inv + c0b, acc[mi][ni][3] * inv + c0b);
        }
    }
}

// ---------------------------------------------------------------------------
// overlap-add: y[b,c,u,v] = 0.25 * sum over <=4 covering patches of Z
__global__ void scatter_kernel(const float* __restrict__ ZAll) {
    int idx = blockIdx.x * 256 + threadIdx.x;
    int b = blockIdx.y;
    int v = idx & 127, u = (idx >> 7) & 127, c = idx >> 14;
    const float* Z = ZAll + (size_t)b * M2 * L;
    float s = 0.f;
    int ky0 = (u + 1) & 1, kx0 = (v + 1) & 1;
#pragma unroll
    for (int a = 0; a < 2; a++) {
        int ky = ky0 + 2 * a;
        int i2 = u + 1 - ky;
        if (i2 < 0 || i2 > 126) continue;
        int pi = i2 >> 1;
#pragma unroll
        for (int q = 0; q < 2; q++) {
            int kx = kx0 + 2 * q;
            int j2 = v + 1 - kx;
            if (j2 < 0 || j2 > 126) continue;
            int pj = j2 >> 1;
            int m = c * 16 + ky * 4 + kx;
            s += Z[(size_t)m * L + pi * 64 + pj];
        }
    }
    g_y[b * (C1 * H1 * W1) + idx] = 0.25f * s;
}

// final 4-group dilated 3x3 convs (rates 1,2,4,8) + bias + relu, FFMA2 over oc-pairs
__global__ void __launch_bounds__(256) final_conv(const float* __restrict__ w,
                                                  const float* __restrict__ bias,
                                                  float* __restrict__ out) {
    __shared__ __align__(16) float sy[32 * 32];
    __shared__ __align__(16) float swp[9 * 16];
    int t = threadIdx.x;
    int tv = t & 15, tu = t >> 4;
    int tile = blockIdx.x;
    int u0 = (tile >> 3) * 16, v0 = (tile & 7) * 16;
    int bg = blockIdx.y;
    int b = bg >> 2, g = bg & 3;
    int r = 1 << g;
    int Wt = 16 + 2 * r;
    const float* yb = g_y + b * (C1 * H1 * W1);
    ull acc2[8] = {};
    for (int c = 0; c < C1; c++) {
        const float* yc = yb + c * (H1 * W1);
        for (int e = t; e < Wt * Wt; e += 256) {
            int lu = e / Wt, lv = e % Wt;
            int gu = u0 - r + lu, gv = v0 - r + lv;
            float val = 0.f;
            if ((unsigned)gu < 128u && (unsigned)gv < 128u) val = yc[gu * 128 + gv];
            sy[lu * Wt + lv] = val;
        }
        if (t < 144) {
            int oc = t / 9, tap = t % 9;
            swp[tap * 16 + (oc >> 1) * 2 + (oc & 1)] =
                w[((g * 16 + oc) * C1 + c) * 9 + tap];
        }
        __syncthreads();
#pragma unroll
        for (int kh = 0; kh < 3; kh++)
#pragma unroll
            for (int kw = 0; kw < 3; kw++) {
                int tap = kh * 3 + kw;
                ull vv = packf2(sy[(tu + kh * r) * Wt + (tv + kw * r)]);
                const ull* wp = (const ull*)&swp[tap * 16];
#pragma unroll
                for (int pr = 0; pr < 8; pr++)
                    acc2[pr] = ffma2(vv, wp[pr], acc2[pr]);
            }
        __syncthreads();
    }
    int u = u0 + tu, v = v0 + tv;
#pragma unroll
    for (int pr = 0; pr < 8; pr++) {
        union { ull u64; float2 f; } cv; cv.u64 = acc2[pr];
        int oc0 = pr * 2;
        float o0 = fmaxf(cv.f.x + bias[g * 16 + oc0], 0.f);
        float o1 = fmaxf(cv.f.y + bias[g * 16 + oc0 + 1], 0.f);
        out[((b * 64 + g * 16 + oc0) * 128 + u) * 128 + v] = o0;
        out[((b * 64 + g * 16 + oc0 + 1) * 128 + u) * 128 + v] = o1;
    }
}

// ---------------------------------------------------------------------------
extern "C" void kernel_launch(void* const* d_in, const int* in_sizes, int n_in,
                              void* d_out, int out_size) {
    (void)in_sizes; (void)n_in; (void)out_size;
    const float* x1       = (const float*)d_in[0];
    const float* x2       = (const float*)d_in[1];
    const float* mask     = (const float*)d_in[2];
    const float* mask_all = (const float*)d_in[3];
    const float* conv_w   = (const float*)d_in[4];
    const float* conv_b   = (const float*)d_in[5];
    float* out = (float*)d_out;

    cudaFuncSetAttribute(hmma_gemm<KS, true>,  cudaFuncAttributeMaxDynamicSharedMemorySize, SMEM_GEMM);
    cudaFuncSetAttribute(hmma_gemm<KX, false>, cudaFuncAttributeMaxDynamicSharedMemorySize, SMEM_GEMM);

    unsigned char* pA; cudaGetSymbolAddress((void**)&pA, g_poolA);
    unsigned char* pB; cudaGetSymbolAddress((void**)&pB, g_poolB);
    __half* d_X3a;  cudaGetSymbolAddress((void**)&d_X3a, g_X3a);
    __half* d_X3b;  cudaGetSymbolAddress((void**)&d_X3b, g_X3b);
    __half* d_Rch;  cudaGetSymbolAddress((void**)&d_Rch, g_Rch);

    float*  d_corr = (float*)pA;                       // phase 1 of poolA
    float*  d_Z    = (float*)pA;                       // phase 2 of poolA, first 128MB
    __half* d_AcTh = (__half*)(pA + 134217728);        // phase 2 of poolA, second 128MB
    float*  d_Ac   = (float*)pB;                       // poolB

    // fork-join stream (created per call; not destroyed)
    cudaStream_t s2;
    cudaStreamCreateWithFlags(&s2, cudaStreamNonBlocking);
    cudaEvent_t evA, evB;
    cudaEventCreateWithFlags(&evA, cudaEventDisableTiming);
    cudaEventCreateWithFlags(&evB, cudaEventDisableTiming);

    prep_kernel<<<dim3(16, Bn), 256>>>(x2, mask);                      // #1
    build_X3<<<dim3(16, Bn), 256>>>(x2);                               // #2
    invnorm_kernel<<<dim3(16, Bn), 256>>>();                           // #3
    // corr: M=N=4096, K=192 triples (4th launch -> ncu samples this)
    hmma_gemm<KX, false><<<dim3(32, 32, Bn), 128, SMEM_GEMM>>>(        // #4
        d_X3a, d_X3b, d_corr, (size_t)L * KX, (size_t)L * KX, (size_t)L * L, KX / 32);
    compact_kernel<<<Bn, 256>>>();                                     // #5

    // fork: build_Rc + cmT overlap scores/softmax on s2 (disjoint buffers)
    cudaEventRecord(evA, 0);
    cudaStreamWaitEvent(s2, evA, 0);
    build_Rc<<<dim3(16, M2, Bn), 256, 0, s2>>>(x1);
    cmT_kernel<<<dim3(M2, Bn), 256, 0, s2>>>(x1);
    cudaEventRecord(evB, s2);

    scores_kernel<<<dim3(16, 1024, Bn), 256>>>(d_corr, d_Ac, mask_all); // corr dead after
    softmax_emit<<<dim3(128, Bn), 256>>>(d_Ac, d_AcTh, mask_all);       // Ac dead after

    // join, then paste: M=2048, N=4096, K=n1 (padded)
    cudaStreamWaitEvent(0, evB, 0);
    hmma_gemm<KS, true><<<dim3(16, 32, Bn), 128, SMEM_GEMM>>>(
        d_Rch, d_AcTh, d_Z, (size_t)M2 * KS, (size_t)L * KS, (size_t)M2 * L, 0);
    scatter_kernel<<<dim3(8192, Bn), 256>>>(d_Z);
    final_conv<<<dim3(64, 16), 256>>>(conv_w, conv_b, out);
}